// round 2
// baseline (speedup 1.0000x reference)
#include <cuda_runtime.h>
#include <cuda_bf16.h>
#include <math.h>

#define S_   2048
#define H_   16
#define D_   2048
#define DH_  128
#define DK_  64
#define EPS_ 1e-6f

// Scratch (device globals: no allocation allowed)
static __device__ float g_Yq[(size_t)H_ * S_ * DH_];   // gelu(q @ Wq1)  [h][s][128]
static __device__ float g_Yk[(size_t)H_ * S_ * DH_];   // gelu(k @ Wk1)  [h][s][128]
static __device__ float g_Qf[(size_t)H_ * S_ * DK_];   // |q features|   [h][s][64]
static __device__ float g_KfT[(size_t)H_ * DK_ * S_];  // |k features|^T [h][e][t]

__device__ __forceinline__ float gelu_f(float x) {
    // exact erf gelu (matches torch F.gelu default / jax approximate=False)
    return 0.5f * x * (1.0f + erff(x * 0.70710678118654752440f));
}

// ---------------------------------------------------------------------------
// Stage 1: Y = gelu(X_head @ W1), X is [S,D] with head slice, W1 is [H,128,128]
// grid (S/128, H), 256 threads, 8x8 register tiles
// ---------------------------------------------------------------------------
__global__ void __launch_bounds__(256, 1)
feat1_kernel(const float* __restrict__ x, const float* __restrict__ w,
             float* __restrict__ y)
{
    extern __shared__ float sm[];
    float* Xs = sm;               // [128][132]
    float* Ws = sm + 128 * 132;   // [128][132]
    const int h = blockIdx.y, sb = blockIdx.x, tid = threadIdx.x;
    const float* xblk = x + (size_t)(sb * 128) * D_ + h * DH_;
    const float* wblk = w + (size_t)h * DH_ * DH_;
    for (int i = tid; i < 128 * 32; i += 256) {
        int r = i >> 5, c = (i & 31) << 2;
        float4 a = *(const float4*)(xblk + (size_t)r * D_ + c);
        float4 b = *(const float4*)(wblk + r * DH_ + c);
        float* pa = Xs + r * 132 + c;
        pa[0] = a.x; pa[1] = a.y; pa[2] = a.z; pa[3] = a.w;
        float* pb = Ws + r * 132 + c;
        pb[0] = b.x; pb[1] = b.y; pb[2] = b.z; pb[3] = b.w;
    }
    __syncthreads();
    const int ty = tid >> 4, tx = tid & 15;
    float acc[8][8];
#pragma unroll
    for (int i = 0; i < 8; i++)
#pragma unroll
        for (int j = 0; j < 8; j++) acc[i][j] = 0.f;
#pragma unroll 4
    for (int d = 0; d < 128; d++) {
        float a[8], b[8];
#pragma unroll
        for (int ii = 0; ii < 8; ii++) a[ii] = Xs[(ty * 8 + ii) * 132 + d];
        float4 b0 = *(const float4*)(Ws + d * 132 + tx * 8);
        float4 b1 = *(const float4*)(Ws + d * 132 + tx * 8 + 4);
        b[0] = b0.x; b[1] = b0.y; b[2] = b0.z; b[3] = b0.w;
        b[4] = b1.x; b[5] = b1.y; b[6] = b1.z; b[7] = b1.w;
#pragma unroll
        for (int ii = 0; ii < 8; ii++)
#pragma unroll
            for (int jj = 0; jj < 8; jj++)
                acc[ii][jj] = fmaf(a[ii], b[jj], acc[ii][jj]);
    }
    float* yblk = y + ((size_t)h * S_ + sb * 128) * DH_;
#pragma unroll
    for (int ii = 0; ii < 8; ii++)
#pragma unroll
        for (int jj = 0; jj < 8; jj++)
            yblk[(size_t)(ty * 8 + ii) * DH_ + tx * 8 + jj] = gelu_f(acc[ii][jj]);
}

// ---------------------------------------------------------------------------
// Stage 2 (Q path): Qf = |gelu(Y @ W2)|,  W2 [H,128,64]
// ---------------------------------------------------------------------------
__global__ void __launch_bounds__(256, 1)
featq2_kernel(const float* __restrict__ y, const float* __restrict__ w2)
{
    extern __shared__ float sm[];
    float* Ys = sm;               // [128][132]
    float* Ws = sm + 128 * 132;   // [128][68]
    const int h = blockIdx.y, sb = blockIdx.x, tid = threadIdx.x;
    const float* yblk = y + ((size_t)h * S_ + sb * 128) * DH_;
    const float* wblk = w2 + (size_t)h * DH_ * DK_;
    for (int i = tid; i < 128 * 32; i += 256) {
        int r = i >> 5, c = (i & 31) << 2;
        float4 a = *(const float4*)(yblk + (size_t)r * DH_ + c);
        float* pa = Ys + r * 132 + c;
        pa[0] = a.x; pa[1] = a.y; pa[2] = a.z; pa[3] = a.w;
    }
    for (int i = tid; i < 128 * 16; i += 256) {
        int r = i >> 4, c = (i & 15) << 2;
        float4 b = *(const float4*)(wblk + r * DK_ + c);
        float* pb = Ws + r * 68 + c;
        pb[0] = b.x; pb[1] = b.y; pb[2] = b.z; pb[3] = b.w;
    }
    __syncthreads();
    const int ty = tid >> 4, tx = tid & 15;
    float acc[8][4];
#pragma unroll
    for (int i = 0; i < 8; i++)
#pragma unroll
        for (int j = 0; j < 4; j++) acc[i][j] = 0.f;
#pragma unroll 4
    for (int d = 0; d < 128; d++) {
        float a[8];
#pragma unroll
        for (int ii = 0; ii < 8; ii++) a[ii] = Ys[(ty * 8 + ii) * 132 + d];
        float4 b4 = *(const float4*)(Ws + d * 68 + tx * 4);
#pragma unroll
        for (int ii = 0; ii < 8; ii++) {
            acc[ii][0] = fmaf(a[ii], b4.x, acc[ii][0]);
            acc[ii][1] = fmaf(a[ii], b4.y, acc[ii][1]);
            acc[ii][2] = fmaf(a[ii], b4.z, acc[ii][2]);
            acc[ii][3] = fmaf(a[ii], b4.w, acc[ii][3]);
        }
    }
    float* outp = g_Qf + ((size_t)h * S_ + sb * 128) * DK_;
#pragma unroll
    for (int ii = 0; ii < 8; ii++)
#pragma unroll
        for (int jj = 0; jj < 4; jj++)
            outp[(size_t)(ty * 8 + ii) * DK_ + tx * 4 + jj] = fabsf(gelu_f(acc[ii][jj]));
}

// ---------------------------------------------------------------------------
// Stage 2 (K path): k2 = |sD| * gelu(Y @ W2); k3 = k2 + (k2 @ ik) * sD2
// Stores |k3| TRANSPOSED per head: g_KfT[h][e][t]  (for conflict-free score GEMM)
// ---------------------------------------------------------------------------
__global__ void __launch_bounds__(256, 1)
featk2_kernel(const float* __restrict__ y, const float* __restrict__ w2,
              const float* __restrict__ ik, const float* __restrict__ sD,
              const float* __restrict__ sD2)
{
    extern __shared__ float sm[];
    float* Ys = sm;               // [128][132]; reused as k2s [128][68]
    float* Ws = sm + 128 * 132;   // [128][68];  reused as iks [64][68]
    const int h = blockIdx.y, sb = blockIdx.x, tid = threadIdx.x;
    const float* yblk = y + ((size_t)h * S_ + sb * 128) * DH_;
    const float* wblk = w2 + (size_t)h * DH_ * DK_;
    for (int i = tid; i < 128 * 32; i += 256) {
        int r = i >> 5, c = (i & 31) << 2;
        float4 a = *(const float4*)(yblk + (size_t)r * DH_ + c);
        float* pa = Ys + r * 132 + c;
        pa[0] = a.x; pa[1] = a.y; pa[2] = a.z; pa[3] = a.w;
    }
    for (int i = tid; i < 128 * 16; i += 256) {
        int r = i >> 4, c = (i & 15) << 2;
        float4 b = *(const float4*)(wblk + r * DK_ + c);
        float* pb = Ws + r * 68 + c;
        pb[0] = b.x; pb[1] = b.y; pb[2] = b.z; pb[3] = b.w;
    }
    __syncthreads();
    const int ty = tid >> 4, tx = tid & 15;
    float acc[8][4];
#pragma unroll
    for (int i = 0; i < 8; i++)
#pragma unroll
        for (int j = 0; j < 4; j++) acc[i][j] = 0.f;
#pragma unroll 4
    for (int d = 0; d < 128; d++) {
        float a[8];
#pragma unroll
        for (int ii = 0; ii < 8; ii++) a[ii] = Ys[(ty * 8 + ii) * 132 + d];
        float4 b4 = *(const float4*)(Ws + d * 68 + tx * 4);
#pragma unroll
        for (int ii = 0; ii < 8; ii++) {
            acc[ii][0] = fmaf(a[ii], b4.x, acc[ii][0]);
            acc[ii][1] = fmaf(a[ii], b4.y, acc[ii][1]);
            acc[ii][2] = fmaf(a[ii], b4.z, acc[ii][2]);
            acc[ii][3] = fmaf(a[ii], b4.w, acc[ii][3]);
        }
    }
    // k2 = |sD| * gelu(acc)
    float4 sd4 = *(const float4*)(sD + h * DK_ + tx * 4);
    float sdv[4] = {fabsf(sd4.x), fabsf(sd4.y), fabsf(sd4.z), fabsf(sd4.w)};
    float k2r[8][4];
#pragma unroll
    for (int ii = 0; ii < 8; ii++)
#pragma unroll
        for (int jj = 0; jj < 4; jj++)
            k2r[ii][jj] = sdv[jj] * gelu_f(acc[ii][jj]);
    __syncthreads();  // done reading Ys/Ws
    float* k2s = Ys;  // [128][68]
#pragma unroll
    for (int ii = 0; ii < 8; ii++) {
        float4 o = make_float4(k2r[ii][0], k2r[ii][1], k2r[ii][2], k2r[ii][3]);
        *(float4*)(k2s + (ty * 8 + ii) * 68 + tx * 4) = o;
    }
    for (int i = tid; i < 64 * 16; i += 256) {      // iks [64][68]
        int r = i >> 4, c = (i & 15) << 2;
        float4 b = *(const float4*)(ik + (size_t)h * DK_ * DK_ + r * DK_ + c);
        float* pb = Ws + r * 68 + c;
        pb[0] = b.x; pb[1] = b.y; pb[2] = b.z; pb[3] = b.w;
    }
    __syncthreads();
    float acc2[8][4];
#pragma unroll
    for (int i = 0; i < 8; i++)
#pragma unroll
        for (int j = 0; j < 4; j++) acc2[i][j] = 0.f;
#pragma unroll 4
    for (int e = 0; e < 64; e++) {
        float a[8];
#pragma unroll
        for (int ii = 0; ii < 8; ii++) a[ii] = k2s[(ty * 8 + ii) * 68 + e];
        float4 b4 = *(const float4*)(Ws + e * 68 + tx * 4);
#pragma unroll
        for (int ii = 0; ii < 8; ii++) {
            acc2[ii][0] = fmaf(a[ii], b4.x, acc2[ii][0]);
            acc2[ii][1] = fmaf(a[ii], b4.y, acc2[ii][1]);
            acc2[ii][2] = fmaf(a[ii], b4.z, acc2[ii][2]);
            acc2[ii][3] = fmaf(a[ii], b4.w, acc2[ii][3]);
        }
    }
    float4 s24 = *(const float4*)(sD2 + h * DK_ + tx * 4);
    float s2v[4] = {s24.x, s24.y, s24.z, s24.w};
#pragma unroll
    for (int ii = 0; ii < 8; ii++)
#pragma unroll
        for (int jj = 0; jj < 4; jj++) {
            float k3 = k2r[ii][jj] + acc2[ii][jj] * s2v[jj];
            // transposed store: [h][e][t]
            g_KfT[((size_t)h * DK_ + tx * 4 + jj) * S_ + sb * 128 + ty * 8 + ii] = fabsf(k3);
        }
}

// ---------------------------------------------------------------------------
// Stage 3: fused scores -> mask/exp merge -> AV -> row-normalize
// attn[s,t] = (mask ? lr+EPS : exp(spw)) ; denom[s] = sum(mask?lr:0)+EPS+exp(sp_lse)
// out[s, h*128+d] = (attn @ V) / denom
// mask is int32 (bool widened by the harness pipeline)
// grid (S/128, H), 256 threads, t-tile = 64
// ---------------------------------------------------------------------------
__global__ void __launch_bounds__(256, 1)
attn_kernel(const float* __restrict__ v, const int* __restrict__ mask,
            const float* __restrict__ sp_lse, const float* __restrict__ spw,
            float* __restrict__ out)
{
    extern __shared__ float sm[];
    float* qs  = sm;                  // [128][68]  Qf block
    float* ksT = qs + 128 * 68;       // [64][68]   K^T tile (e-major)
    float* ws  = ksT + 64 * 68;       // [128][68]  merged weights
    float* vs  = ws + 128 * 68;       // [64][132]  V tile
    float* rs  = vs + 64 * 132;       // [128]      row sums
    const int h = blockIdx.y, sb = blockIdx.x, tid = threadIdx.x;
    const int ty = tid >> 4, tx = tid & 15;
    const int i0 = ty * 8;

    const float* qblk = g_Qf + ((size_t)h * S_ + sb * 128) * DK_;
    for (int i = tid; i < 128 * 16; i += 256) {
        int r = i >> 4, c = (i & 15) << 2;
        float4 a = *(const float4*)(qblk + (size_t)r * DK_ + c);
        float* p = qs + r * 68 + c;
        p[0] = a.x; p[1] = a.y; p[2] = a.z; p[3] = a.w;
    }
    if (tid < 128) rs[tid] = 0.f;

    float acc[8][8];
#pragma unroll
    for (int i = 0; i < 8; i++)
#pragma unroll
        for (int j = 0; j < 8; j++) acc[i][j] = 0.f;
    float rsum[8];
#pragma unroll
    for (int i = 0; i < 8; i++) rsum[i] = 0.f;
    __syncthreads();

    for (int tb = 0; tb < 32; tb++) {
        const float* kblk = g_KfT + (size_t)h * DK_ * S_ + tb * 64;
        for (int i = tid; i < 64 * 16; i += 256) {
            int r = i >> 4, c = (i & 15) << 2;
            float4 a = *(const float4*)(kblk + (size_t)r * S_ + c);
            float* p = ksT + r * 68 + c;
            p[0] = a.x; p[1] = a.y; p[2] = a.z; p[3] = a.w;
        }
        const float* vblk = v + (size_t)(tb * 64) * D_ + h * DH_;
        for (int i = tid; i < 64 * 32; i += 256) {
            int r = i >> 5, c = (i & 31) << 2;
            float4 a = *(const float4*)(vblk + (size_t)r * D_ + c);
            float* p = vs + r * 132 + c;
            p[0] = a.x; p[1] = a.y; p[2] = a.z; p[3] = a.w;
        }
        __syncthreads();

        // lr scores: rows i0..+7, cols tx*4..+3, K=64
        float sacc[8][4];
#pragma unroll
        for (int i = 0; i < 8; i++)
#pragma unroll
            for (int j = 0; j < 4; j++) sacc[i][j] = 0.f;
#pragma unroll 4
        for (int e = 0; e < 64; e++) {
            float a[8];
#pragma unroll
            for (int ii = 0; ii < 8; ii++) a[ii] = qs[(i0 + ii) * 68 + e];
            float4 b4 = *(const float4*)(ksT + e * 68 + tx * 4);
#pragma unroll
            for (int ii = 0; ii < 8; ii++) {
                sacc[ii][0] = fmaf(a[ii], b4.x, sacc[ii][0]);
                sacc[ii][1] = fmaf(a[ii], b4.y, sacc[ii][1]);
                sacc[ii][2] = fmaf(a[ii], b4.z, sacc[ii][2]);
                sacc[ii][3] = fmaf(a[ii], b4.w, sacc[ii][3]);
            }
        }

        const int tcol = tb * 64 + tx * 4;
#pragma unroll
        for (int ii = 0; ii < 8; ii++) {
            const int s = sb * 128 + i0 + ii;
            int4 m4 = *(const int4*)(mask + (size_t)s * S_ + tcol);
            float4 w4 = *(const float4*)(spw + ((size_t)(h * S_ + s)) * S_ + tcol);
            float l0 = sacc[ii][0], l1 = sacc[ii][1];
            float l2 = sacc[ii][2], l3 = sacc[ii][3];
            float o0 = m4.x ? (l0 + EPS_) : __expf(w4.x);
            float o1 = m4.y ? (l1 + EPS_) : __expf(w4.y);
            float o2 = m4.z ? (l2 + EPS_) : __expf(w4.z);
            float o3 = m4.w ? (l3 + EPS_) : __expf(w4.w);
            rsum[ii] += (m4.x ? l0 : 0.f) + (m4.y ? l1 : 0.f)
                      + (m4.z ? l2 : 0.f) + (m4.w ? l3 : 0.f);
            *(float4*)(ws + (i0 + ii) * 68 + tx * 4) = make_float4(o0, o1, o2, o3);
        }
        __syncthreads();

        // acc += W[128x64] @ V[64x128]
#pragma unroll 4
        for (int e = 0; e < 64; e++) {
            float a[8];
#pragma unroll
            for (int ii = 0; ii < 8; ii++) a[ii] = ws[(i0 + ii) * 68 + e];
            float4 b0 = *(const float4*)(vs + e * 132 + tx * 8);
            float4 b1 = *(const float4*)(vs + e * 132 + tx * 8 + 4);
            float b[8] = {b0.x, b0.y, b0.z, b0.w, b1.x, b1.y, b1.z, b1.w};
#pragma unroll
            for (int ii = 0; ii < 8; ii++)
#pragma unroll
                for (int jj = 0; jj < 8; jj++)
                    acc[ii][jj] = fmaf(a[ii], b[jj], acc[ii][jj]);
        }
        __syncthreads();
    }

#pragma unroll
    for (int ii = 0; ii < 8; ii++) atomicAdd(&rs[i0 + ii], rsum[ii]);
    __syncthreads();

    float* oblk = out + (size_t)(sb * 128) * D_ + h * DH_;
#pragma unroll
    for (int ii = 0; ii < 8; ii++) {
        const int s = sb * 128 + i0 + ii;
        float inv = 1.0f / (rs[i0 + ii] + EPS_ + __expf(sp_lse[h * S_ + s]));
#pragma unroll
        for (int jj = 0; jj < 8; jj++)
            oblk[(size_t)(i0 + ii) * D_ + tx * 8 + jj] = acc[ii][jj] * inv;
    }
}

// ---------------------------------------------------------------------------
extern "C" void kernel_launch(void* const* d_in, const int* in_sizes, int n_in,
                              void* d_out, int out_size)
{
    (void)in_sizes; (void)n_in; (void)out_size;
    const float* q      = (const float*)d_in[0];
    const float* k      = (const float*)d_in[1];
    const float* v      = (const float*)d_in[2];
    const int*   mask   = (const int*)d_in[3];
    const float* sp_lse = (const float*)d_in[4];
    const float* spw    = (const float*)d_in[5];
    const float* kq1    = (const float*)d_in[6];
    const float* kk1    = (const float*)d_in[7];
    const float* kq2    = (const float*)d_in[8];
    const float* kk2    = (const float*)d_in[9];
    const float* ik     = (const float*)d_in[10];
    const float* sD     = (const float*)d_in[11];
    const float* sD2    = (const float*)d_in[12];
    float* out = (float*)d_out;

    float *yq = 0, *yk = 0;
    cudaGetSymbolAddress((void**)&yq, g_Yq);
    cudaGetSymbolAddress((void**)&yk, g_Yk);

    const int smem1 = 2 * 128 * 132 * 4;                                  // 135168
    const int smemB = (128 * 132 + 128 * 68) * 4;                         // 102400
    const int smemA = (128 * 68 + 64 * 68 + 128 * 68 + 64 * 132 + 128) * 4; // 121344
    cudaFuncSetAttribute(feat1_kernel,  cudaFuncAttributeMaxDynamicSharedMemorySize, smem1);
    cudaFuncSetAttribute(featq2_kernel, cudaFuncAttributeMaxDynamicSharedMemorySize, smemB);
    cudaFuncSetAttribute(featk2_kernel, cudaFuncAttributeMaxDynamicSharedMemorySize, smemB);
    cudaFuncSetAttribute(attn_kernel,   cudaFuncAttributeMaxDynamicSharedMemorySize, smemA);

    dim3 grid(S_ / 128, H_), blk(256);
    feat1_kernel<<<grid, blk, smem1>>>(q, kq1, yq);
    feat1_kernel<<<grid, blk, smem1>>>(k, kk1, yk);
    featq2_kernel<<<grid, blk, smemB>>>(yq, kq2);
    featk2_kernel<<<grid, blk, smemB>>>(yk, kk2, ik, sD, sD2);
    attn_kernel<<<grid, blk, smemA>>>(v, mask, sp_lse, spw, out);
}

// round 4
// speedup vs baseline: 1.0553x; 1.0553x over previous
#include <cuda_runtime.h>
#include <cuda_bf16.h>
#include <math.h>
#include <mma.h>

using namespace nvcuda;

#define S_   2048
#define H_   16
#define D_   2048
#define DH_  128
#define DK_  64
#define EPS_ 1e-6f

// Scratch (device globals: no allocation allowed)
static __device__ float g_Yq[(size_t)H_ * S_ * DH_];   // gelu(q @ Wq1)  [h][s][128]
static __device__ float g_Yk[(size_t)H_ * S_ * DH_];   // gelu(k @ Wk1)  [h][s][128]
static __device__ float g_Qf[(size_t)H_ * S_ * DK_];   // |q features|   [h][s][64]
static __device__ float g_KfT[(size_t)H_ * DK_ * S_];  // |k features|^T [h][e][t]

__device__ __forceinline__ float gelu_f(float x) {
    // exact erf gelu (matches torch F.gelu default / jax approximate=False)
    return 0.5f * x * (1.0f + erff(x * 0.70710678118654752440f));
}

// ---------------------------------------------------------------------------
// Stage 1: Y = gelu(X_head @ W1), X is [S,D] with head slice, W1 is [H,128,128]
// grid (S/128, H), 256 threads, 8x8 register tiles
// ---------------------------------------------------------------------------
__global__ void __launch_bounds__(256, 1)
feat1_kernel(const float* __restrict__ x, const float* __restrict__ w,
             float* __restrict__ y)
{
    extern __shared__ float sm[];
    float* Xs = sm;               // [128][132]
    float* Ws = sm + 128 * 132;   // [128][132]
    const int h = blockIdx.y, sb = blockIdx.x, tid = threadIdx.x;
    const float* xblk = x + (size_t)(sb * 128) * D_ + h * DH_;
    const float* wblk = w + (size_t)h * DH_ * DH_;
    for (int i = tid; i < 128 * 32; i += 256) {
        int r = i >> 5, c = (i & 31) << 2;
        float4 a = *(const float4*)(xblk + (size_t)r * D_ + c);
        float4 b = *(const float4*)(wblk + r * DH_ + c);
        float* pa = Xs + r * 132 + c;
        pa[0] = a.x; pa[1] = a.y; pa[2] = a.z; pa[3] = a.w;
        float* pb = Ws + r * 132 + c;
        pb[0] = b.x; pb[1] = b.y; pb[2] = b.z; pb[3] = b.w;
    }
    __syncthreads();
    const int ty = tid >> 4, tx = tid & 15;
    float acc[8][8];
#pragma unroll
    for (int i = 0; i < 8; i++)
#pragma unroll
        for (int j = 0; j < 8; j++) acc[i][j] = 0.f;
#pragma unroll 4
    for (int d = 0; d < 128; d++) {
        float a[8], b[8];
#pragma unroll
        for (int ii = 0; ii < 8; ii++) a[ii] = Xs[(ty * 8 + ii) * 132 + d];
        float4 b0 = *(const float4*)(Ws + d * 132 + tx * 8);
        float4 b1 = *(const float4*)(Ws + d * 132 + tx * 8 + 4);
        b[0] = b0.x; b[1] = b0.y; b[2] = b0.z; b[3] = b0.w;
        b[4] = b1.x; b[5] = b1.y; b[6] = b1.z; b[7] = b1.w;
#pragma unroll
        for (int ii = 0; ii < 8; ii++)
#pragma unroll
            for (int jj = 0; jj < 8; jj++)
                acc[ii][jj] = fmaf(a[ii], b[jj], acc[ii][jj]);
    }
    float* yblk = y + ((size_t)h * S_ + sb * 128) * DH_;
#pragma unroll
    for (int ii = 0; ii < 8; ii++)
#pragma unroll
        for (int jj = 0; jj < 8; jj++)
            yblk[(size_t)(ty * 8 + ii) * DH_ + tx * 8 + jj] = gelu_f(acc[ii][jj]);
}

// ---------------------------------------------------------------------------
// Stage 2 (Q path): Qf = |gelu(Y @ W2)|,  W2 [H,128,64]
// ---------------------------------------------------------------------------
__global__ void __launch_bounds__(256, 1)
featq2_kernel(const float* __restrict__ y, const float* __restrict__ w2)
{
    extern __shared__ float sm[];
    float* Ys = sm;               // [128][132]
    float* Ws = sm + 128 * 132;   // [128][68]
    const int h = blockIdx.y, sb = blockIdx.x, tid = threadIdx.x;
    const float* yblk = y + ((size_t)h * S_ + sb * 128) * DH_;
    const float* wblk = w2 + (size_t)h * DH_ * DK_;
    for (int i = tid; i < 128 * 32; i += 256) {
        int r = i >> 5, c = (i & 31) << 2;
        float4 a = *(const float4*)(yblk + (size_t)r * DH_ + c);
        float* pa = Ys + r * 132 + c;
        pa[0] = a.x; pa[1] = a.y; pa[2] = a.z; pa[3] = a.w;
    }
    for (int i = tid; i < 128 * 16; i += 256) {
        int r = i >> 4, c = (i & 15) << 2;
        float4 b = *(const float4*)(wblk + r * DK_ + c);
        float* pb = Ws + r * 68 + c;
        pb[0] = b.x; pb[1] = b.y; pb[2] = b.z; pb[3] = b.w;
    }
    __syncthreads();
    const int ty = tid >> 4, tx = tid & 15;
    float acc[8][4];
#pragma unroll
    for (int i = 0; i < 8; i++)
#pragma unroll
        for (int j = 0; j < 4; j++) acc[i][j] = 0.f;
#pragma unroll 4
    for (int d = 0; d < 128; d++) {
        float a[8];
#pragma unroll
        for (int ii = 0; ii < 8; ii++) a[ii] = Ys[(ty * 8 + ii) * 132 + d];
        float4 b4 = *(const float4*)(Ws + d * 68 + tx * 4);
#pragma unroll
        for (int ii = 0; ii < 8; ii++) {
            acc[ii][0] = fmaf(a[ii], b4.x, acc[ii][0]);
            acc[ii][1] = fmaf(a[ii], b4.y, acc[ii][1]);
            acc[ii][2] = fmaf(a[ii], b4.z, acc[ii][2]);
            acc[ii][3] = fmaf(a[ii], b4.w, acc[ii][3]);
        }
    }
    float* outp = g_Qf + ((size_t)h * S_ + sb * 128) * DK_;
#pragma unroll
    for (int ii = 0; ii < 8; ii++)
#pragma unroll
        for (int jj = 0; jj < 4; jj++)
            outp[(size_t)(ty * 8 + ii) * DK_ + tx * 4 + jj] = fabsf(gelu_f(acc[ii][jj]));
}

// ---------------------------------------------------------------------------
// Stage 2 (K path): k2 = |sD| * gelu(Y @ W2); k3 = k2 + (k2 @ ik) * sD2
// Stores |k3| TRANSPOSED per head: g_KfT[h][e][t]
// ---------------------------------------------------------------------------
__global__ void __launch_bounds__(256, 1)
featk2_kernel(const float* __restrict__ y, const float* __restrict__ w2,
              const float* __restrict__ ik, const float* __restrict__ sD,
              const float* __restrict__ sD2)
{
    extern __shared__ float sm[];
    float* Ys = sm;               // [128][132]; reused as k2s [128][68]
    float* Ws = sm + 128 * 132;   // [128][68];  reused as iks [64][68]
    const int h = blockIdx.y, sb = blockIdx.x, tid = threadIdx.x;
    const float* yblk = y + ((size_t)h * S_ + sb * 128) * DH_;
    const float* wblk = w2 + (size_t)h * DH_ * DK_;
    for (int i = tid; i < 128 * 32; i += 256) {
        int r = i >> 5, c = (i & 31) << 2;
        float4 a = *(const float4*)(yblk + (size_t)r * DH_ + c);
        float* pa = Ys + r * 132 + c;
        pa[0] = a.x; pa[1] = a.y; pa[2] = a.z; pa[3] = a.w;
    }
    for (int i = tid; i < 128 * 16; i += 256) {
        int r = i >> 4, c = (i & 15) << 2;
        float4 b = *(const float4*)(wblk + r * DK_ + c);
        float* pb = Ws + r * 68 + c;
        pb[0] = b.x; pb[1] = b.y; pb[2] = b.z; pb[3] = b.w;
    }
    __syncthreads();
    const int ty = tid >> 4, tx = tid & 15;
    float acc[8][4];
#pragma unroll
    for (int i = 0; i < 8; i++)
#pragma unroll
        for (int j = 0; j < 4; j++) acc[i][j] = 0.f;
#pragma unroll 4
    for (int d = 0; d < 128; d++) {
        float a[8];
#pragma unroll
        for (int ii = 0; ii < 8; ii++) a[ii] = Ys[(ty * 8 + ii) * 132 + d];
        float4 b4 = *(const float4*)(Ws + d * 68 + tx * 4);
#pragma unroll
        for (int ii = 0; ii < 8; ii++) {
            acc[ii][0] = fmaf(a[ii], b4.x, acc[ii][0]);
            acc[ii][1] = fmaf(a[ii], b4.y, acc[ii][1]);
            acc[ii][2] = fmaf(a[ii], b4.z, acc[ii][2]);
            acc[ii][3] = fmaf(a[ii], b4.w, acc[ii][3]);
        }
    }
    float4 sd4 = *(const float4*)(sD + h * DK_ + tx * 4);
    float sdv[4] = {fabsf(sd4.x), fabsf(sd4.y), fabsf(sd4.z), fabsf(sd4.w)};
    float k2r[8][4];
#pragma unroll
    for (int ii = 0; ii < 8; ii++)
#pragma unroll
        for (int jj = 0; jj < 4; jj++)
            k2r[ii][jj] = sdv[jj] * gelu_f(acc[ii][jj]);
    __syncthreads();
    float* k2s = Ys;  // [128][68]
#pragma unroll
    for (int ii = 0; ii < 8; ii++) {
        float4 o = make_float4(k2r[ii][0], k2r[ii][1], k2r[ii][2], k2r[ii][3]);
        *(float4*)(k2s + (ty * 8 + ii) * 68 + tx * 4) = o;
    }
    for (int i = tid; i < 64 * 16; i += 256) {      // iks [64][68]
        int r = i >> 4, c = (i & 15) << 2;
        float4 b = *(const float4*)(ik + (size_t)h * DK_ * DK_ + r * DK_ + c);
        float* pb = Ws + r * 68 + c;
        pb[0] = b.x; pb[1] = b.y; pb[2] = b.z; pb[3] = b.w;
    }
    __syncthreads();
    float acc2[8][4];
#pragma unroll
    for (int i = 0; i < 8; i++)
#pragma unroll
        for (int j = 0; j < 4; j++) acc2[i][j] = 0.f;
#pragma unroll 4
    for (int e = 0; e < 64; e++) {
        float a[8];
#pragma unroll
        for (int ii = 0; ii < 8; ii++) a[ii] = k2s[(ty * 8 + ii) * 68 + e];
        float4 b4 = *(const float4*)(Ws + e * 68 + tx * 4);
#pragma unroll
        for (int ii = 0; ii < 8; ii++) {
            acc2[ii][0] = fmaf(a[ii], b4.x, acc2[ii][0]);
            acc2[ii][1] = fmaf(a[ii], b4.y, acc2[ii][1]);
            acc2[ii][2] = fmaf(a[ii], b4.z, acc2[ii][2]);
            acc2[ii][3] = fmaf(a[ii], b4.w, acc2[ii][3]);
        }
    }
    float4 s24 = *(const float4*)(sD2 + h * DK_ + tx * 4);
    float s2v[4] = {s24.x, s24.y, s24.z, s24.w};
#pragma unroll
    for (int ii = 0; ii < 8; ii++)
#pragma unroll
        for (int jj = 0; jj < 4; jj++) {
            float k3 = k2r[ii][jj] + acc2[ii][jj] * s2v[jj];
            g_KfT[((size_t)h * DK_ + tx * 4 + jj) * S_ + sb * 128 + ty * 8 + ii] = fabsf(k3);
        }
}

// ---------------------------------------------------------------------------
// Stage 3 (WMMA tf32): scores -> mask/exp merge -> AV -> normalize
// grid (S/128, H), 256 threads (8 warps); t-tile = 64
// ---------------------------------------------------------------------------
#define QS_LD  72
#define KS_LD  72
#define WS_LD  72
#define VS_LD  136

__global__ void __launch_bounds__(256, 1)
attn_kernel(const float* __restrict__ v, const int* __restrict__ mask,
            const float* __restrict__ sp_lse, const float* __restrict__ spw,
            float* __restrict__ out)
{
    extern __shared__ float sm[];
    float* qs  = sm;                       // [128][72]
    float* ksT = qs + 128 * QS_LD;         // [64][72]
    float* ws  = ksT + 64 * KS_LD;         // [128][72]   P / merged weights
    float* vs  = ws + 128 * WS_LD;         // [64][136]
    float* rs  = vs + 64 * VS_LD;          // [128]
    const int h = blockIdx.y, sb = blockIdx.x, tid = threadIdx.x;
    const int warp = tid >> 5;
    const int r  = tid >> 1;               // elementwise row (0..127)
    const int ch = (tid & 1) * 32;         // merge col half (64-wide tiles)

    // load Qf block [128][64]
    const float* qblk = g_Qf + ((size_t)h * S_ + sb * 128) * DK_;
    for (int i = tid; i < 128 * 16; i += 256) {
        int rr = i >> 4, c = (i & 15) << 2;
        float4 a = *(const float4*)(qblk + (size_t)rr * DK_ + c);
        float* p = qs + rr * QS_LD + c;
        p[0] = a.x; p[1] = a.y; p[2] = a.z; p[3] = a.w;
    }
    if (tid < 128) rs[tid] = 0.f;

    wmma::fragment<wmma::accumulator, 16, 16, 8, float> accf[8];
#pragma unroll
    for (int n = 0; n < 8; n++) wmma::fill_fragment(accf[n], 0.f);
    float rloc = 0.f;
    __syncthreads();

    const int* mrow  = mask + (size_t)(sb * 128 + r) * S_ + ch;
    const float* wrow = spw + ((size_t)h * S_ + sb * 128 + r) * S_ + ch;

    for (int tb = 0; tb < 32; tb++) {
        // K^T tile [64e][64t]
        const float* kblk = g_KfT + (size_t)h * DK_ * S_ + tb * 64;
        for (int i = tid; i < 64 * 16; i += 256) {
            int rr = i >> 4, c = (i & 15) << 2;
            float4 a = *(const float4*)(kblk + (size_t)rr * S_ + c);
            float* p = ksT + rr * KS_LD + c;
            p[0] = a.x; p[1] = a.y; p[2] = a.z; p[3] = a.w;
        }
        // V tile [64t][128d]
        const float* vblk = v + (size_t)(tb * 64) * D_ + h * DH_;
        for (int i = tid; i < 64 * 32; i += 256) {
            int rr = i >> 5, c = (i & 31) << 2;
            float4 a = *(const float4*)(vblk + (size_t)rr * D_ + c);
            float* p = vs + rr * VS_LD + c;
            p[0] = a.x; p[1] = a.y; p[2] = a.z; p[3] = a.w;
        }
        __syncthreads();

        // --- scores: P[16x64] per warp, K=64 (tf32) ---
        {
            wmma::fragment<wmma::accumulator, 16, 16, 8, float> fp[4];
#pragma unroll
            for (int n = 0; n < 4; n++) wmma::fill_fragment(fp[n], 0.f);
#pragma unroll
            for (int kk = 0; kk < 8; kk++) {
                wmma::fragment<wmma::matrix_a, 16, 16, 8, wmma::precision::tf32, wmma::row_major> fa;
                wmma::load_matrix_sync(fa, qs + (16 * warp) * QS_LD + kk * 8, QS_LD);
#pragma unroll
                for (int i = 0; i < fa.num_elements; i++) fa.x[i] = wmma::__float_to_tf32(fa.x[i]);
#pragma unroll
                for (int n = 0; n < 4; n++) {
                    wmma::fragment<wmma::matrix_b, 16, 16, 8, wmma::precision::tf32, wmma::row_major> fb;
                    wmma::load_matrix_sync(fb, ksT + (kk * 8) * KS_LD + n * 16, KS_LD);
#pragma unroll
                    for (int i = 0; i < fb.num_elements; i++) fb.x[i] = wmma::__float_to_tf32(fb.x[i]);
                    wmma::mma_sync(fp[n], fa, fb, fp[n]);
                }
            }
#pragma unroll
            for (int n = 0; n < 4; n++)
                wmma::store_matrix_sync(ws + (16 * warp) * WS_LD + n * 16, fp[n], WS_LD, wmma::mem_row_major);
        }
        __syncthreads();

        // --- elementwise merge + row sum (thread owns row r, cols ch..ch+31) ---
        {
            const int* mp = mrow + tb * 64;
            const float* wp = wrow + tb * 64;
            float* pw = ws + r * WS_LD + ch;
#pragma unroll
            for (int j = 0; j < 8; j++) {
                int4 m4 = *(const int4*)(mp + j * 4);
                float4 w4 = *(const float4*)(wp + j * 4);
                float4 p4 = *(float4*)(pw + j * 4);
                float o0 = m4.x ? (p4.x + EPS_) : __expf(w4.x);
                float o1 = m4.y ? (p4.y + EPS_) : __expf(w4.y);
                float o2 = m4.z ? (p4.z + EPS_) : __expf(w4.z);
                float o3 = m4.w ? (p4.w + EPS_) : __expf(w4.w);
                rloc += (m4.x ? p4.x : 0.f) + (m4.y ? p4.y : 0.f)
                      + (m4.z ? p4.z : 0.f) + (m4.w ? p4.w : 0.f);
                *(float4*)(pw + j * 4) = make_float4(o0, o1, o2, o3);
            }
        }
        __syncthreads();

        // --- AV: O[16x128] per warp, K=64 (tf32) ---
#pragma unroll
        for (int kk = 0; kk < 8; kk++) {
            wmma::fragment<wmma::matrix_a, 16, 16, 8, wmma::precision::tf32, wmma::row_major> fa;
            wmma::load_matrix_sync(fa, ws + (16 * warp) * WS_LD + kk * 8, WS_LD);
#pragma unroll
            for (int i = 0; i < fa.num_elements; i++) fa.x[i] = wmma::__float_to_tf32(fa.x[i]);
#pragma unroll
            for (int n = 0; n < 8; n++) {
                wmma::fragment<wmma::matrix_b, 16, 16, 8, wmma::precision::tf32, wmma::row_major> fb;
                wmma::load_matrix_sync(fb, vs + (kk * 8) * VS_LD + n * 16, VS_LD);
#pragma unroll
                for (int i = 0; i < fb.num_elements; i++) fb.x[i] = wmma::__float_to_tf32(fb.x[i]);
                wmma::mma_sync(accf[n], fa, fb, accf[n]);
            }
        }
        __syncthreads();
    }

    // store unnormalized output
    float* oblk = out + (size_t)(sb * 128 + 16 * warp) * D_ + h * DH_;
#pragma unroll
    for (int n = 0; n < 8; n++)
        wmma::store_matrix_sync(oblk + n * 16, accf[n], D_, wmma::mem_row_major);
    atomicAdd(&rs[r], rloc);
    __syncthreads();

    // normalize rows in place — FULL 128 columns (2 threads/row x 64 cols)
    {
        const int oh = (tid & 1) * 64;
        float denom = rs[r] + EPS_ + __expf(sp_lse[h * S_ + sb * 128 + r]);
        float inv = 1.0f / denom;
        float* op = out + (size_t)(sb * 128 + r) * D_ + h * DH_ + oh;
#pragma unroll
        for (int j = 0; j < 16; j++) {
            float4 t = *(float4*)(op + j * 4);
            t.x *= inv; t.y *= inv; t.z *= inv; t.w *= inv;
            *(float4*)(op + j * 4) = t;
        }
    }
}

// ---------------------------------------------------------------------------
extern "C" void kernel_launch(void* const* d_in, const int* in_sizes, int n_in,
                              void* d_out, int out_size)
{
    (void)in_sizes; (void)n_in; (void)out_size;
    const float* q      = (const float*)d_in[0];
    const float* k      = (const float*)d_in[1];
    const float* v      = (const float*)d_in[2];
    const int*   mask   = (const int*)d_in[3];
    const float* sp_lse = (const float*)d_in[4];
    const float* spw    = (const float*)d_in[5];
    const float* kq1    = (const float*)d_in[6];
    const float* kk1    = (const float*)d_in[7];
    const float* kq2    = (const float*)d_in[8];
    const float* kk2    = (const float*)d_in[9];
    const float* ik     = (const float*)d_in[10];
    const float* sD     = (const float*)d_in[11];
    const float* sD2    = (const float*)d_in[12];
    float* out = (float*)d_out;

    float *yq = 0, *yk = 0;
    cudaGetSymbolAddress((void**)&yq, g_Yq);
    cudaGetSymbolAddress((void**)&yk, g_Yk);

    const int smem1 = 2 * 128 * 132 * 4;                                    // 135168
    const int smemB = (128 * 132 + 128 * 68) * 4;                           // 102400
    const int smemA = (128 * QS_LD + 64 * KS_LD + 128 * WS_LD + 64 * VS_LD + 128) * 4; // 127488
    cudaFuncSetAttribute(feat1_kernel,  cudaFuncAttributeMaxDynamicSharedMemorySize, smem1);
    cudaFuncSetAttribute(featq2_kernel, cudaFuncAttributeMaxDynamicSharedMemorySize, smemB);
    cudaFuncSetAttribute(featk2_kernel, cudaFuncAttributeMaxDynamicSharedMemorySize, smemB);
    cudaFuncSetAttribute(attn_kernel,   cudaFuncAttributeMaxDynamicSharedMemorySize, smemA);

    dim3 grid(S_ / 128, H_), blk(256);
    feat1_kernel<<<grid, blk, smem1>>>(q, kq1, yq);
    feat1_kernel<<<grid, blk, smem1>>>(k, kk1, yk);
    featq2_kernel<<<grid, blk, smemB>>>(yq, kq2);
    featk2_kernel<<<grid, blk, smemB>>>(yk, kk2, ik, sD, sD2);
    attn_kernel<<<grid, blk, smemA>>>(v, mask, sp_lse, spw, out);
}

// round 5
// speedup vs baseline: 1.4001x; 1.3268x over previous
#include <cuda_runtime.h>
#include <cuda_bf16.h>
#include <math.h>
#include <mma.h>

using namespace nvcuda;

#define S_   2048
#define H_   16
#define D_   2048
#define DH_  128
#define DK_  64
#define EPS_ 1e-6f

// Scratch (device globals: no allocation allowed)
static __device__ float g_Yq[(size_t)H_ * S_ * DH_];   // gelu(q @ Wq1)  [h][s][128]
static __device__ float g_Yk[(size_t)H_ * S_ * DH_];   // gelu(k @ Wk1)  [h][s][128]
static __device__ float g_Qf[(size_t)H_ * S_ * DK_];   // |q features|   [h][s][64]
static __device__ float g_KfT[(size_t)H_ * DK_ * S_];  // |k features|^T [h][e][t]

__device__ __forceinline__ float gelu_f(float x) {
    return 0.5f * x * (1.0f + erff(x * 0.70710678118654752440f));
}

// ---------------------------------------------------------------------------
// Stage 1: Y = gelu(X_head @ W1)
// ---------------------------------------------------------------------------
__global__ void __launch_bounds__(256, 1)
feat1_kernel(const float* __restrict__ x, const float* __restrict__ w,
             float* __restrict__ y)
{
    extern __shared__ float sm[];
    float* Xs = sm;               // [128][132]
    float* Ws = sm + 128 * 132;   // [128][132]
    const int h = blockIdx.y, sb = blockIdx.x, tid = threadIdx.x;
    const float* xblk = x + (size_t)(sb * 128) * D_ + h * DH_;
    const float* wblk = w + (size_t)h * DH_ * DH_;
    for (int i = tid; i < 128 * 32; i += 256) {
        int r = i >> 5, c = (i & 31) << 2;
        float4 a = *(const float4*)(xblk + (size_t)r * D_ + c);
        float4 b = *(const float4*)(wblk + r * DH_ + c);
        float* pa = Xs + r * 132 + c;
        pa[0] = a.x; pa[1] = a.y; pa[2] = a.z; pa[3] = a.w;
        float* pb = Ws + r * 132 + c;
        pb[0] = b.x; pb[1] = b.y; pb[2] = b.z; pb[3] = b.w;
    }
    __syncthreads();
    const int ty = tid >> 4, tx = tid & 15;
    float acc[8][8];
#pragma unroll
    for (int i = 0; i < 8; i++)
#pragma unroll
        for (int j = 0; j < 8; j++) acc[i][j] = 0.f;
#pragma unroll 4
    for (int d = 0; d < 128; d++) {
        float a[8], b[8];
#pragma unroll
        for (int ii = 0; ii < 8; ii++) a[ii] = Xs[(ty * 8 + ii) * 132 + d];
        float4 b0 = *(const float4*)(Ws + d * 132 + tx * 8);
        float4 b1 = *(const float4*)(Ws + d * 132 + tx * 8 + 4);
        b[0] = b0.x; b[1] = b0.y; b[2] = b0.z; b[3] = b0.w;
        b[4] = b1.x; b[5] = b1.y; b[6] = b1.z; b[7] = b1.w;
#pragma unroll
        for (int ii = 0; ii < 8; ii++)
#pragma unroll
            for (int jj = 0; jj < 8; jj++)
                acc[ii][jj] = fmaf(a[ii], b[jj], acc[ii][jj]);
    }
    float* yblk = y + ((size_t)h * S_ + sb * 128) * DH_;
#pragma unroll
    for (int ii = 0; ii < 8; ii++)
#pragma unroll
        for (int jj = 0; jj < 8; jj++)
            yblk[(size_t)(ty * 8 + ii) * DH_ + tx * 8 + jj] = gelu_f(acc[ii][jj]);
}

// ---------------------------------------------------------------------------
// Stage 2 fused: z=0 Q path, z=1 K path
// ---------------------------------------------------------------------------
__global__ void __launch_bounds__(256, 1)
feat2_kernel(const float* __restrict__ yq, const float* __restrict__ yk,
             const float* __restrict__ wq2, const float* __restrict__ wk2,
             const float* __restrict__ ik, const float* __restrict__ sD,
             const float* __restrict__ sD2)
{
    extern __shared__ float sm[];
    float* Ys = sm;               // [128][132]  (K path reuses as k2s [128][68])
    float* Ws = sm + 128 * 132;   // [128][68]
    const int h = blockIdx.y, sb = blockIdx.x, tid = threadIdx.x;
    const int ty = tid >> 4, tx = tid & 15;
    const int kpath = blockIdx.z;
    const float* y  = kpath ? yk : yq;
    const float* w2 = kpath ? wk2 : wq2;

    const float* yblk = y + ((size_t)h * S_ + sb * 128) * DH_;
    const float* wblk = w2 + (size_t)h * DH_ * DK_;
    for (int i = tid; i < 128 * 32; i += 256) {
        int r = i >> 5, c = (i & 31) << 2;
        float4 a = *(const float4*)(yblk + (size_t)r * DH_ + c);
        float* pa = Ys + r * 132 + c;
        pa[0] = a.x; pa[1] = a.y; pa[2] = a.z; pa[3] = a.w;
    }
    for (int i = tid; i < 128 * 16; i += 256) {
        int r = i >> 4, c = (i & 15) << 2;
        float4 b = *(const float4*)(wblk + r * DK_ + c);
        float* pb = Ws + r * 68 + c;
        pb[0] = b.x; pb[1] = b.y; pb[2] = b.z; pb[3] = b.w;
    }
    __syncthreads();
    float acc[8][4];
#pragma unroll
    for (int i = 0; i < 8; i++)
#pragma unroll
        for (int j = 0; j < 4; j++) acc[i][j] = 0.f;
#pragma unroll 4
    for (int d = 0; d < 128; d++) {
        float a[8];
#pragma unroll
        for (int ii = 0; ii < 8; ii++) a[ii] = Ys[(ty * 8 + ii) * 132 + d];
        float4 b4 = *(const float4*)(Ws + d * 68 + tx * 4);
#pragma unroll
        for (int ii = 0; ii < 8; ii++) {
            acc[ii][0] = fmaf(a[ii], b4.x, acc[ii][0]);
            acc[ii][1] = fmaf(a[ii], b4.y, acc[ii][1]);
            acc[ii][2] = fmaf(a[ii], b4.z, acc[ii][2]);
            acc[ii][3] = fmaf(a[ii], b4.w, acc[ii][3]);
        }
    }

    if (!kpath) {
        // Qf = |gelu(acc)|
        float* outp = g_Qf + ((size_t)h * S_ + sb * 128) * DK_;
#pragma unroll
        for (int ii = 0; ii < 8; ii++)
#pragma unroll
            for (int jj = 0; jj < 4; jj++)
                outp[(size_t)(ty * 8 + ii) * DK_ + tx * 4 + jj] = fabsf(gelu_f(acc[ii][jj]));
        return;
    }

    // K path: k2 = |sD| * gelu(acc); k3 = k2 + (k2 @ ik) * sD2; store |k3|^T
    float4 sd4 = *(const float4*)(sD + h * DK_ + tx * 4);
    float sdv[4] = {fabsf(sd4.x), fabsf(sd4.y), fabsf(sd4.z), fabsf(sd4.w)};
    float k2r[8][4];
#pragma unroll
    for (int ii = 0; ii < 8; ii++)
#pragma unroll
        for (int jj = 0; jj < 4; jj++)
            k2r[ii][jj] = sdv[jj] * gelu_f(acc[ii][jj]);
    __syncthreads();
    float* k2s = Ys;  // [128][68]
#pragma unroll
    for (int ii = 0; ii < 8; ii++) {
        float4 o = make_float4(k2r[ii][0], k2r[ii][1], k2r[ii][2], k2r[ii][3]);
        *(float4*)(k2s + (ty * 8 + ii) * 68 + tx * 4) = o;
    }
    for (int i = tid; i < 64 * 16; i += 256) {
        int r = i >> 4, c = (i & 15) << 2;
        float4 b = *(const float4*)(ik + (size_t)h * DK_ * DK_ + r * DK_ + c);
        float* pb = Ws + r * 68 + c;
        pb[0] = b.x; pb[1] = b.y; pb[2] = b.z; pb[3] = b.w;
    }
    __syncthreads();
    float acc2[8][4];
#pragma unroll
    for (int i = 0; i < 8; i++)
#pragma unroll
        for (int j = 0; j < 4; j++) acc2[i][j] = 0.f;
#pragma unroll 4
    for (int e = 0; e < 64; e++) {
        float a[8];
#pragma unroll
        for (int ii = 0; ii < 8; ii++) a[ii] = k2s[(ty * 8 + ii) * 68 + e];
        float4 b4 = *(const float4*)(Ws + e * 68 + tx * 4);
#pragma unroll
        for (int ii = 0; ii < 8; ii++) {
            acc2[ii][0] = fmaf(a[ii], b4.x, acc2[ii][0]);
            acc2[ii][1] = fmaf(a[ii], b4.y, acc2[ii][1]);
            acc2[ii][2] = fmaf(a[ii], b4.z, acc2[ii][2]);
            acc2[ii][3] = fmaf(a[ii], b4.w, acc2[ii][3]);
        }
    }
    float4 s24 = *(const float4*)(sD2 + h * DK_ + tx * 4);
    float s2v[4] = {s24.x, s24.y, s24.z, s24.w};
#pragma unroll
    for (int ii = 0; ii < 8; ii++)
#pragma unroll
        for (int jj = 0; jj < 4; jj++) {
            float k3 = k2r[ii][jj] + acc2[ii][jj] * s2v[jj];
            g_KfT[((size_t)h * DK_ + tx * 4 + jj) * S_ + sb * 128 + ty * 8 + ii] = fabsf(k3);
        }
}

// ---------------------------------------------------------------------------
// Stage 3 (WMMA tf32, double-buffered, 2 CTAs/SM): t-tile = 32
//   smem: qs[128][72] | ksT 2x[64][36] | ws[128][36] | vs 2x[32][136] | rs[128]
//   = 109,056 B -> 2 CTAs/SM, grid 256 = 1 wave
// ---------------------------------------------------------------------------
#define QS_LD  72
#define KS_LD  36
#define WS_LD  36
#define VS_LD  136

__global__ void __launch_bounds__(256, 2)
attn_kernel(const float* __restrict__ v, const int* __restrict__ mask,
            const float* __restrict__ sp_lse, const float* __restrict__ spw,
            float* __restrict__ out)
{
    extern __shared__ float sm[];
    float* qs  = sm;                          // [128][72]
    float* ksT = qs + 128 * QS_LD;            // 2 x [64][36]
    float* ws  = ksT + 2 * 64 * KS_LD;        // [128][36]
    float* vs  = ws + 128 * WS_LD;            // 2 x [32][136]
    float* rs  = vs + 2 * 32 * VS_LD;         // [128]
    const int h = blockIdx.y, sb = blockIdx.x, tid = threadIdx.x;
    const int warp = tid >> 5, lane = tid & 31;

    // load Qf block [128][64]
    const float* qblk = g_Qf + ((size_t)h * S_ + sb * 128) * DK_;
    for (int i = tid; i < 128 * 16; i += 256) {
        int rr = i >> 4, c = (i & 15) << 2;
        float4 a = *(const float4*)(qblk + (size_t)rr * DK_ + c);
        float* p = qs + rr * QS_LD + c;
        p[0] = a.x; p[1] = a.y; p[2] = a.z; p[3] = a.w;
    }
    if (tid < 128) rs[tid] = 0.f;

    const float* kbase = g_KfT + (size_t)h * DK_ * S_;
    // preload tile 0 into buffer 0
    {
#pragma unroll
        for (int j = 0; j < 2; j++) {
            int i = tid + j * 256; int rr = i >> 3, c = (i & 7) << 2;
            float4 a = *(const float4*)(kbase + (size_t)rr * S_ + c);
            float* p = ksT + rr * KS_LD + c;
            p[0] = a.x; p[1] = a.y; p[2] = a.z; p[3] = a.w;
        }
#pragma unroll
        for (int j = 0; j < 4; j++) {
            int i = tid + j * 256; int rr = i >> 5, c = (i & 31) << 2;
            float4 a = *(const float4*)(v + (size_t)rr * D_ + h * DH_ + c);
            float* p = vs + rr * VS_LD + c;
            p[0] = a.x; p[1] = a.y; p[2] = a.z; p[3] = a.w;
        }
    }

    wmma::fragment<wmma::accumulator, 16, 16, 8, float> accf[8];
#pragma unroll
    for (int n = 0; n < 8; n++) wmma::fill_fragment(accf[n], 0.f);
    float rloc = 0.f;

    // merge addressing: warp-local rows (row = 16*warp + lane/2, 16 cols each)
    const int mrow = 16 * warp + (lane >> 1);
    const int s_glob = sb * 128 + mrow;
    const int ch = (lane & 1) * 16;
    const int*   mbase = mask + (size_t)s_glob * S_ + ch;
    const float* wbase = spw + ((size_t)h * S_ + s_glob) * S_ + ch;
    __syncthreads();

    for (int tb = 0; tb < 64; tb++) {
        const int b = tb & 1;
        float* ksb = ksT + b * 64 * KS_LD;
        float* vsb = vs  + b * 32 * VS_LD;
        float* ksn = ksT + (b ^ 1) * 64 * KS_LD;
        float* vsn = vs  + (b ^ 1) * 32 * VS_LD;

        // register-stage next tiles (overlaps with MMA below)
        float4 knxt[2], vnxt[4];
        const bool more = (tb + 1 < 64);
        if (more) {
            const float* kn = kbase + (tb + 1) * 32;
#pragma unroll
            for (int j = 0; j < 2; j++) {
                int i = tid + j * 256; int rr = i >> 3, c = (i & 7) << 2;
                knxt[j] = *(const float4*)(kn + (size_t)rr * S_ + c);
            }
            const float* vn = v + (size_t)((tb + 1) * 32) * D_ + h * DH_;
#pragma unroll
            for (int j = 0; j < 4; j++) {
                int i = tid + j * 256; int rr = i >> 5, c = (i & 31) << 2;
                vnxt[j] = *(const float4*)(vn + (size_t)rr * D_ + c);
            }
        }

        // --- scores: P[16x32] per warp, K=64 (tf32) ---
        {
            wmma::fragment<wmma::accumulator, 16, 16, 8, float> fp[2];
#pragma unroll
            for (int n = 0; n < 2; n++) wmma::fill_fragment(fp[n], 0.f);
#pragma unroll
            for (int kk = 0; kk < 8; kk++) {
                wmma::fragment<wmma::matrix_a, 16, 16, 8, wmma::precision::tf32, wmma::row_major> fa;
                wmma::load_matrix_sync(fa, qs + (16 * warp) * QS_LD + kk * 8, QS_LD);
#pragma unroll
                for (int i = 0; i < fa.num_elements; i++) fa.x[i] = wmma::__float_to_tf32(fa.x[i]);
#pragma unroll
                for (int n = 0; n < 2; n++) {
                    wmma::fragment<wmma::matrix_b, 16, 16, 8, wmma::precision::tf32, wmma::row_major> fb;
                    wmma::load_matrix_sync(fb, ksb + (kk * 8) * KS_LD + n * 16, KS_LD);
#pragma unroll
                    for (int i = 0; i < fb.num_elements; i++) fb.x[i] = wmma::__float_to_tf32(fb.x[i]);
                    wmma::mma_sync(fp[n], fa, fb, fp[n]);
                }
            }
#pragma unroll
            for (int n = 0; n < 2; n++)
                wmma::store_matrix_sync(ws + (16 * warp) * WS_LD + n * 16, fp[n], WS_LD, wmma::mem_row_major);
        }
        __syncwarp();

        // --- merge (warp-local rows): w = mask ? lr+EPS : exp(spw); rowsum ---
        {
            const int*   mp = mbase + tb * 32;
            const float* wp = wbase + tb * 32;
            float* pw = ws + mrow * WS_LD + ch;
#pragma unroll
            for (int j = 0; j < 4; j++) {
                int4   m4 = *(const int4*)(mp + j * 4);
                float4 w4 = *(const float4*)(wp + j * 4);
                float4 p4 = *(float4*)(pw + j * 4);
                float o0 = m4.x ? (p4.x + EPS_) : __expf(w4.x);
                float o1 = m4.y ? (p4.y + EPS_) : __expf(w4.y);
                float o2 = m4.z ? (p4.z + EPS_) : __expf(w4.z);
                float o3 = m4.w ? (p4.w + EPS_) : __expf(w4.w);
                rloc += (m4.x ? p4.x : 0.f) + (m4.y ? p4.y : 0.f)
                      + (m4.z ? p4.z : 0.f) + (m4.w ? p4.w : 0.f);
                *(float4*)(pw + j * 4) = make_float4(o0, o1, o2, o3);
            }
        }
        __syncthreads();   // A: all ws rows merged

        // --- AV: O[16x128] per warp, K=32 (tf32) ---
#pragma unroll
        for (int kk = 0; kk < 4; kk++) {
            wmma::fragment<wmma::matrix_a, 16, 16, 8, wmma::precision::tf32, wmma::row_major> fa;
            wmma::load_matrix_sync(fa, ws + (16 * warp) * WS_LD + kk * 8, WS_LD);
#pragma unroll
            for (int i = 0; i < fa.num_elements; i++) fa.x[i] = wmma::__float_to_tf32(fa.x[i]);
#pragma unroll
            for (int n = 0; n < 8; n++) {
                wmma::fragment<wmma::matrix_b, 16, 16, 8, wmma::precision::tf32, wmma::row_major> fb;
                wmma::load_matrix_sync(fb, vsb + (kk * 8) * VS_LD + n * 16, VS_LD);
#pragma unroll
                for (int i = 0; i < fb.num_elements; i++) fb.x[i] = wmma::__float_to_tf32(fb.x[i]);
                wmma::mma_sync(accf[n], fa, fb, accf[n]);
            }
        }

        // store staged next tiles into the other buffer
        if (more) {
#pragma unroll
            for (int j = 0; j < 2; j++) {
                int i = tid + j * 256; int rr = i >> 3, c = (i & 7) << 2;
                float* p = ksn + rr * KS_LD + c;
                p[0] = knxt[j].x; p[1] = knxt[j].y; p[2] = knxt[j].z; p[3] = knxt[j].w;
            }
#pragma unroll
            for (int j = 0; j < 4; j++) {
                int i = tid + j * 256; int rr = i >> 5, c = (i & 31) << 2;
                float* p = vsn + rr * VS_LD + c;
                p[0] = vnxt[j].x; p[1] = vnxt[j].y; p[2] = vnxt[j].z; p[3] = vnxt[j].w;
            }
        }
        __syncthreads();   // B: next tiles ready; ws safe to overwrite
    }

    // store unnormalized output
    float* oblk = out + (size_t)(sb * 128 + 16 * warp) * D_ + h * DH_;
#pragma unroll
    for (int n = 0; n < 8; n++)
        wmma::store_matrix_sync(oblk + n * 16, accf[n], D_, wmma::mem_row_major);
    atomicAdd(&rs[mrow], rloc);
    __syncthreads();

    // normalize rows in place — full 128 columns (2 threads/row x 64 cols)
    {
        const int r = tid >> 1;
        const int oh = (tid & 1) * 64;
        float denom = rs[r] + EPS_ + __expf(sp_lse[h * S_ + sb * 128 + r]);
        float inv = 1.0f / denom;
        float* op = out + (size_t)(sb * 128 + r) * D_ + h * DH_ + oh;
#pragma unroll
        for (int j = 0; j < 16; j++) {
            float4 t = *(float4*)(op + j * 4);
            t.x *= inv; t.y *= inv; t.z *= inv; t.w *= inv;
            *(float4*)(op + j * 4) = t;
        }
    }
}

// ---------------------------------------------------------------------------
extern "C" void kernel_launch(void* const* d_in, const int* in_sizes, int n_in,
                              void* d_out, int out_size)
{
    (void)in_sizes; (void)n_in; (void)out_size;
    const float* q      = (const float*)d_in[0];
    const float* k      = (const float*)d_in[1];
    const float* v      = (const float*)d_in[2];
    const int*   mask   = (const int*)d_in[3];
    const float* sp_lse = (const float*)d_in[4];
    const float* spw    = (const float*)d_in[5];
    const float* kq1    = (const float*)d_in[6];
    const float* kk1    = (const float*)d_in[7];
    const float* kq2    = (const float*)d_in[8];
    const float* kk2    = (const float*)d_in[9];
    const float* ik     = (const float*)d_in[10];
    const float* sD     = (const float*)d_in[11];
    const float* sD2    = (const float*)d_in[12];
    float* out = (float*)d_out;

    float *yq = 0, *yk = 0;
    cudaGetSymbolAddress((void**)&yq, g_Yq);
    cudaGetSymbolAddress((void**)&yk, g_Yk);

    const int smem1 = 2 * 128 * 132 * 4;                                    // 135168
    const int smemB = (128 * 132 + 128 * 68) * 4;                           // 102400
    const int smemA = (128 * QS_LD + 2 * 64 * KS_LD + 128 * WS_LD + 2 * 32 * VS_LD + 128) * 4; // 109056
    cudaFuncSetAttribute(feat1_kernel, cudaFuncAttributeMaxDynamicSharedMemorySize, smem1);
    cudaFuncSetAttribute(feat2_kernel, cudaFuncAttributeMaxDynamicSharedMemorySize, smemB);
    cudaFuncSetAttribute(attn_kernel,  cudaFuncAttributeMaxDynamicSharedMemorySize, smemA);

    dim3 grid(S_ / 128, H_), blk(256);
    dim3 grid2(S_ / 128, H_, 2);
    feat1_kernel<<<grid, blk, smem1>>>(q, kq1, yq);
    feat1_kernel<<<grid, blk, smem1>>>(k, kk1, yk);
    feat2_kernel<<<grid2, blk, smemB>>>(yq, yk, kq2, kk2, ik, sD, sD2);
    attn_kernel<<<grid, blk, smemA>>>(v, mask, sp_lse, spw, out);
}

// round 7
// speedup vs baseline: 2.7224x; 1.9444x over previous
#include <cuda_runtime.h>
#include <cuda_fp16.h>
#include <math.h>

#define S_   2048
#define H_   16
#define D_   2048
#define DH_  128
#define DK_  64
#define EPS_ 1e-6f

// K features pre-scaled by 4096 (keeps fp16 normal); P scaled by 1024.
// Both folded exactly into fp32 epilogue.

static __device__ float  g_Yq[(size_t)H_ * S_ * DH_];
static __device__ float  g_Yk[(size_t)H_ * S_ * DH_];
static __device__ __half g_Qf[(size_t)H_ * S_ * DK_];   // [h][s][64]
static __device__ __half g_Kf[(size_t)H_ * S_ * DK_];   // [h][t][64], x4096
static __device__ __half g_VT[(size_t)H_ * DH_ * S_];   // [h][d][t]

__device__ __forceinline__ float gelu_f(float x) {
    return 0.5f * x * (1.0f + erff(x * 0.70710678118654752440f));
}

__device__ __forceinline__ void mma16816(float* c, const unsigned* a, const unsigned* b) {
    asm volatile(
        "mma.sync.aligned.m16n8k16.row.col.f32.f16.f16.f32 "
        "{%0,%1,%2,%3}, {%4,%5,%6,%7}, {%8,%9}, {%0,%1,%2,%3};\n"
        : "+f"(c[0]), "+f"(c[1]), "+f"(c[2]), "+f"(c[3])
        : "r"(a[0]), "r"(a[1]), "r"(a[2]), "r"(a[3]), "r"(b[0]), "r"(b[1]));
}

__device__ __forceinline__ unsigned h2u(float lo, float hi) {
    __half2 h = __floats2half2_rn(lo, hi);
    return *(unsigned*)&h;
}

// ---------------------------------------------------------------------------
// Stage 1: Y = gelu(X_head @ W1)   (fp32 SIMT, unchanged)
// ---------------------------------------------------------------------------
__global__ void __launch_bounds__(256, 1)
feat1_kernel(const float* __restrict__ x, const float* __restrict__ w,
             float* __restrict__ y)
{
    extern __shared__ float sm[];
    float* Xs = sm;               // [128][132]
    float* Ws = sm + 128 * 132;   // [128][132]
    const int h = blockIdx.y, sb = blockIdx.x, tid = threadIdx.x;
    const float* xblk = x + (size_t)(sb * 128) * D_ + h * DH_;
    const float* wblk = w + (size_t)h * DH_ * DH_;
    for (int i = tid; i < 128 * 32; i += 256) {
        int r = i >> 5, c = (i & 31) << 2;
        float4 a = *(const float4*)(xblk + (size_t)r * D_ + c);
        float4 b = *(const float4*)(wblk + r * DH_ + c);
        float* pa = Xs + r * 132 + c;
        pa[0] = a.x; pa[1] = a.y; pa[2] = a.z; pa[3] = a.w;
        float* pb = Ws + r * 132 + c;
        pb[0] = b.x; pb[1] = b.y; pb[2] = b.z; pb[3] = b.w;
    }
    __syncthreads();
    const int ty = tid >> 4, tx = tid & 15;
    float acc[8][8];
#pragma unroll
    for (int i = 0; i < 8; i++)
#pragma unroll
        for (int j = 0; j < 8; j++) acc[i][j] = 0.f;
#pragma unroll 4
    for (int d = 0; d < 128; d++) {
        float a[8], b[8];
#pragma unroll
        for (int ii = 0; ii < 8; ii++) a[ii] = Xs[(ty * 8 + ii) * 132 + d];
        float4 b0 = *(const float4*)(Ws + d * 132 + tx * 8);
        float4 b1 = *(const float4*)(Ws + d * 132 + tx * 8 + 4);
        b[0] = b0.x; b[1] = b0.y; b[2] = b0.z; b[3] = b0.w;
        b[4] = b1.x; b[5] = b1.y; b[6] = b1.z; b[7] = b1.w;
#pragma unroll
        for (int ii = 0; ii < 8; ii++)
#pragma unroll
            for (int jj = 0; jj < 8; jj++)
                acc[ii][jj] = fmaf(a[ii], b[jj], acc[ii][jj]);
    }
    float* yblk = y + ((size_t)h * S_ + sb * 128) * DH_;
#pragma unroll
    for (int ii = 0; ii < 8; ii++)
#pragma unroll
        for (int jj = 0; jj < 8; jj++)
            yblk[(size_t)(ty * 8 + ii) * DH_ + tx * 8 + jj] = gelu_f(acc[ii][jj]);
}

// ---------------------------------------------------------------------------
// Stage 2 fused: z=0 Q path -> g_Qf (half), z=1 K path -> g_Kf (half, x4096)
// ---------------------------------------------------------------------------
__global__ void __launch_bounds__(256, 1)
feat2_kernel(const float* __restrict__ yq, const float* __restrict__ yk,
             const float* __restrict__ wq2, const float* __restrict__ wk2,
             const float* __restrict__ ik, const float* __restrict__ sD,
             const float* __restrict__ sD2)
{
    extern __shared__ float sm[];
    float* Ys = sm;               // [128][132]
    float* Ws = sm + 128 * 132;   // [128][68]
    const int h = blockIdx.y, sb = blockIdx.x, tid = threadIdx.x;
    const int ty = tid >> 4, tx = tid & 15;
    const int kpath = blockIdx.z;
    const float* y  = kpath ? yk : yq;
    const float* w2 = kpath ? wk2 : wq2;

    const float* yblk = y + ((size_t)h * S_ + sb * 128) * DH_;
    const float* wblk = w2 + (size_t)h * DH_ * DK_;
    for (int i = tid; i < 128 * 32; i += 256) {
        int r = i >> 5, c = (i & 31) << 2;
        float4 a = *(const float4*)(yblk + (size_t)r * DH_ + c);
        float* pa = Ys + r * 132 + c;
        pa[0] = a.x; pa[1] = a.y; pa[2] = a.z; pa[3] = a.w;
    }
    for (int i = tid; i < 128 * 16; i += 256) {
        int r = i >> 4, c = (i & 15) << 2;
        float4 b = *(const float4*)(wblk + r * DK_ + c);
        float* pb = Ws + r * 68 + c;
        pb[0] = b.x; pb[1] = b.y; pb[2] = b.z; pb[3] = b.w;
    }
    __syncthreads();
    float acc[8][4];
#pragma unroll
    for (int i = 0; i < 8; i++)
#pragma unroll
        for (int j = 0; j < 4; j++) acc[i][j] = 0.f;
#pragma unroll 4
    for (int d = 0; d < 128; d++) {
        float a[8];
#pragma unroll
        for (int ii = 0; ii < 8; ii++) a[ii] = Ys[(ty * 8 + ii) * 132 + d];
        float4 b4 = *(const float4*)(Ws + d * 68 + tx * 4);
#pragma unroll
        for (int ii = 0; ii < 8; ii++) {
            acc[ii][0] = fmaf(a[ii], b4.x, acc[ii][0]);
            acc[ii][1] = fmaf(a[ii], b4.y, acc[ii][1]);
            acc[ii][2] = fmaf(a[ii], b4.z, acc[ii][2]);
            acc[ii][3] = fmaf(a[ii], b4.w, acc[ii][3]);
        }
    }

    if (!kpath) {
        __half* outp = g_Qf + ((size_t)h * S_ + sb * 128) * DK_;
#pragma unroll
        for (int ii = 0; ii < 8; ii++)
#pragma unroll
            for (int jj = 0; jj < 4; jj++)
                outp[(size_t)(ty * 8 + ii) * DK_ + tx * 4 + jj] =
                    __float2half(fabsf(gelu_f(acc[ii][jj])));
        return;
    }

    float4 sd4 = *(const float4*)(sD + h * DK_ + tx * 4);
    float sdv[4] = {fabsf(sd4.x), fabsf(sd4.y), fabsf(sd4.z), fabsf(sd4.w)};
    float k2r[8][4];
#pragma unroll
    for (int ii = 0; ii < 8; ii++)
#pragma unroll
        for (int jj = 0; jj < 4; jj++)
            k2r[ii][jj] = sdv[jj] * gelu_f(acc[ii][jj]);
    __syncthreads();
    float* k2s = Ys;  // [128][68]
#pragma unroll
    for (int ii = 0; ii < 8; ii++) {
        float4 o = make_float4(k2r[ii][0], k2r[ii][1], k2r[ii][2], k2r[ii][3]);
        *(float4*)(k2s + (ty * 8 + ii) * 68 + tx * 4) = o;
    }
    for (int i = tid; i < 64 * 16; i += 256) {
        int r = i >> 4, c = (i & 15) << 2;
        float4 b = *(const float4*)(ik + (size_t)h * DK_ * DK_ + r * DK_ + c);
        float* pb = Ws + r * 68 + c;
        pb[0] = b.x; pb[1] = b.y; pb[2] = b.z; pb[3] = b.w;
    }
    __syncthreads();
    float acc2[8][4];
#pragma unroll
    for (int i = 0; i < 8; i++)
#pragma unroll
        for (int j = 0; j < 4; j++) acc2[i][j] = 0.f;
#pragma unroll 4
    for (int e = 0; e < 64; e++) {
        float a[8];
#pragma unroll
        for (int ii = 0; ii < 8; ii++) a[ii] = k2s[(ty * 8 + ii) * 68 + e];
        float4 b4 = *(const float4*)(Ws + e * 68 + tx * 4);
#pragma unroll
        for (int ii = 0; ii < 8; ii++) {
            acc2[ii][0] = fmaf(a[ii], b4.x, acc2[ii][0]);
            acc2[ii][1] = fmaf(a[ii], b4.y, acc2[ii][1]);
            acc2[ii][2] = fmaf(a[ii], b4.z, acc2[ii][2]);
            acc2[ii][3] = fmaf(a[ii], b4.w, acc2[ii][3]);
        }
    }
    float4 s24 = *(const float4*)(sD2 + h * DK_ + tx * 4);
    float s2v[4] = {s24.x, s24.y, s24.z, s24.w};
    __half* outp = g_Kf + ((size_t)h * S_ + sb * 128) * DK_;
#pragma unroll
    for (int ii = 0; ii < 8; ii++)
#pragma unroll
        for (int jj = 0; jj < 4; jj++) {
            float k3 = k2r[ii][jj] + acc2[ii][jj] * s2v[jj];
            outp[(size_t)(ty * 8 + ii) * DK_ + tx * 4 + jj] =
                __float2half(fabsf(k3) * 4096.0f);
        }
}

// ---------------------------------------------------------------------------
// V transpose per head: g_VT[h][d][t] = (half) v[t][h*128+d]
// ---------------------------------------------------------------------------
__global__ void __launch_bounds__(256, 1)
vtrans_kernel(const float* __restrict__ v)
{
    __shared__ __half Vs[128][136];
    const int h = blockIdx.y, tb = blockIdx.x, tid = threadIdx.x;
    for (int i = tid; i < 128 * 32; i += 256) {
        int t = i >> 5, ds = (i & 31) << 2;
        float4 f = *(const float4*)(v + (size_t)(tb * 128 + t) * D_ + h * DH_ + ds);
        Vs[ds + 0][t] = __float2half(f.x);
        Vs[ds + 1][t] = __float2half(f.y);
        Vs[ds + 2][t] = __float2half(f.z);
        Vs[ds + 3][t] = __float2half(f.w);
    }
    __syncthreads();
    for (int i = tid; i < 128 * 16; i += 256) {
        int d = i >> 4, seg = (i & 15) << 3;
        *(uint4*)(g_VT + ((size_t)h * DH_ + d) * S_ + tb * 128 + seg) =
            *(const uint4*)&Vs[d][seg];
    }
}

// ---------------------------------------------------------------------------
// Stage 3: register-resident fp16 mma pipeline
// grid (S/128, H), 256 thr (8 warps x 16 rows), t-tile = 32, 64 iters
// ---------------------------------------------------------------------------
__global__ void __launch_bounds__(256, 2)
attn2_kernel(const int* __restrict__ mask, const float* __restrict__ sp_lse,
             const float* __restrict__ spw, float* __restrict__ out)
{
    __shared__ __half Ks[2][32][72];     // [buf][t][e]
    __shared__ __half Vs[2][128][40];    // [buf][d][t]
    __shared__ float  rs[128];

    const int h = blockIdx.y, sb = blockIdx.x, tid = threadIdx.x;
    const int warp = tid >> 5, lane = tid & 31;
    const int tq = lane >> 2, tc = lane & 3;
    const int r0l = warp * 16 + tq;            // local rows r0l, r0l+8
    const int gr0 = sb * 128 + r0l;

    const __half* qp0 = g_Qf + ((size_t)h * S_ + gr0) * DK_;
    const __half* qp1 = qp0 + 8 * DK_;
    const __half* kbase = g_Kf + (size_t)h * S_ * DK_;
    const __half* vbase = g_VT + (size_t)h * DH_ * S_;

    // staging indices
    const int krow = tid >> 3, kseg = (tid & 7) << 3;       // K: 32 rows x 128B
    const int vd = tid >> 1, vseg = (tid & 1) << 4;         // VT: 128 rows x 64B

    float O[16][4];
#pragma unroll
    for (int n = 0; n < 16; n++)
#pragma unroll
        for (int j = 0; j < 4; j++) O[n][j] = 0.f;
    float rl0 = 0.f, rl1 = 0.f;

    // preload tile 0 direct, stage tile 1 in regs
    {
        *(uint4*)&Ks[0][krow][kseg] = *(const uint4*)(kbase + (size_t)krow * DK_ + kseg);
        const __half* vsrc = vbase + (size_t)vd * S_ + vseg;
        *(uint4*)&Vs[0][vd][vseg]     = *(const uint4*)vsrc;
        *(uint4*)&Vs[0][vd][vseg + 8] = *(const uint4*)(vsrc + 8);
    }
    uint4 kst = *(const uint4*)(kbase + (size_t)(32 + krow) * DK_ + kseg);
    uint4 vst0, vst1;
    {
        const __half* vsrc = vbase + (size_t)vd * S_ + 32 + vseg;
        vst0 = *(const uint4*)vsrc;
        vst1 = *(const uint4*)(vsrc + 8);
    }
    __syncthreads();

    const size_t mrow0 = (size_t)gr0 * S_;
    const size_t mrow1 = (size_t)(gr0 + 8) * S_;
    const size_t wrow0 = ((size_t)h * S_ + gr0) * S_;
    const size_t wrow1 = wrow0 + 8 * S_;

    for (int tb = 0; tb < 64; tb++) {
        const int buf = tb & 1;
        if (tb + 1 < 64) {
            *(uint4*)&Ks[buf ^ 1][krow][kseg]   = kst;
            *(uint4*)&Vs[buf ^ 1][vd][vseg]     = vst0;
            *(uint4*)&Vs[buf ^ 1][vd][vseg + 8] = vst1;
        }
        if (tb + 2 < 64) {
            kst = *(const uint4*)(kbase + (size_t)((tb + 2) * 32 + krow) * DK_ + kseg);
            const __half* vsrc = vbase + (size_t)vd * S_ + (tb + 2) * 32 + vseg;
            vst0 = *(const uint4*)vsrc;
            vst1 = *(const uint4*)(vsrc + 8);
        }

        // --- scores: S[4 n-tiles][4], K=64 over 4 k-chunks ---
        float S[4][4];
#pragma unroll
        for (int j = 0; j < 4; j++)
#pragma unroll
            for (int e = 0; e < 4; e++) S[j][e] = 0.f;
#pragma unroll
        for (int kc = 0; kc < 4; kc++) {
            unsigned a[4];
            a[0] = *(const unsigned*)(qp0 + kc * 16 + tc * 2);
            a[1] = *(const unsigned*)(qp1 + kc * 16 + tc * 2);
            a[2] = *(const unsigned*)(qp0 + kc * 16 + tc * 2 + 8);
            a[3] = *(const unsigned*)(qp1 + kc * 16 + tc * 2 + 8);
#pragma unroll
            for (int j = 0; j < 4; j++) {
                unsigned b[2];
                b[0] = *(const unsigned*)&Ks[buf][8 * j + tq][kc * 16 + tc * 2];
                b[1] = *(const unsigned*)&Ks[buf][8 * j + tq][kc * 16 + tc * 2 + 8];
                mma16816(S[j], a, b);
            }
        }

        // --- merge in registers (lr_true = S/4096; P stored x1024) ---
        const int cbase = tb * 32 + tc * 2;
#pragma unroll
        for (int j = 0; j < 4; j++) {
            const int col = cbase + 8 * j;
            int2 m0 = *(const int2*)(mask + mrow0 + col);
            int2 m1 = *(const int2*)(mask + mrow1 + col);
            float2 w0 = *(const float2*)(spw + wrow0 + col);
            float2 w1 = *(const float2*)(spw + wrow1 + col);
            float s0 = S[j][0], s1 = S[j][1], s2 = S[j][2], s3 = S[j][3];
            rl0 += (m0.x ? s0 : 0.f) + (m0.y ? s1 : 0.f);
            rl1 += (m1.x ? s2 : 0.f) + (m1.y ? s3 : 0.f);
            S[j][0] = m0.x ? fmaf(s0, 0.25f, 1.024e-3f) : __expf(w0.x) * 1024.f;
            S[j][1] = m0.y ? fmaf(s1, 0.25f, 1.024e-3f) : __expf(w0.y) * 1024.f;
            S[j][2] = m1.x ? fmaf(s2, 0.25f, 1.024e-3f) : __expf(w1.x) * 1024.f;
            S[j][3] = m1.y ? fmaf(s3, 0.25f, 1.024e-3f) : __expf(w1.y) * 1024.f;
        }

        // --- AV: O[16 n-tiles] += P[16x32] @ V[32x128] ---
#pragma unroll
        for (int kc = 0; kc < 2; kc++) {
            unsigned a[4];
            a[0] = h2u(S[2 * kc][0],     S[2 * kc][1]);
            a[1] = h2u(S[2 * kc][2],     S[2 * kc][3]);
            a[2] = h2u(S[2 * kc + 1][0], S[2 * kc + 1][1]);
            a[3] = h2u(S[2 * kc + 1][2], S[2 * kc + 1][3]);
#pragma unroll
            for (int n = 0; n < 16; n++) {
                unsigned b[2];
                b[0] = *(const unsigned*)&Vs[buf][8 * n + tq][kc * 16 + tc * 2];
                b[1] = *(const unsigned*)&Vs[buf][8 * n + tq][kc * 16 + tc * 2 + 8];
                mma16816(O[n], a, b);
            }
        }
        __syncthreads();
    }

    // row-sum reduce across the 4 tc lanes, store (rows unique per group)
    rl0 += __shfl_xor_sync(0xFFFFFFFFu, rl0, 1);
    rl0 += __shfl_xor_sync(0xFFFFFFFFu, rl0, 2);
    rl1 += __shfl_xor_sync(0xFFFFFFFFu, rl1, 1);
    rl1 += __shfl_xor_sync(0xFFFFFFFFu, rl1, 2);
    if (tc == 0) { rs[r0l] = rl0; rs[r0l + 8] = rl1; }
    __syncthreads();

    const float den0 = rs[r0l]     * (1.f / 4096.f) + EPS_ + __expf(sp_lse[h * S_ + gr0]);
    const float den1 = rs[r0l + 8] * (1.f / 4096.f) + EPS_ + __expf(sp_lse[h * S_ + gr0 + 8]);
    const float inv0 = 1.f / (1024.f * den0);
    const float inv1 = 1.f / (1024.f * den1);
    float* op0 = out + (size_t)gr0 * D_ + h * DH_;
    float* op1 = op0 + 8 * D_;
#pragma unroll
    for (int n = 0; n < 16; n++) {
        float2 t0 = make_float2(O[n][0] * inv0, O[n][1] * inv0);
        float2 t1 = make_float2(O[n][2] * inv1, O[n][3] * inv1);
        *(float2*)(op0 + 8 * n + tc * 2) = t0;
        *(float2*)(op1 + 8 * n + tc * 2) = t1;
    }
}

// ---------------------------------------------------------------------------
extern "C" void kernel_launch(void* const* d_in, const int* in_sizes, int n_in,
                              void* d_out, int out_size)
{
    (void)in_sizes; (void)n_in; (void)out_size;
    const float* q      = (const float*)d_in[0];
    const float* k      = (const float*)d_in[1];
    const float* v      = (const float*)d_in[2];
    const int*   mask   = (const int*)d_in[3];
    const float* sp_lse = (const float*)d_in[4];
    const float* spw    = (const float*)d_in[5];
    const float* kq1    = (const float*)d_in[6];
    const float* kk1    = (const float*)d_in[7];
    const float* kq2    = (const float*)d_in[8];
    const float* kk2    = (const float*)d_in[9];
    const float* ik     = (const float*)d_in[10];
    const float* sD     = (const float*)d_in[11];
    const float* sD2    = (const float*)d_in[12];
    float* out = (float*)d_out;

    float *yq = 0, *yk = 0;
    cudaGetSymbolAddress((void**)&yq, g_Yq);
    cudaGetSymbolAddress((void**)&yk, g_Yk);

    const int smem1 = 2 * 128 * 132 * 4;
    const int smemB = (128 * 132 + 128 * 68) * 4;
    cudaFuncSetAttribute(feat1_kernel, cudaFuncAttributeMaxDynamicSharedMemorySize, smem1);
    cudaFuncSetAttribute(feat2_kernel, cudaFuncAttributeMaxDynamicSharedMemorySize, smemB);

    dim3 grid(S_ / 128, H_), blk(256);
    dim3 grid2(S_ / 128, H_, 2);
    feat1_kernel<<<grid, blk, smem1>>>(q, kq1, yq);
    feat1_kernel<<<grid, blk, smem1>>>(k, kk1, yk);
    feat2_kernel<<<grid2, blk, smemB>>>(yq, yk, kq2, kk2, ik, sD, sD2);
    vtrans_kernel<<<grid, blk>>>(v);
    attn2_kernel<<<grid, blk>>>(mask, sp_lse, spw, out);
}

// round 8
// speedup vs baseline: 3.1008x; 1.1390x over previous
#include <cuda_runtime.h>
#include <cuda_fp16.h>
#include <math.h>

#define S_   2048
#define H_   16
#define D_   2048
#define DH_  128
#define DK_  64
#define EPS_ 1e-6f

// K features pre-scaled by 4096; merged P scaled by 1024; both folded exactly
// into the fp32 epilogue.

static __device__ __half g_Qf[(size_t)H_ * S_ * DK_];   // [h][s][64]
static __device__ __half g_Kf[(size_t)H_ * S_ * DK_];   // [h][t][64], x4096
static __device__ __half g_VT[(size_t)H_ * DH_ * S_];   // [h][d][t]

__device__ __forceinline__ float gelu_f(float x) {
    return 0.5f * x * (1.0f + erff(x * 0.70710678118654752440f));
}

__device__ __forceinline__ void mma16816(float* c, const unsigned* a, const unsigned* b) {
    asm volatile(
        "mma.sync.aligned.m16n8k16.row.col.f32.f16.f16.f32 "
        "{%0,%1,%2,%3}, {%4,%5,%6,%7}, {%8,%9}, {%0,%1,%2,%3};\n"
        : "+f"(c[0]), "+f"(c[1]), "+f"(c[2]), "+f"(c[3])
        : "r"(a[0]), "r"(a[1]), "r"(a[2]), "r"(a[3]), "r"(b[0]), "r"(b[1]));
}

__device__ __forceinline__ unsigned h2u(float lo, float hi) {
    __half2 h = __floats2half2_rn(lo, hi);
    return *(unsigned*)&h;
}

__device__ __forceinline__ void cpa16(unsigned dst, const void* src) {
    asm volatile("cp.async.cg.shared.global [%0], [%1], 16;" :: "r"(dst), "l"(src));
}
#define CP_COMMIT()  asm volatile("cp.async.commit_group;")
#define CP_WAIT1()   asm volatile("cp.async.wait_group 1;")

// ---------------------------------------------------------------------------
// Fused feature kernel: z=0 Q path, z=1 K path.
//  stage1: Y = gelu(X @ W1)  (Y kept in smem)
//  stage2: Q: Qf=|gelu(Y@W2)| ; K: k2=|sD|*gelu(Y@W2); k3=k2+(k2@ik)*sD2 -> |k3|*4096
// grid (16,16,2), 256 threads
// ---------------------------------------------------------------------------
__global__ void __launch_bounds__(256, 1)
featfused_kernel(const float* __restrict__ q, const float* __restrict__ k,
                 const float* __restrict__ wq1, const float* __restrict__ wk1,
                 const float* __restrict__ wq2, const float* __restrict__ wk2,
                 const float* __restrict__ ik, const float* __restrict__ sD,
                 const float* __restrict__ sD2)
{
    extern __shared__ float sm[];
    float* Xs = sm;               // [128][132]; later Y, later k2s[128][68]
    float* Ws = sm + 128 * 132;   // [128][132]; later W2 [128][68], later ik [64][68]
    const int h = blockIdx.y, sb = blockIdx.x, tid = threadIdx.x;
    const int ty = tid >> 4, tx = tid & 15;
    const int kpath = blockIdx.z;
    const float* x  = kpath ? k : q;
    const float* w1 = kpath ? wk1 : wq1;
    const float* w2 = kpath ? wk2 : wq2;

    // ---- stage 1 ----
    const float* xblk = x + (size_t)(sb * 128) * D_ + h * DH_;
    const float* w1b  = w1 + (size_t)h * DH_ * DH_;
    for (int i = tid; i < 128 * 32; i += 256) {
        int r = i >> 5, c = (i & 31) << 2;
        float4 a = *(const float4*)(xblk + (size_t)r * D_ + c);
        float4 b = *(const float4*)(w1b + r * DH_ + c);
        float* pa = Xs + r * 132 + c;
        pa[0] = a.x; pa[1] = a.y; pa[2] = a.z; pa[3] = a.w;
        float* pb = Ws + r * 132 + c;
        pb[0] = b.x; pb[1] = b.y; pb[2] = b.z; pb[3] = b.w;
    }
    __syncthreads();
    float acc[8][8];
#pragma unroll
    for (int i = 0; i < 8; i++)
#pragma unroll
        for (int j = 0; j < 8; j++) acc[i][j] = 0.f;
#pragma unroll 4
    for (int d = 0; d < 128; d++) {
        float a[8], b[8];
#pragma unroll
        for (int ii = 0; ii < 8; ii++) a[ii] = Xs[(ty * 8 + ii) * 132 + d];
        float4 b0 = *(const float4*)(Ws + d * 132 + tx * 8);
        float4 b1 = *(const float4*)(Ws + d * 132 + tx * 8 + 4);
        b[0] = b0.x; b[1] = b0.y; b[2] = b0.z; b[3] = b0.w;
        b[4] = b1.x; b[5] = b1.y; b[6] = b1.z; b[7] = b1.w;
#pragma unroll
        for (int ii = 0; ii < 8; ii++)
#pragma unroll
            for (int jj = 0; jj < 8; jj++)
                acc[ii][jj] = fmaf(a[ii], b[jj], acc[ii][jj]);
    }
    __syncthreads();
    // Y -> Xs (stride 132); W2 -> Ws[128][68]
#pragma unroll
    for (int ii = 0; ii < 8; ii++)
#pragma unroll
        for (int jj = 0; jj < 8; jj++)
            Xs[(ty * 8 + ii) * 132 + tx * 8 + jj] = gelu_f(acc[ii][jj]);
    const float* w2b = w2 + (size_t)h * DH_ * DK_;
    for (int i = tid; i < 128 * 16; i += 256) {
        int r = i >> 4, c = (i & 15) << 2;
        float4 b = *(const float4*)(w2b + r * DK_ + c);
        float* pb = Ws + r * 68 + c;
        pb[0] = b.x; pb[1] = b.y; pb[2] = b.z; pb[3] = b.w;
    }
    __syncthreads();

    // ---- stage 2 ----
    float acc2[8][4];
#pragma unroll
    for (int i = 0; i < 8; i++)
#pragma unroll
        for (int j = 0; j < 4; j++) acc2[i][j] = 0.f;
#pragma unroll 4
    for (int d = 0; d < 128; d++) {
        float a[8];
#pragma unroll
        for (int ii = 0; ii < 8; ii++) a[ii] = Xs[(ty * 8 + ii) * 132 + d];
        float4 b4 = *(const float4*)(Ws + d * 68 + tx * 4);
#pragma unroll
        for (int ii = 0; ii < 8; ii++) {
            acc2[ii][0] = fmaf(a[ii], b4.x, acc2[ii][0]);
            acc2[ii][1] = fmaf(a[ii], b4.y, acc2[ii][1]);
            acc2[ii][2] = fmaf(a[ii], b4.z, acc2[ii][2]);
            acc2[ii][3] = fmaf(a[ii], b4.w, acc2[ii][3]);
        }
    }

    if (!kpath) {
        __half* outp = g_Qf + ((size_t)h * S_ + sb * 128) * DK_;
#pragma unroll
        for (int ii = 0; ii < 8; ii++)
#pragma unroll
            for (int jj = 0; jj < 4; jj++)
                outp[(size_t)(ty * 8 + ii) * DK_ + tx * 4 + jj] =
                    __float2half(fabsf(gelu_f(acc2[ii][jj])));
        return;
    }

    // K path
    float4 sd4 = *(const float4*)(sD + h * DK_ + tx * 4);
    float sdv[4] = {fabsf(sd4.x), fabsf(sd4.y), fabsf(sd4.z), fabsf(sd4.w)};
    float k2r[8][4];
#pragma unroll
    for (int ii = 0; ii < 8; ii++)
#pragma unroll
        for (int jj = 0; jj < 4; jj++)
            k2r[ii][jj] = sdv[jj] * gelu_f(acc2[ii][jj]);
    __syncthreads();
    float* k2s = Xs;  // [128][68]
#pragma unroll
    for (int ii = 0; ii < 8; ii++) {
        float4 o = make_float4(k2r[ii][0], k2r[ii][1], k2r[ii][2], k2r[ii][3]);
        *(float4*)(k2s + (ty * 8 + ii) * 68 + tx * 4) = o;
    }
    for (int i = tid; i < 64 * 16; i += 256) {
        int r = i >> 4, c = (i & 15) << 2;
        float4 b = *(const float4*)(ik + (size_t)h * DK_ * DK_ + r * DK_ + c);
        float* pb = Ws + r * 68 + c;
        pb[0] = b.x; pb[1] = b.y; pb[2] = b.z; pb[3] = b.w;
    }
    __syncthreads();
    float acc3[8][4];
#pragma unroll
    for (int i = 0; i < 8; i++)
#pragma unroll
        for (int j = 0; j < 4; j++) acc3[i][j] = 0.f;
#pragma unroll 4
    for (int e = 0; e < 64; e++) {
        float a[8];
#pragma unroll
        for (int ii = 0; ii < 8; ii++) a[ii] = k2s[(ty * 8 + ii) * 68 + e];
        float4 b4 = *(const float4*)(Ws + e * 68 + tx * 4);
#pragma unroll
        for (int ii = 0; ii < 8; ii++) {
            acc3[ii][0] = fmaf(a[ii], b4.x, acc3[ii][0]);
            acc3[ii][1] = fmaf(a[ii], b4.y, acc3[ii][1]);
            acc3[ii][2] = fmaf(a[ii], b4.z, acc3[ii][2]);
            acc3[ii][3] = fmaf(a[ii], b4.w, acc3[ii][3]);
        }
    }
    float4 s24 = *(const float4*)(sD2 + h * DK_ + tx * 4);
    float s2v[4] = {s24.x, s24.y, s24.z, s24.w};
    __half* outp = g_Kf + ((size_t)h * S_ + sb * 128) * DK_;
#pragma unroll
    for (int ii = 0; ii < 8; ii++)
#pragma unroll
        for (int jj = 0; jj < 4; jj++) {
            float k3 = k2r[ii][jj] + acc3[ii][jj] * s2v[jj];
            outp[(size_t)(ty * 8 + ii) * DK_ + tx * 4 + jj] =
                __float2half(fabsf(k3) * 4096.0f);
        }
}

// ---------------------------------------------------------------------------
// V transpose per head: g_VT[h][d][t] = (half) v[t][h*128+d]
// ---------------------------------------------------------------------------
__global__ void __launch_bounds__(256, 1)
vtrans_kernel(const float* __restrict__ v)
{
    __shared__ __half Vs[128][136];
    const int h = blockIdx.y, tb = blockIdx.x, tid = threadIdx.x;
    for (int i = tid; i < 128 * 32; i += 256) {
        int t = i >> 5, ds = (i & 31) << 2;
        float4 f = *(const float4*)(v + (size_t)(tb * 128 + t) * D_ + h * DH_ + ds);
        Vs[ds + 0][t] = __float2half(f.x);
        Vs[ds + 1][t] = __float2half(f.y);
        Vs[ds + 2][t] = __float2half(f.z);
        Vs[ds + 3][t] = __float2half(f.w);
    }
    __syncthreads();
    for (int i = tid; i < 128 * 16; i += 256) {
        int d = i >> 4, seg = (i & 15) << 3;
        *(uint4*)(g_VT + ((size_t)h * DH_ + d) * S_ + tb * 128 + seg) =
            *(const uint4*)&Vs[d][seg];
    }
}

// ---------------------------------------------------------------------------
// Stage 3: fp16 mma pipeline, 3-stage cp.async, spw prefetched into regs
// grid (16,16), 256 thr (8 warps x 16 rows), t-tile = 32, 64 iters
// ---------------------------------------------------------------------------
__global__ void __launch_bounds__(256, 2)
attn2_kernel(const int* __restrict__ mask, const float* __restrict__ sp_lse,
             const float* __restrict__ spw, float* __restrict__ out)
{
    __shared__ __half Ks[3][32][72];     // [stage][t][e]
    __shared__ __half Vs[3][128][40];    // [stage][d][t]
    __shared__ float  rs[128];

    const int h = blockIdx.y, sb = blockIdx.x, tid = threadIdx.x;
    const int warp = tid >> 5, lane = tid & 31;
    const int tq = lane >> 2, tc = lane & 3;
    const int r0l = warp * 16 + tq;
    const int gr0 = sb * 128 + r0l;

    const __half* qp0 = g_Qf + ((size_t)h * S_ + gr0) * DK_;
    const __half* qp1 = qp0 + 8 * DK_;
    const __half* kbase = g_Kf + (size_t)h * S_ * DK_;
    const __half* vbase = g_VT + (size_t)h * DH_ * S_;

    // cp.async staging indices
    const int krow = tid >> 3, kseg = (tid & 7) << 3;   // 32 rows x 8 segs (16B)
    const int vrowA = tid >> 2, vsegA = (tid & 3) << 3; // 128 rows x 4 segs, 2 per thread
    const unsigned ks_sm = (unsigned)__cvta_generic_to_shared(&Ks[0][0][0]);
    const unsigned vs_sm = (unsigned)__cvta_generic_to_shared(&Vs[0][0][0]);

    float O[16][4];
#pragma unroll
    for (int n = 0; n < 16; n++)
#pragma unroll
        for (int j = 0; j < 4; j++) O[n][j] = 0.f;
    float rl0 = 0.f, rl1 = 0.f;

    // prologue: stage tiles 0 and 1
#pragma unroll
    for (int t = 0; t < 2; t++) {
        cpa16(ks_sm + (t * 32 * 72 + krow * 72 + kseg) * 2,
              kbase + (size_t)(t * 32 + krow) * DK_ + kseg);
        cpa16(vs_sm + (t * 128 * 40 + vrowA * 40 + vsegA) * 2,
              vbase + (size_t)vrowA * S_ + t * 32 + vsegA);
        cpa16(vs_sm + (t * 128 * 40 + (vrowA + 64) * 40 + vsegA) * 2,
              vbase + (size_t)(vrowA + 64) * S_ + t * 32 + vsegA);
        CP_COMMIT();
    }

    const size_t mrow0 = (size_t)gr0 * S_;
    const size_t mrow1 = (size_t)(gr0 + 8) * S_;
    const size_t wrow0 = ((size_t)h * S_ + gr0) * S_;
    const size_t wrow1 = wrow0 + 8 * S_;

    int buf = 0, bufn = 2;
    for (int tb = 0; tb < 64; tb++) {
        CP_WAIT1();
        __syncthreads();

        // early spw loads for this tile (DRAM latency hidden behind scores)
        const int cbase = tb * 32 + tc * 2;
        float2 w0r[4], w1r[4];
#pragma unroll
        for (int j = 0; j < 4; j++) {
            w0r[j] = *(const float2*)(spw + wrow0 + cbase + 8 * j);
            w1r[j] = *(const float2*)(spw + wrow1 + cbase + 8 * j);
        }

        // prefetch tile tb+2 into bufn
        if (tb + 2 < 64) {
            cpa16(ks_sm + (bufn * 32 * 72 + krow * 72 + kseg) * 2,
                  kbase + (size_t)((tb + 2) * 32 + krow) * DK_ + kseg);
            cpa16(vs_sm + (bufn * 128 * 40 + vrowA * 40 + vsegA) * 2,
                  vbase + (size_t)vrowA * S_ + (tb + 2) * 32 + vsegA);
            cpa16(vs_sm + (bufn * 128 * 40 + (vrowA + 64) * 40 + vsegA) * 2,
                  vbase + (size_t)(vrowA + 64) * S_ + (tb + 2) * 32 + vsegA);
        }
        CP_COMMIT();

        // --- scores: S[4 n-tiles][4], K=64 ---
        float S[4][4];
#pragma unroll
        for (int j = 0; j < 4; j++)
#pragma unroll
            for (int e = 0; e < 4; e++) S[j][e] = 0.f;
#pragma unroll
        for (int kc = 0; kc < 4; kc++) {
            unsigned a[4];
            a[0] = *(const unsigned*)(qp0 + kc * 16 + tc * 2);
            a[1] = *(const unsigned*)(qp1 + kc * 16 + tc * 2);
            a[2] = *(const unsigned*)(qp0 + kc * 16 + tc * 2 + 8);
            a[3] = *(const unsigned*)(qp1 + kc * 16 + tc * 2 + 8);
#pragma unroll
            for (int j = 0; j < 4; j++) {
                unsigned b[2];
                b[0] = *(const unsigned*)&Ks[buf][8 * j + tq][kc * 16 + tc * 2];
                b[1] = *(const unsigned*)&Ks[buf][8 * j + tq][kc * 16 + tc * 2 + 8];
                mma16816(S[j], a, b);
            }
        }

        // --- merge in registers (lr_true = S/4096; P stored x1024) ---
#pragma unroll
        for (int j = 0; j < 4; j++) {
            const int col = cbase + 8 * j;
            int2 m0 = *(const int2*)(mask + mrow0 + col);
            int2 m1 = *(const int2*)(mask + mrow1 + col);
            float s0 = S[j][0], s1 = S[j][1], s2 = S[j][2], s3 = S[j][3];
            rl0 += (m0.x ? s0 : 0.f) + (m0.y ? s1 : 0.f);
            rl1 += (m1.x ? s2 : 0.f) + (m1.y ? s3 : 0.f);
            S[j][0] = m0.x ? fmaf(s0, 0.25f, 1.024e-3f) : __expf(w0r[j].x) * 1024.f;
            S[j][1] = m0.y ? fmaf(s1, 0.25f, 1.024e-3f) : __expf(w0r[j].y) * 1024.f;
            S[j][2] = m1.x ? fmaf(s2, 0.25f, 1.024e-3f) : __expf(w1r[j].x) * 1024.f;
            S[j][3] = m1.y ? fmaf(s3, 0.25f, 1.024e-3f) : __expf(w1r[j].y) * 1024.f;
        }

        // --- AV: O += P[16x32] @ V[32x128] ---
#pragma unroll
        for (int kc = 0; kc < 2; kc++) {
            unsigned a[4];
            a[0] = h2u(S[2 * kc][0],     S[2 * kc][1]);
            a[1] = h2u(S[2 * kc][2],     S[2 * kc][3]);
            a[2] = h2u(S[2 * kc + 1][0], S[2 * kc + 1][1]);
            a[3] = h2u(S[2 * kc + 1][2], S[2 * kc + 1][3]);
#pragma unroll
            for (int n = 0; n < 16; n++) {
                unsigned b[2];
                b[0] = *(const unsigned*)&Vs[buf][8 * n + tq][kc * 16 + tc * 2];
                b[1] = *(const unsigned*)&Vs[buf][8 * n + tq][kc * 16 + tc * 2 + 8];
                mma16816(O[n], a, b);
            }
        }

        buf = (buf == 2) ? 0 : buf + 1;
        bufn = (bufn == 2) ? 0 : bufn + 1;
    }

    // row-sum reduce across the 4 tc lanes
    rl0 += __shfl_xor_sync(0xFFFFFFFFu, rl0, 1);
    rl0 += __shfl_xor_sync(0xFFFFFFFFu, rl0, 2);
    rl1 += __shfl_xor_sync(0xFFFFFFFFu, rl1, 1);
    rl1 += __shfl_xor_sync(0xFFFFFFFFu, rl1, 2);
    if (tc == 0) { rs[r0l] = rl0; rs[r0l + 8] = rl1; }
    __syncthreads();

    const float den0 = rs[r0l]     * (1.f / 4096.f) + EPS_ + __expf(sp_lse[h * S_ + gr0]);
    const float den1 = rs[r0l + 8] * (1.f / 4096.f) + EPS_ + __expf(sp_lse[h * S_ + gr0 + 8]);
    const float inv0 = 1.f / (1024.f * den0);
    const float inv1 = 1.f / (1024.f * den1);
    float* op0 = out + (size_t)gr0 * D_ + h * DH_;
    float* op1 = op0 + 8 * D_;
#pragma unroll
    for (int n = 0; n < 16; n++) {
        float2 t0 = make_float2(O[n][0] * inv0, O[n][1] * inv0);
        float2 t1 = make_float2(O[n][2] * inv1, O[n][3] * inv1);
        *(float2*)(op0 + 8 * n + tc * 2) = t0;
        *(float2*)(op1 + 8 * n + tc * 2) = t1;
    }
}

// ---------------------------------------------------------------------------
extern "C" void kernel_launch(void* const* d_in, const int* in_sizes, int n_in,
                              void* d_out, int out_size)
{
    (void)in_sizes; (void)n_in; (void)out_size;
    const float* q      = (const float*)d_in[0];
    const float* k      = (const float*)d_in[1];
    const float* v      = (const float*)d_in[2];
    const int*   mask   = (const int*)d_in[3];
    const float* sp_lse = (const float*)d_in[4];
    const float* spw    = (const float*)d_in[5];
    const float* kq1    = (const float*)d_in[6];
    const float* kk1    = (const float*)d_in[7];
    const float* kq2    = (const float*)d_in[8];
    const float* kk2    = (const float*)d_in[9];
    const float* ik     = (const float*)d_in[10];
    const float* sD     = (const float*)d_in[11];
    const float* sD2    = (const float*)d_in[12];
    float* out = (float*)d_out;

    const int smemF = 2 * 128 * 132 * 4;   // 135168
    cudaFuncSetAttribute(featfused_kernel, cudaFuncAttributeMaxDynamicSharedMemorySize, smemF);

    dim3 grid(S_ / 128, H_), blk(256);
    dim3 gridF(S_ / 128, H_, 2);
    featfused_kernel<<<gridF, blk, smemF>>>(q, k, kq1, kk1, kq2, kk2, ik, sD, sD2);
    vtrans_kernel<<<grid, blk>>>(v);
    attn2_kernel<<<grid, blk>>>(mask, sp_lse, spw, out);
}

// round 9
// speedup vs baseline: 3.9423x; 1.2714x over previous
#include <cuda_runtime.h>
#include <cuda_fp16.h>
#include <math.h>

#define S_   2048
#define H_   16
#define D_   2048
#define DH_  128
#define DK_  64
#define EPS_ 1e-6f

// K features pre-scaled by 4096; merged P scaled by 1024; folded into epilogue.

static __device__ __half g_Qf[(size_t)H_ * S_ * DK_];   // [h][s][64]
static __device__ __half g_Kf[(size_t)H_ * S_ * DK_];   // [h][t][64], x4096
static __device__ __half g_VT[(size_t)H_ * DH_ * S_];   // [h][d][t]

__device__ __forceinline__ float gelu_f(float x) {
    return 0.5f * x * (1.0f + erff(x * 0.70710678118654752440f));
}

__device__ __forceinline__ void mma16816(float* c, const unsigned* a, const unsigned* b) {
    asm volatile(
        "mma.sync.aligned.m16n8k16.row.col.f32.f16.f16.f32 "
        "{%0,%1,%2,%3}, {%4,%5,%6,%7}, {%8,%9}, {%0,%1,%2,%3};\n"
        : "+f"(c[0]), "+f"(c[1]), "+f"(c[2]), "+f"(c[3])
        : "r"(a[0]), "r"(a[1]), "r"(a[2]), "r"(a[3]), "r"(b[0]), "r"(b[1]));
}

__device__ __forceinline__ unsigned h2u(float lo, float hi) {
    __half2 h = __floats2half2_rn(lo, hi);
    return *(unsigned*)&h;
}

__device__ __forceinline__ void cpa16(unsigned dst, const void* src) {
    asm volatile("cp.async.cg.shared.global [%0], [%1], 16;" :: "r"(dst), "l"(src));
}
#define CP_COMMIT()  asm volatile("cp.async.commit_group;")
#define CP_WAIT1()   asm volatile("cp.async.wait_group 1;")

// ---------------------------------------------------------------------------
// Fused feature kernel (fp16 MMA): z=0 Q path, z=1 K path.
// 256 thr, 8 warps x 16 rows; grid (16,16,2)
// smem: Xh[128][136] | W1T[128][136] (later k2s[128][72]) | W2T[64][136] | ikT[64][72]
// ---------------------------------------------------------------------------
#define XH_LD   136
#define W1_LD   136
#define W2_LD   136
#define IK_LD   72
#define K2_LD   72
#define SMEM_XH   0
#define SMEM_W1T  (128 * XH_LD)
#define SMEM_W2T  (SMEM_W1T + 128 * W1_LD)
#define SMEM_IKT  (SMEM_W2T + 64 * W2_LD)
#define SMEM_FEAT_HALVES (SMEM_IKT + 64 * IK_LD)

__global__ void __launch_bounds__(256, 2)
featfused_kernel(const float* __restrict__ q, const float* __restrict__ k,
                 const float* __restrict__ wq1, const float* __restrict__ wk1,
                 const float* __restrict__ wq2, const float* __restrict__ wk2,
                 const float* __restrict__ ik, const float* __restrict__ sD,
                 const float* __restrict__ sD2)
{
    extern __shared__ __half smh[];
    __half* Xh  = smh + SMEM_XH;    // [128][136]  X, later Y
    __half* W1T = smh + SMEM_W1T;   // [128][136]  W1^T[e][d]; K path reuses as k2s
    __half* W2T = smh + SMEM_W2T;   // [64][136]   W2^T[e2][d]
    __half* ikT = smh + SMEM_IKT;   // [64][72]    ik^T[f][e]
    __half* k2s = W1T;              // [128][72]

    const int h = blockIdx.y, sb = blockIdx.x, tid = threadIdx.x;
    const int warp = tid >> 5, lane = tid & 31;
    const int tq = lane >> 2, tc = lane & 3;
    const int r0l = warp * 16 + tq;
    const int gr0 = sb * 128 + r0l;
    const int kpath = blockIdx.z;
    const float* x  = kpath ? k : q;
    const float* w1 = kpath ? wk1 : wq1;
    const float* w2 = kpath ? wk2 : wq2;

    // ---- fill smem ----
    const float* xblk = x + (size_t)(sb * 128) * D_ + h * DH_;
    for (int i = tid; i < 128 * 32; i += 256) {           // Xh[r][d]
        int r = i >> 5, c = (i & 31) << 2;
        float4 a = *(const float4*)(xblk + (size_t)r * D_ + c);
        *(unsigned*)&Xh[r * XH_LD + c]     = h2u(a.x, a.y);
        *(unsigned*)&Xh[r * XH_LD + c + 2] = h2u(a.z, a.w);
    }
    const float* w1b = w1 + (size_t)h * DH_ * DH_;
    for (int i = tid; i < 128 * 32; i += 256) {           // W1T[e][d] transpose
        int d = i >> 5, e = (i & 31) << 2;
        float4 a = *(const float4*)(w1b + d * DH_ + e);
        W1T[(e + 0) * W1_LD + d] = __float2half(a.x);
        W1T[(e + 1) * W1_LD + d] = __float2half(a.y);
        W1T[(e + 2) * W1_LD + d] = __float2half(a.z);
        W1T[(e + 3) * W1_LD + d] = __float2half(a.w);
    }
    const float* w2b = w2 + (size_t)h * DH_ * DK_;
    for (int i = tid; i < 128 * 16; i += 256) {           // W2T[e2][d] transpose
        int d = i >> 4, e = (i & 15) << 2;
        float4 a = *(const float4*)(w2b + d * DK_ + e);
        W2T[(e + 0) * W2_LD + d] = __float2half(a.x);
        W2T[(e + 1) * W2_LD + d] = __float2half(a.y);
        W2T[(e + 2) * W2_LD + d] = __float2half(a.z);
        W2T[(e + 3) * W2_LD + d] = __float2half(a.w);
    }
    if (kpath) {
        const float* ikb = ik + (size_t)h * DK_ * DK_;
        for (int i = tid; i < 64 * 16; i += 256) {        // ikT[f][e] transpose
            int e = i >> 4, f = (i & 15) << 2;
            float4 a = *(const float4*)(ikb + e * DK_ + f);
            ikT[(f + 0) * IK_LD + e] = __float2half(a.x);
            ikT[(f + 1) * IK_LD + e] = __float2half(a.y);
            ikT[(f + 2) * IK_LD + e] = __float2half(a.z);
            ikT[(f + 3) * IK_LD + e] = __float2half(a.w);
        }
    }
    __syncthreads();

    // ---- stage 1: Y = gelu(X @ W1), Y[16x128] per warp ----
    float acc1[16][4];
#pragma unroll
    for (int n = 0; n < 16; n++)
#pragma unroll
        for (int j = 0; j < 4; j++) acc1[n][j] = 0.f;
#pragma unroll
    for (int kc = 0; kc < 8; kc++) {
        unsigned a[4];
        a[0] = *(const unsigned*)&Xh[r0l * XH_LD + kc * 16 + tc * 2];
        a[1] = *(const unsigned*)&Xh[(r0l + 8) * XH_LD + kc * 16 + tc * 2];
        a[2] = *(const unsigned*)&Xh[r0l * XH_LD + kc * 16 + tc * 2 + 8];
        a[3] = *(const unsigned*)&Xh[(r0l + 8) * XH_LD + kc * 16 + tc * 2 + 8];
#pragma unroll
        for (int n = 0; n < 16; n++) {
            unsigned b[2];
            b[0] = *(const unsigned*)&W1T[(n * 8 + tq) * W1_LD + kc * 16 + tc * 2];
            b[1] = *(const unsigned*)&W1T[(n * 8 + tq) * W1_LD + kc * 16 + tc * 2 + 8];
            mma16816(acc1[n], a, b);
        }
    }
    // gelu + writeback Y to Xh (warp-local rows)
#pragma unroll
    for (int n = 0; n < 16; n++) {
        int col = n * 8 + tc * 2;
        *(unsigned*)&Xh[r0l * XH_LD + col] =
            h2u(gelu_f(acc1[n][0]), gelu_f(acc1[n][1]));
        *(unsigned*)&Xh[(r0l + 8) * XH_LD + col] =
            h2u(gelu_f(acc1[n][2]), gelu_f(acc1[n][3]));
    }
    __syncwarp();

    // ---- stage 2: G = Y @ W2, [16x64] per warp ----
    float acc2[8][4];
#pragma unroll
    for (int n = 0; n < 8; n++)
#pragma unroll
        for (int j = 0; j < 4; j++) acc2[n][j] = 0.f;
#pragma unroll
    for (int kc = 0; kc < 8; kc++) {
        unsigned a[4];
        a[0] = *(const unsigned*)&Xh[r0l * XH_LD + kc * 16 + tc * 2];
        a[1] = *(const unsigned*)&Xh[(r0l + 8) * XH_LD + kc * 16 + tc * 2];
        a[2] = *(const unsigned*)&Xh[r0l * XH_LD + kc * 16 + tc * 2 + 8];
        a[3] = *(const unsigned*)&Xh[(r0l + 8) * XH_LD + kc * 16 + tc * 2 + 8];
#pragma unroll
        for (int n = 0; n < 8; n++) {
            unsigned b[2];
            b[0] = *(const unsigned*)&W2T[(n * 8 + tq) * W2_LD + kc * 16 + tc * 2];
            b[1] = *(const unsigned*)&W2T[(n * 8 + tq) * W2_LD + kc * 16 + tc * 2 + 8];
            mma16816(acc2[n], a, b);
        }
    }

    if (!kpath) {
        __half* outp = g_Qf + ((size_t)h * S_ + gr0) * DK_;
#pragma unroll
        for (int n = 0; n < 8; n++) {
            int col = n * 8 + tc * 2;
            *(unsigned*)(outp + col) =
                h2u(fabsf(gelu_f(acc2[n][0])), fabsf(gelu_f(acc2[n][1])));
            *(unsigned*)(outp + 8 * DK_ + col) =
                h2u(fabsf(gelu_f(acc2[n][2])), fabsf(gelu_f(acc2[n][3])));
        }
        return;
    }

    // ---- K path: k2 = |sD|*gelu(G)*4096 ; k3 = k2 + (k2@ik)*sD2 ; |k3| out ----
    float k2r[8][4];
#pragma unroll
    for (int n = 0; n < 8; n++) {
        int col = n * 8 + tc * 2;
        float2 sd = *(const float2*)(sD + h * DK_ + col);
        float s0 = fabsf(sd.x) * 4096.f, s1 = fabsf(sd.y) * 4096.f;
        k2r[n][0] = s0 * gelu_f(acc2[n][0]);
        k2r[n][1] = s1 * gelu_f(acc2[n][1]);
        k2r[n][2] = s0 * gelu_f(acc2[n][2]);
        k2r[n][3] = s1 * gelu_f(acc2[n][3]);
    }
    __syncthreads();   // all warps done with W1T before overwrite as k2s
#pragma unroll
    for (int n = 0; n < 8; n++) {
        int col = n * 8 + tc * 2;
        *(unsigned*)&k2s[r0l * K2_LD + col]       = h2u(k2r[n][0], k2r[n][1]);
        *(unsigned*)&k2s[(r0l + 8) * K2_LD + col] = h2u(k2r[n][2], k2r[n][3]);
    }
    __syncwarp();

    float acc3[8][4];
#pragma unroll
    for (int n = 0; n < 8; n++)
#pragma unroll
        for (int j = 0; j < 4; j++) acc3[n][j] = 0.f;
#pragma unroll
    for (int kc = 0; kc < 4; kc++) {
        unsigned a[4];
        a[0] = *(const unsigned*)&k2s[r0l * K2_LD + kc * 16 + tc * 2];
        a[1] = *(const unsigned*)&k2s[(r0l + 8) * K2_LD + kc * 16 + tc * 2];
        a[2] = *(const unsigned*)&k2s[r0l * K2_LD + kc * 16 + tc * 2 + 8];
        a[3] = *(const unsigned*)&k2s[(r0l + 8) * K2_LD + kc * 16 + tc * 2 + 8];
#pragma unroll
        for (int n = 0; n < 8; n++) {
            unsigned b[2];
            b[0] = *(const unsigned*)&ikT[(n * 8 + tq) * IK_LD + kc * 16 + tc * 2];
            b[1] = *(const unsigned*)&ikT[(n * 8 + tq) * IK_LD + kc * 16 + tc * 2 + 8];
            mma16816(acc3[n], a, b);
        }
    }
    __half* outp = g_Kf + ((size_t)h * S_ + gr0) * DK_;
#pragma unroll
    for (int n = 0; n < 8; n++) {
        int col = n * 8 + tc * 2;
        float2 s2 = *(const float2*)(sD2 + h * DK_ + col);
        float o0 = fabsf(fmaf(acc3[n][0], s2.x, k2r[n][0]));
        float o1 = fabsf(fmaf(acc3[n][1], s2.y, k2r[n][1]));
        float o2 = fabsf(fmaf(acc3[n][2], s2.x, k2r[n][2]));
        float o3 = fabsf(fmaf(acc3[n][3], s2.y, k2r[n][3]));
        *(unsigned*)(outp + col)           = h2u(o0, o1);
        *(unsigned*)(outp + 8 * DK_ + col) = h2u(o2, o3);
    }
}

// ---------------------------------------------------------------------------
// V transpose per head: g_VT[h][d][t] = (half) v[t][h*128+d]
// ---------------------------------------------------------------------------
__global__ void __launch_bounds__(256, 1)
vtrans_kernel(const float* __restrict__ v)
{
    __shared__ __half Vs[128][136];
    const int h = blockIdx.y, tb = blockIdx.x, tid = threadIdx.x;
    for (int i = tid; i < 128 * 32; i += 256) {
        int t = i >> 5, ds = (i & 31) << 2;
        float4 f = *(const float4*)(v + (size_t)(tb * 128 + t) * D_ + h * DH_ + ds);
        Vs[ds + 0][t] = __float2half(f.x);
        Vs[ds + 1][t] = __float2half(f.y);
        Vs[ds + 2][t] = __float2half(f.z);
        Vs[ds + 3][t] = __float2half(f.w);
    }
    __syncthreads();
    for (int i = tid; i < 128 * 16; i += 256) {
        int d = i >> 4, seg = (i & 15) << 3;
        *(uint4*)(g_VT + ((size_t)h * DH_ + d) * S_ + tb * 128 + seg) =
            *(const uint4*)&Vs[d][seg];
    }
}

// ---------------------------------------------------------------------------
// Stage 3: fp16 mma pipeline, 3-stage cp.async, spw prefetched into regs
// ---------------------------------------------------------------------------
__global__ void __launch_bounds__(256, 2)
attn2_kernel(const int* __restrict__ mask, const float* __restrict__ sp_lse,
             const float* __restrict__ spw, float* __restrict__ out)
{
    __shared__ __half Ks[3][32][72];
    __shared__ __half Vs[3][128][40];
    __shared__ float  rs[128];

    const int h = blockIdx.y, sb = blockIdx.x, tid = threadIdx.x;
    const int warp = tid >> 5, lane = tid & 31;
    const int tq = lane >> 2, tc = lane & 3;
    const int r0l = warp * 16 + tq;
    const int gr0 = sb * 128 + r0l;

    const __half* qp0 = g_Qf + ((size_t)h * S_ + gr0) * DK_;
    const __half* qp1 = qp0 + 8 * DK_;
    const __half* kbase = g_Kf + (size_t)h * S_ * DK_;
    const __half* vbase = g_VT + (size_t)h * DH_ * S_;

    const int krow = tid >> 3, kseg = (tid & 7) << 3;
    const int vrowA = tid >> 2, vsegA = (tid & 3) << 3;
    const unsigned ks_sm = (unsigned)__cvta_generic_to_shared(&Ks[0][0][0]);
    const unsigned vs_sm = (unsigned)__cvta_generic_to_shared(&Vs[0][0][0]);

    float O[16][4];
#pragma unroll
    for (int n = 0; n < 16; n++)
#pragma unroll
        for (int j = 0; j < 4; j++) O[n][j] = 0.f;
    float rl0 = 0.f, rl1 = 0.f;

#pragma unroll
    for (int t = 0; t < 2; t++) {
        cpa16(ks_sm + (t * 32 * 72 + krow * 72 + kseg) * 2,
              kbase + (size_t)(t * 32 + krow) * DK_ + kseg);
        cpa16(vs_sm + (t * 128 * 40 + vrowA * 40 + vsegA) * 2,
              vbase + (size_t)vrowA * S_ + t * 32 + vsegA);
        cpa16(vs_sm + (t * 128 * 40 + (vrowA + 64) * 40 + vsegA) * 2,
              vbase + (size_t)(vrowA + 64) * S_ + t * 32 + vsegA);
        CP_COMMIT();
    }

    const size_t mrow0 = (size_t)gr0 * S_;
    const size_t mrow1 = (size_t)(gr0 + 8) * S_;
    const size_t wrow0 = ((size_t)h * S_ + gr0) * S_;
    const size_t wrow1 = wrow0 + 8 * S_;

    int buf = 0, bufn = 2;
    for (int tb = 0; tb < 64; tb++) {
        CP_WAIT1();
        __syncthreads();

        const int cbase = tb * 32 + tc * 2;
        float2 w0r[4], w1r[4];
#pragma unroll
        for (int j = 0; j < 4; j++) {
            w0r[j] = *(const float2*)(spw + wrow0 + cbase + 8 * j);
            w1r[j] = *(const float2*)(spw + wrow1 + cbase + 8 * j);
        }

        if (tb + 2 < 64) {
            cpa16(ks_sm + (bufn * 32 * 72 + krow * 72 + kseg) * 2,
                  kbase + (size_t)((tb + 2) * 32 + krow) * DK_ + kseg);
            cpa16(vs_sm + (bufn * 128 * 40 + vrowA * 40 + vsegA) * 2,
                  vbase + (size_t)vrowA * S_ + (tb + 2) * 32 + vsegA);
            cpa16(vs_sm + (bufn * 128 * 40 + (vrowA + 64) * 40 + vsegA) * 2,
                  vbase + (size_t)(vrowA + 64) * S_ + (tb + 2) * 32 + vsegA);
        }
        CP_COMMIT();

        float S[4][4];
#pragma unroll
        for (int j = 0; j < 4; j++)
#pragma unroll
            for (int e = 0; e < 4; e++) S[j][e] = 0.f;
#pragma unroll
        for (int kc = 0; kc < 4; kc++) {
            unsigned a[4];
            a[0] = *(const unsigned*)(qp0 + kc * 16 + tc * 2);
            a[1] = *(const unsigned*)(qp1 + kc * 16 + tc * 2);
            a[2] = *(const unsigned*)(qp0 + kc * 16 + tc * 2 + 8);
            a[3] = *(const unsigned*)(qp1 + kc * 16 + tc * 2 + 8);
#pragma unroll
            for (int j = 0; j < 4; j++) {
                unsigned b[2];
                b[0] = *(const unsigned*)&Ks[buf][8 * j + tq][kc * 16 + tc * 2];
                b[1] = *(const unsigned*)&Ks[buf][8 * j + tq][kc * 16 + tc * 2 + 8];
                mma16816(S[j], a, b);
            }
        }

#pragma unroll
        for (int j = 0; j < 4; j++) {
            const int col = cbase + 8 * j;
            int2 m0 = *(const int2*)(mask + mrow0 + col);
            int2 m1 = *(const int2*)(mask + mrow1 + col);
            float s0 = S[j][0], s1 = S[j][1], s2 = S[j][2], s3 = S[j][3];
            rl0 += (m0.x ? s0 : 0.f) + (m0.y ? s1 : 0.f);
            rl1 += (m1.x ? s2 : 0.f) + (m1.y ? s3 : 0.f);
            S[j][0] = m0.x ? fmaf(s0, 0.25f, 1.024e-3f) : __expf(w0r[j].x) * 1024.f;
            S[j][1] = m0.y ? fmaf(s1, 0.25f, 1.024e-3f) : __expf(w0r[j].y) * 1024.f;
            S[j][2] = m1.x ? fmaf(s2, 0.25f, 1.024e-3f) : __expf(w1r[j].x) * 1024.f;
            S[j][3] = m1.y ? fmaf(s3, 0.25f, 1.024e-3f) : __expf(w1r[j].y) * 1024.f;
        }

#pragma unroll
        for (int kc = 0; kc < 2; kc++) {
            unsigned a[4];
            a[0] = h2u(S[2 * kc][0],     S[2 * kc][1]);
            a[1] = h2u(S[2 * kc][2],     S[2 * kc][3]);
            a[2] = h2u(S[2 * kc + 1][0], S[2 * kc + 1][1]);
            a[3] = h2u(S[2 * kc + 1][2], S[2 * kc + 1][3]);
#pragma unroll
            for (int n = 0; n < 16; n++) {
                unsigned b[2];
                b[0] = *(const unsigned*)&Vs[buf][8 * n + tq][kc * 16 + tc * 2];
                b[1] = *(const unsigned*)&Vs[buf][8 * n + tq][kc * 16 + tc * 2 + 8];
                mma16816(O[n], a, b);
            }
        }

        buf = (buf == 2) ? 0 : buf + 1;
        bufn = (bufn == 2) ? 0 : bufn + 1;
    }

    rl0 += __shfl_xor_sync(0xFFFFFFFFu, rl0, 1);
    rl0 += __shfl_xor_sync(0xFFFFFFFFu, rl0, 2);
    rl1 += __shfl_xor_sync(0xFFFFFFFFu, rl1, 1);
    rl1 += __shfl_xor_sync(0xFFFFFFFFu, rl1, 2);
    if (tc == 0) { rs[r0l] = rl0; rs[r0l + 8] = rl1; }
    __syncthreads();

    const float den0 = rs[r0l]     * (1.f / 4096.f) + EPS_ + __expf(sp_lse[h * S_ + gr0]);
    const float den1 = rs[r0l + 8] * (1.f / 4096.f) + EPS_ + __expf(sp_lse[h * S_ + gr0 + 8]);
    const float inv0 = 1.f / (1024.f * den0);
    const float inv1 = 1.f / (1024.f * den1);
    float* op0 = out + (size_t)gr0 * D_ + h * DH_;
    float* op1 = op0 + 8 * D_;
#pragma unroll
    for (int n = 0; n < 16; n++) {
        float2 t0 = make_float2(O[n][0] * inv0, O[n][1] * inv0);
        float2 t1 = make_float2(O[n][2] * inv1, O[n][3] * inv1);
        *(float2*)(op0 + 8 * n + tc * 2) = t0;
        *(float2*)(op1 + 8 * n + tc * 2) = t1;
    }
}

// ---------------------------------------------------------------------------
extern "C" void kernel_launch(void* const* d_in, const int* in_sizes, int n_in,
                              void* d_out, int out_size)
{
    (void)in_sizes; (void)n_in; (void)out_size;
    const float* q      = (const float*)d_in[0];
    const float* k      = (const float*)d_in[1];
    const float* v      = (const float*)d_in[2];
    const int*   mask   = (const int*)d_in[3];
    const float* sp_lse = (const float*)d_in[4];
    const float* spw    = (const float*)d_in[5];
    const float* kq1    = (const float*)d_in[6];
    const float* kk1    = (const float*)d_in[7];
    const float* kq2    = (const float*)d_in[8];
    const float* kk2    = (const float*)d_in[9];
    const float* ik     = (const float*)d_in[10];
    const float* sD     = (const float*)d_in[11];
    const float* sD2    = (const float*)d_in[12];
    float* out = (float*)d_out;

    const int smemF = SMEM_FEAT_HALVES * 2;   // 96256 B
    cudaFuncSetAttribute(featfused_kernel, cudaFuncAttributeMaxDynamicSharedMemorySize, smemF);

    dim3 grid(S_ / 128, H_), blk(256);
    dim3 gridF(S_ / 128, H_, 2);
    featfused_kernel<<<gridF, blk, smemF>>>(q, k, kq1, kk1, kq2, kk2, ik, sD, sD2);
    vtrans_kernel<<<grid, blk>>>(v);
    attn2_kernel<<<grid, blk>>>(mask, sp_lse, spw, out);
}

// round 10
// speedup vs baseline: 4.5248x; 1.1478x over previous
#include <cuda_runtime.h>
#include <cuda_fp16.h>
#include <math.h>

#define S_   2048
#define H_   16
#define D_   2048
#define DH_  128
#define DK_  64
#define EPS_ 1e-6f

// K features pre-scaled by 4096; merged P scaled by 1024; folded into epilogue.

static __device__ __half g_Qf[(size_t)H_ * S_ * DK_];   // [h][s][64]
static __device__ __half g_Kf[(size_t)H_ * S_ * DK_];   // [h][t][64], x4096
static __device__ __half g_VT[(size_t)H_ * DH_ * S_];   // [h][d][t]

__device__ __forceinline__ float gelu_f(float x) {
    return 0.5f * x * (1.0f + erff(x * 0.70710678118654752440f));
}

__device__ __forceinline__ void mma16816(float* c, const unsigned* a, const unsigned* b) {
    asm volatile(
        "mma.sync.aligned.m16n8k16.row.col.f32.f16.f16.f32 "
        "{%0,%1,%2,%3}, {%4,%5,%6,%7}, {%8,%9}, {%0,%1,%2,%3};\n"
        : "+f"(c[0]), "+f"(c[1]), "+f"(c[2]), "+f"(c[3])
        : "r"(a[0]), "r"(a[1]), "r"(a[2]), "r"(a[3]), "r"(b[0]), "r"(b[1]));
}

__device__ __forceinline__ void ldsm4(unsigned& r0, unsigned& r1, unsigned& r2,
                                      unsigned& r3, unsigned addr) {
    asm volatile("ldmatrix.sync.aligned.m8n8.x4.shared.b16 {%0,%1,%2,%3}, [%4];"
        : "=r"(r0), "=r"(r1), "=r"(r2), "=r"(r3) : "r"(addr));
}

__device__ __forceinline__ unsigned h2u(float lo, float hi) {
    __half2 h = __floats2half2_rn(lo, hi);
    return *(unsigned*)&h;
}

__device__ __forceinline__ float ex2f(float x) {
    float r; asm("ex2.approx.f32 %0, %1;" : "=f"(r) : "f"(x)); return r;
}

__device__ __forceinline__ void cpa16(unsigned dst, const void* src) {
    asm volatile("cp.async.cg.shared.global [%0], [%1], 16;" :: "r"(dst), "l"(src));
}
#define CP_COMMIT()  asm volatile("cp.async.commit_group;")
#define CP_WAIT1()   asm volatile("cp.async.wait_group 1;")

// ---------------------------------------------------------------------------
// Fused feature kernel (fp16 MMA): z=0 Q path, z=1 K path. (unchanged)
// ---------------------------------------------------------------------------
#define XH_LD   136
#define W1_LD   136
#define W2_LD   136
#define IK_LD   72
#define K2_LD   72
#define SMEM_XH   0
#define SMEM_W1T  (128 * XH_LD)
#define SMEM_W2T  (SMEM_W1T + 128 * W1_LD)
#define SMEM_IKT  (SMEM_W2T + 64 * W2_LD)
#define SMEM_FEAT_HALVES (SMEM_IKT + 64 * IK_LD)

__global__ void __launch_bounds__(256, 2)
featfused_kernel(const float* __restrict__ q, const float* __restrict__ k,
                 const float* __restrict__ wq1, const float* __restrict__ wk1,
                 const float* __restrict__ wq2, const float* __restrict__ wk2,
                 const float* __restrict__ ik, const float* __restrict__ sD,
                 const float* __restrict__ sD2)
{
    extern __shared__ __half smh[];
    __half* Xh  = smh + SMEM_XH;
    __half* W1T = smh + SMEM_W1T;
    __half* W2T = smh + SMEM_W2T;
    __half* ikT = smh + SMEM_IKT;
    __half* k2s = W1T;

    const int h = blockIdx.y, sb = blockIdx.x, tid = threadIdx.x;
    const int warp = tid >> 5, lane = tid & 31;
    const int tq = lane >> 2, tc = lane & 3;
    const int r0l = warp * 16 + tq;
    const int gr0 = sb * 128 + r0l;
    const int kpath = blockIdx.z;
    const float* x  = kpath ? k : q;
    const float* w1 = kpath ? wk1 : wq1;
    const float* w2 = kpath ? wk2 : wq2;

    const float* xblk = x + (size_t)(sb * 128) * D_ + h * DH_;
    for (int i = tid; i < 128 * 32; i += 256) {
        int r = i >> 5, c = (i & 31) << 2;
        float4 a = *(const float4*)(xblk + (size_t)r * D_ + c);
        *(unsigned*)&Xh[r * XH_LD + c]     = h2u(a.x, a.y);
        *(unsigned*)&Xh[r * XH_LD + c + 2] = h2u(a.z, a.w);
    }
    const float* w1b = w1 + (size_t)h * DH_ * DH_;
    for (int i = tid; i < 128 * 32; i += 256) {
        int d = i >> 5, e = (i & 31) << 2;
        float4 a = *(const float4*)(w1b + d * DH_ + e);
        W1T[(e + 0) * W1_LD + d] = __float2half(a.x);
        W1T[(e + 1) * W1_LD + d] = __float2half(a.y);
        W1T[(e + 2) * W1_LD + d] = __float2half(a.z);
        W1T[(e + 3) * W1_LD + d] = __float2half(a.w);
    }
    const float* w2b = w2 + (size_t)h * DH_ * DK_;
    for (int i = tid; i < 128 * 16; i += 256) {
        int d = i >> 4, e = (i & 15) << 2;
        float4 a = *(const float4*)(w2b + d * DK_ + e);
        W2T[(e + 0) * W2_LD + d] = __float2half(a.x);
        W2T[(e + 1) * W2_LD + d] = __float2half(a.y);
        W2T[(e + 2) * W2_LD + d] = __float2half(a.z);
        W2T[(e + 3) * W2_LD + d] = __float2half(a.w);
    }
    if (kpath) {
        const float* ikb = ik + (size_t)h * DK_ * DK_;
        for (int i = tid; i < 64 * 16; i += 256) {
            int e = i >> 4, f = (i & 15) << 2;
            float4 a = *(const float4*)(ikb + e * DK_ + f);
            ikT[(f + 0) * IK_LD + e] = __float2half(a.x);
            ikT[(f + 1) * IK_LD + e] = __float2half(a.y);
            ikT[(f + 2) * IK_LD + e] = __float2half(a.z);
            ikT[(f + 3) * IK_LD + e] = __float2half(a.w);
        }
    }
    __syncthreads();

    float acc1[16][4];
#pragma unroll
    for (int n = 0; n < 16; n++)
#pragma unroll
        for (int j = 0; j < 4; j++) acc1[n][j] = 0.f;
#pragma unroll
    for (int kc = 0; kc < 8; kc++) {
        unsigned a[4];
        a[0] = *(const unsigned*)&Xh[r0l * XH_LD + kc * 16 + tc * 2];
        a[1] = *(const unsigned*)&Xh[(r0l + 8) * XH_LD + kc * 16 + tc * 2];
        a[2] = *(const unsigned*)&Xh[r0l * XH_LD + kc * 16 + tc * 2 + 8];
        a[3] = *(const unsigned*)&Xh[(r0l + 8) * XH_LD + kc * 16 + tc * 2 + 8];
#pragma unroll
        for (int n = 0; n < 16; n++) {
            unsigned b[2];
            b[0] = *(const unsigned*)&W1T[(n * 8 + tq) * W1_LD + kc * 16 + tc * 2];
            b[1] = *(const unsigned*)&W1T[(n * 8 + tq) * W1_LD + kc * 16 + tc * 2 + 8];
            mma16816(acc1[n], a, b);
        }
    }
#pragma unroll
    for (int n = 0; n < 16; n++) {
        int col = n * 8 + tc * 2;
        *(unsigned*)&Xh[r0l * XH_LD + col] =
            h2u(gelu_f(acc1[n][0]), gelu_f(acc1[n][1]));
        *(unsigned*)&Xh[(r0l + 8) * XH_LD + col] =
            h2u(gelu_f(acc1[n][2]), gelu_f(acc1[n][3]));
    }
    __syncwarp();

    float acc2[8][4];
#pragma unroll
    for (int n = 0; n < 8; n++)
#pragma unroll
        for (int j = 0; j < 4; j++) acc2[n][j] = 0.f;
#pragma unroll
    for (int kc = 0; kc < 8; kc++) {
        unsigned a[4];
        a[0] = *(const unsigned*)&Xh[r0l * XH_LD + kc * 16 + tc * 2];
        a[1] = *(const unsigned*)&Xh[(r0l + 8) * XH_LD + kc * 16 + tc * 2];
        a[2] = *(const unsigned*)&Xh[r0l * XH_LD + kc * 16 + tc * 2 + 8];
        a[3] = *(const unsigned*)&Xh[(r0l + 8) * XH_LD + kc * 16 + tc * 2 + 8];
#pragma unroll
        for (int n = 0; n < 8; n++) {
            unsigned b[2];
            b[0] = *(const unsigned*)&W2T[(n * 8 + tq) * W2_LD + kc * 16 + tc * 2];
            b[1] = *(const unsigned*)&W2T[(n * 8 + tq) * W2_LD + kc * 16 + tc * 2 + 8];
            mma16816(acc2[n], a, b);
        }
    }

    if (!kpath) {
        __half* outp = g_Qf + ((size_t)h * S_ + gr0) * DK_;
#pragma unroll
        for (int n = 0; n < 8; n++) {
            int col = n * 8 + tc * 2;
            *(unsigned*)(outp + col) =
                h2u(fabsf(gelu_f(acc2[n][0])), fabsf(gelu_f(acc2[n][1])));
            *(unsigned*)(outp + 8 * DK_ + col) =
                h2u(fabsf(gelu_f(acc2[n][2])), fabsf(gelu_f(acc2[n][3])));
        }
        return;
    }

    float k2r[8][4];
#pragma unroll
    for (int n = 0; n < 8; n++) {
        int col = n * 8 + tc * 2;
        float2 sd = *(const float2*)(sD + h * DK_ + col);
        float s0 = fabsf(sd.x) * 4096.f, s1 = fabsf(sd.y) * 4096.f;
        k2r[n][0] = s0 * gelu_f(acc2[n][0]);
        k2r[n][1] = s1 * gelu_f(acc2[n][1]);
        k2r[n][2] = s0 * gelu_f(acc2[n][2]);
        k2r[n][3] = s1 * gelu_f(acc2[n][3]);
    }
    __syncthreads();
#pragma unroll
    for (int n = 0; n < 8; n++) {
        int col = n * 8 + tc * 2;
        *(unsigned*)&k2s[r0l * K2_LD + col]       = h2u(k2r[n][0], k2r[n][1]);
        *(unsigned*)&k2s[(r0l + 8) * K2_LD + col] = h2u(k2r[n][2], k2r[n][3]);
    }
    __syncwarp();

    float acc3[8][4];
#pragma unroll
    for (int n = 0; n < 8; n++)
#pragma unroll
        for (int j = 0; j < 4; j++) acc3[n][j] = 0.f;
#pragma unroll
    for (int kc = 0; kc < 4; kc++) {
        unsigned a[4];
        a[0] = *(const unsigned*)&k2s[r0l * K2_LD + kc * 16 + tc * 2];
        a[1] = *(const unsigned*)&k2s[(r0l + 8) * K2_LD + kc * 16 + tc * 2];
        a[2] = *(const unsigned*)&k2s[r0l * K2_LD + kc * 16 + tc * 2 + 8];
        a[3] = *(const unsigned*)&k2s[(r0l + 8) * K2_LD + kc * 16 + tc * 2 + 8];
#pragma unroll
        for (int n = 0; n < 8; n++) {
            unsigned b[2];
            b[0] = *(const unsigned*)&ikT[(n * 8 + tq) * IK_LD + kc * 16 + tc * 2];
            b[1] = *(const unsigned*)&ikT[(n * 8 + tq) * IK_LD + kc * 16 + tc * 2 + 8];
            mma16816(acc3[n], a, b);
        }
    }
    __half* outp = g_Kf + ((size_t)h * S_ + gr0) * DK_;
#pragma unroll
    for (int n = 0; n < 8; n++) {
        int col = n * 8 + tc * 2;
        float2 s2 = *(const float2*)(sD2 + h * DK_ + col);
        float o0 = fabsf(fmaf(acc3[n][0], s2.x, k2r[n][0]));
        float o1 = fabsf(fmaf(acc3[n][1], s2.y, k2r[n][1]));
        float o2 = fabsf(fmaf(acc3[n][2], s2.x, k2r[n][2]));
        float o3 = fabsf(fmaf(acc3[n][3], s2.y, k2r[n][3]));
        *(unsigned*)(outp + col)           = h2u(o0, o1);
        *(unsigned*)(outp + 8 * DK_ + col) = h2u(o2, o3);
    }
}

// ---------------------------------------------------------------------------
// V transpose per head: g_VT[h][d][t] = (half) v[t][h*128+d]
// ---------------------------------------------------------------------------
__global__ void __launch_bounds__(256, 1)
vtrans_kernel(const float* __restrict__ v)
{
    __shared__ __half Vsm[128][136];
    const int h = blockIdx.y, tb = blockIdx.x, tid = threadIdx.x;
    for (int i = tid; i < 128 * 32; i += 256) {
        int t = i >> 5, ds = (i & 31) << 2;
        float4 f = *(const float4*)(v + (size_t)(tb * 128 + t) * D_ + h * DH_ + ds);
        Vsm[ds + 0][t] = __float2half(f.x);
        Vsm[ds + 1][t] = __float2half(f.y);
        Vsm[ds + 2][t] = __float2half(f.z);
        Vsm[ds + 3][t] = __float2half(f.w);
    }
    __syncthreads();
    for (int i = tid; i < 128 * 16; i += 256) {
        int d = i >> 4, seg = (i & 15) << 3;
        *(uint4*)(g_VT + ((size_t)h * DH_ + d) * S_ + tb * 128 + seg) =
            *(const uint4*)&Vsm[d][seg];
    }
}

// ---------------------------------------------------------------------------
// Stage 3: fp16 mma, ldmatrix operand loads, Q in smem, 3-stage cp.async
// smem (halves): Qs[128*72] | Ks[3*32*72] | Vs[3*128*40] | rs(float)[128]
// ---------------------------------------------------------------------------
#define ATTN_SMEM_BYTES ((128*72 + 3*32*72 + 3*128*40) * 2 + 128 * 4)

__global__ void __launch_bounds__(256, 2)
attn2_kernel(const int* __restrict__ mask, const float* __restrict__ sp_lse,
             const float* __restrict__ spw, float* __restrict__ out)
{
    extern __shared__ __half sma[];
    __half* Qs = sma;                       // [128][72]
    __half* Ks = Qs + 128 * 72;             // [3][32][72]
    __half* Vs = Ks + 3 * 32 * 72;          // [3][128][40]
    float*  rs = (float*)(Vs + 3 * 128 * 40);

    const int h = blockIdx.y, sb = blockIdx.x, tid = threadIdx.x;
    const int warp = tid >> 5, lane = tid & 31;
    const int tq = lane >> 2, tc = lane & 3;
    const int r0l = warp * 16 + tq;
    const int gr0 = sb * 128 + r0l;

    const __half* kbase = g_Kf + (size_t)h * S_ * DK_;
    const __half* vbase = g_VT + (size_t)h * DH_ * S_;
    const __half* qsrc  = g_Qf + ((size_t)h * S_ + sb * 128) * DK_;

    // cp.async staging indices
    const int krow = tid >> 3, kseg = (tid & 7) << 3;
    const int vrowA = tid >> 2, vsegA = (tid & 3) << 3;
    const unsigned qs_sm = (unsigned)__cvta_generic_to_shared(Qs);
    const unsigned ks_sm = (unsigned)__cvta_generic_to_shared(Ks);
    const unsigned vs_sm = (unsigned)__cvta_generic_to_shared(Vs);

    // ldmatrix per-lane addresses
    const int g = lane >> 3, ri = lane & 7;
    const unsigned qa = (unsigned)__cvta_generic_to_shared(
        &Qs[(warp * 16 + (g & 1) * 8 + ri) * 72 + (g >> 1) * 8]);
    const unsigned ka = (unsigned)__cvta_generic_to_shared(
        &Ks[((g >> 1) * 8 + ri) * 72 + (g & 1) * 8]);
    const unsigned va = (unsigned)__cvta_generic_to_shared(
        &Vs[((g >> 1) * 8 + ri) * 40 + (g & 1) * 8]);

    float O[16][4];
#pragma unroll
    for (int n = 0; n < 16; n++)
#pragma unroll
        for (int j = 0; j < 4; j++) O[n][j] = 0.f;
    float rl0 = 0.f, rl1 = 0.f;

    // prologue: Q tile + tile 0 (group 0), tile 1 (group 1)
#pragma unroll
    for (int j = 0; j < 4; j++) {
        int i = tid + j * 256;
        int r = i >> 3, cs = (i & 7) << 3;
        cpa16(qs_sm + (r * 72 + cs) * 2, qsrc + r * 64 + cs);
    }
    cpa16(ks_sm + (krow * 72 + kseg) * 2, kbase + (size_t)krow * DK_ + kseg);
    cpa16(vs_sm + (vrowA * 40 + vsegA) * 2, vbase + (size_t)vrowA * S_ + vsegA);
    cpa16(vs_sm + ((vrowA + 64) * 40 + vsegA) * 2, vbase + (size_t)(vrowA + 64) * S_ + vsegA);
    CP_COMMIT();
    cpa16(ks_sm + (32 * 72 + krow * 72 + kseg) * 2, kbase + (size_t)(32 + krow) * DK_ + kseg);
    cpa16(vs_sm + (128 * 40 + vrowA * 40 + vsegA) * 2, vbase + (size_t)vrowA * S_ + 32 + vsegA);
    cpa16(vs_sm + (128 * 40 + (vrowA + 64) * 40 + vsegA) * 2, vbase + (size_t)(vrowA + 64) * S_ + 32 + vsegA);
    CP_COMMIT();

    const size_t mrow0 = (size_t)gr0 * S_;
    const size_t mrow1 = mrow0 + 8 * S_;
    const size_t wrow0 = ((size_t)h * S_ + gr0) * S_;
    const size_t wrow1 = wrow0 + 8 * S_;

    int buf = 0, bufn = 2;
    for (int tb = 0; tb < 64; tb++) {
        CP_WAIT1();
        __syncthreads();

        // spw prefetch for this tile (DRAM latency hidden behind scores)
        const int cbase = tb * 32 + tc * 2;
        float2 w0r[4], w1r[4];
#pragma unroll
        for (int j = 0; j < 4; j++) {
            w0r[j] = *(const float2*)(spw + wrow0 + cbase + 8 * j);
            w1r[j] = *(const float2*)(spw + wrow1 + cbase + 8 * j);
        }

        // prefetch tile tb+2 into bufn
        if (tb + 2 < 64) {
            cpa16(ks_sm + (bufn * 32 * 72 + krow * 72 + kseg) * 2,
                  kbase + (size_t)((tb + 2) * 32 + krow) * DK_ + kseg);
            cpa16(vs_sm + (bufn * 128 * 40 + vrowA * 40 + vsegA) * 2,
                  vbase + (size_t)vrowA * S_ + (tb + 2) * 32 + vsegA);
            cpa16(vs_sm + (bufn * 128 * 40 + (vrowA + 64) * 40 + vsegA) * 2,
                  vbase + (size_t)(vrowA + 64) * S_ + (tb + 2) * 32 + vsegA);
        }
        CP_COMMIT();

        // --- scores via ldmatrix: S[4 n-tiles][4], K=64 ---
        const unsigned kb = ka + buf * (32 * 72 * 2);
        float S[4][4];
#pragma unroll
        for (int j = 0; j < 4; j++)
#pragma unroll
            for (int e = 0; e < 4; e++) S[j][e] = 0.f;
#pragma unroll
        for (int kc = 0; kc < 4; kc++) {
            unsigned A[4], B[4], C[4];
            ldsm4(A[0], A[1], A[2], A[3], qa + kc * 32);
            ldsm4(B[0], B[1], B[2], B[3], kb + kc * 32);
            mma16816(S[0], A, B + 0);
            mma16816(S[1], A, B + 2);
            ldsm4(C[0], C[1], C[2], C[3], kb + kc * 32 + 16 * 72 * 2);
            mma16816(S[2], A, C + 0);
            mma16816(S[3], A, C + 2);
        }

        // --- merge in registers (lr_true = S/4096; P stored x1024) ---
#pragma unroll
        for (int j = 0; j < 4; j++) {
            const int col = cbase + 8 * j;
            int2 m0 = *(const int2*)(mask + mrow0 + col);
            int2 m1 = *(const int2*)(mask + mrow1 + col);
            float s0 = S[j][0], s1 = S[j][1], s2 = S[j][2], s3 = S[j][3];
            rl0 += (m0.x ? s0 : 0.f) + (m0.y ? s1 : 0.f);
            rl1 += (m1.x ? s2 : 0.f) + (m1.y ? s3 : 0.f);
            S[j][0] = m0.x ? fmaf(s0, 0.25f, 1.024e-3f)
                           : ex2f(fmaf(w0r[j].x, 1.4426950408889634f, 10.f));
            S[j][1] = m0.y ? fmaf(s1, 0.25f, 1.024e-3f)
                           : ex2f(fmaf(w0r[j].y, 1.4426950408889634f, 10.f));
            S[j][2] = m1.x ? fmaf(s2, 0.25f, 1.024e-3f)
                           : ex2f(fmaf(w1r[j].x, 1.4426950408889634f, 10.f));
            S[j][3] = m1.y ? fmaf(s3, 0.25f, 1.024e-3f)
                           : ex2f(fmaf(w1r[j].y, 1.4426950408889634f, 10.f));
        }

        // --- AV via ldmatrix: O += P[16x32] @ V[32x128] ---
        const unsigned vb = va + buf * (128 * 40 * 2);
#pragma unroll
        for (int kc = 0; kc < 2; kc++) {
            unsigned a[4];
            a[0] = h2u(S[2 * kc][0],     S[2 * kc][1]);
            a[1] = h2u(S[2 * kc][2],     S[2 * kc][3]);
            a[2] = h2u(S[2 * kc + 1][0], S[2 * kc + 1][1]);
            a[3] = h2u(S[2 * kc + 1][2], S[2 * kc + 1][3]);
#pragma unroll
            for (int v = 0; v < 8; v++) {
                unsigned B[4];
                ldsm4(B[0], B[1], B[2], B[3], vb + kc * 32 + v * (16 * 40 * 2));
                mma16816(O[2 * v],     a, B + 0);
                mma16816(O[2 * v + 1], a, B + 2);
            }
        }

        buf = (buf == 2) ? 0 : buf + 1;
        bufn = (bufn == 2) ? 0 : bufn + 1;
    }

    rl0 += __shfl_xor_sync(0xFFFFFFFFu, rl0, 1);
    rl0 += __shfl_xor_sync(0xFFFFFFFFu, rl0, 2);
    rl1 += __shfl_xor_sync(0xFFFFFFFFu, rl1, 1);
    rl1 += __shfl_xor_sync(0xFFFFFFFFu, rl1, 2);
    if (tc == 0) { rs[r0l] = rl0; rs[r0l + 8] = rl1; }
    __syncthreads();

    const float den0 = rs[r0l]     * (1.f / 4096.f) + EPS_ + __expf(sp_lse[h * S_ + gr0]);
    const float den1 = rs[r0l + 8] * (1.f / 4096.f) + EPS_ + __expf(sp_lse[h * S_ + gr0 + 8]);
    const float inv0 = 1.f / (1024.f * den0);
    const float inv1 = 1.f / (1024.f * den1);
    float* op0 = out + (size_t)gr0 * D_ + h * DH_;
    float* op1 = op0 + 8 * D_;
#pragma unroll
    for (int n = 0; n < 16; n++) {
        float2 t0 = make_float2(O[n][0] * inv0, O[n][1] * inv0);
        float2 t1 = make_float2(O[n][2] * inv1, O[n][3] * inv1);
        *(float2*)(op0 + 8 * n + tc * 2) = t0;
        *(float2*)(op1 + 8 * n + tc * 2) = t1;
    }
}

// ---------------------------------------------------------------------------
extern "C" void kernel_launch(void* const* d_in, const int* in_sizes, int n_in,
                              void* d_out, int out_size)
{
    (void)in_sizes; (void)n_in; (void)out_size;
    const float* q      = (const float*)d_in[0];
    const float* k      = (const float*)d_in[1];
    const float* v      = (const float*)d_in[2];
    const int*   mask   = (const int*)d_in[3];
    const float* sp_lse = (const float*)d_in[4];
    const float* spw    = (const float*)d_in[5];
    const float* kq1    = (const float*)d_in[6];
    const float* kk1    = (const float*)d_in[7];
    const float* kq2    = (const float*)d_in[8];
    const float* kk2    = (const float*)d_in[9];
    const float* ik     = (const float*)d_in[10];
    const float* sD     = (const float*)d_in[11];
    const float* sD2    = (const float*)d_in[12];
    float* out = (float*)d_out;

    const int smemF = SMEM_FEAT_HALVES * 2;   // 96256 B
    const int smemA = ATTN_SMEM_BYTES;        // 63488 B
    cudaFuncSetAttribute(featfused_kernel, cudaFuncAttributeMaxDynamicSharedMemorySize, smemF);
    cudaFuncSetAttribute(attn2_kernel,     cudaFuncAttributeMaxDynamicSharedMemorySize, smemA);

    dim3 grid(S_ / 128, H_), blk(256);
    dim3 gridF(S_ / 128, H_, 2);
    featfused_kernel<<<gridF, blk, smemF>>>(q, k, kq1, kk1, kq2, kk2, ik, sD, sD2);
    vtrans_kernel<<<grid, blk>>>(v);
    attn2_kernel<<<grid, blk, smemA>>>(mask, sp_lse, spw, out);
}

// round 12
// speedup vs baseline: 4.6694x; 1.0320x over previous
#include <cuda_runtime.h>
#include <cuda_fp16.h>
#include <math.h>

#define S_   2048
#define H_   16
#define D_   2048
#define DH_  128
#define DK_  64
#define EPS_ 1e-6f

// K features pre-scaled by 4096; merged P scaled by 1024; folded into epilogue.

static __device__ __half g_Qf[(size_t)H_ * S_ * DK_];   // [h][s][64]
static __device__ __half g_Kf[(size_t)H_ * S_ * DK_];   // [h][t][64], x4096
static __device__ __half g_VT[(size_t)H_ * DH_ * S_];   // [h][d][t]
static __device__ unsigned g_MB[(size_t)S_ * (S_ / 32)]; // mask bits [s][t/32]

__device__ __forceinline__ float gelu_f(float x) {
    return 0.5f * x * (1.0f + erff(x * 0.70710678118654752440f));
}

__device__ __forceinline__ void mma16816(float* c, const unsigned* a, const unsigned* b) {
    asm volatile(
        "mma.sync.aligned.m16n8k16.row.col.f32.f16.f16.f32 "
        "{%0,%1,%2,%3}, {%4,%5,%6,%7}, {%8,%9}, {%0,%1,%2,%3};\n"
        : "+f"(c[0]), "+f"(c[1]), "+f"(c[2]), "+f"(c[3])
        : "r"(a[0]), "r"(a[1]), "r"(a[2]), "r"(a[3]), "r"(b[0]), "r"(b[1]));
}

__device__ __forceinline__ void ldsm4(unsigned& r0, unsigned& r1, unsigned& r2,
                                      unsigned& r3, unsigned addr) {
    asm volatile("ldmatrix.sync.aligned.m8n8.x4.shared.b16 {%0,%1,%2,%3}, [%4];"
        : "=r"(r0), "=r"(r1), "=r"(r2), "=r"(r3) : "r"(addr));
}

__device__ __forceinline__ void ldsm4t(unsigned& r0, unsigned& r1, unsigned& r2,
                                       unsigned& r3, unsigned addr) {
    asm volatile("ldmatrix.sync.aligned.m8n8.x4.trans.shared.b16 {%0,%1,%2,%3}, [%4];"
        : "=r"(r0), "=r"(r1), "=r"(r2), "=r"(r3) : "r"(addr));
}

__device__ __forceinline__ unsigned h2u(float lo, float hi) {
    __half2 h = __floats2half2_rn(lo, hi);
    return *(unsigned*)&h;
}

__device__ __forceinline__ float ex2f(float x) {
    float r; asm("ex2.approx.f32 %0, %1;" : "=f"(r) : "f"(x)); return r;
}

__device__ __forceinline__ void cpa16(unsigned dst, const void* src) {
    asm volatile("cp.async.cg.shared.global [%0], [%1], 16;" :: "r"(dst), "l"(src));
}
#define CP_COMMIT()  asm volatile("cp.async.commit_group;")
#define CP_WAIT1()   asm volatile("cp.async.wait_group 1;")

// ---------------------------------------------------------------------------
// Mask bit-pack: g_MB[s][t/32] bit c = mask[s][32*(t/32)+c]
// ---------------------------------------------------------------------------
__global__ void __launch_bounds__(256, 4)
maskpack_kernel(const int* __restrict__ mask)
{
    int u = blockIdx.x * 256 + threadIdx.x;           // 0..131071
    const int* p = mask + (size_t)(u >> 6) * S_ + ((u & 63) << 5);
    unsigned bits = 0;
#pragma unroll
    for (int j = 0; j < 8; j++) {
        int4 m = *(const int4*)(p + 4 * j);
        bits |= (m.x ? 1u : 0u) << (4 * j)
              | (m.y ? 1u : 0u) << (4 * j + 1)
              | (m.z ? 1u : 0u) << (4 * j + 2)
              | (m.w ? 1u : 0u) << (4 * j + 3);
    }
    g_MB[u] = bits;
}

// ---------------------------------------------------------------------------
// Fused feature kernel (fp16 MMA + ldmatrix): z=0 Q path, z=1 K path
// smem (halves): Xh[128][136] | W1h[128][136] (reused as k2s[128][72]) |
//                W2h[128][72] | ikh[64][72]
// ---------------------------------------------------------------------------
#define XH_LD   136
#define W1_LD   136
#define W2_LD   72
#define IK_LD   72
#define K2_LD   72
#define SMEM_XH   0
#define SMEM_W1H  (128 * XH_LD)
#define SMEM_W2H  (SMEM_W1H + 128 * W1_LD)
#define SMEM_IKH  (SMEM_W2H + 128 * W2_LD)
#define SMEM_FEAT_HALVES (SMEM_IKH + 64 * IK_LD)

__global__ void __launch_bounds__(256, 2)
featfused_kernel(const float* __restrict__ q, const float* __restrict__ k,
                 const float* __restrict__ wq1, const float* __restrict__ wk1,
                 const float* __restrict__ wq2, const float* __restrict__ wk2,
                 const float* __restrict__ ik, const float* __restrict__ sD,
                 const float* __restrict__ sD2)
{
    extern __shared__ __half smh[];
    __half* Xh  = smh + SMEM_XH;    // [128][136] X rows, later Y rows
    __half* W1h = smh + SMEM_W1H;   // [128][136] W1 rows [d][e]
    __half* W2h = smh + SMEM_W2H;   // [128][72]  W2 rows [d][e2]
    __half* ikh = smh + SMEM_IKH;   // [64][72]   ik rows [e][f]
    __half* k2s = W1h;              // [128][72]  (K path reuse)

    const int h = blockIdx.y, sb = blockIdx.x, tid = threadIdx.x;
    const int warp = tid >> 5, lane = tid & 31;
    const int tq = lane >> 2, tc = lane & 3;
    const int g = lane >> 3, ri = lane & 7;
    const int r0l = warp * 16 + tq;
    const int gr0 = sb * 128 + r0l;
    const int kpath = blockIdx.z;
    const float* x  = kpath ? k : q;
    const float* w1 = kpath ? wk1 : wq1;
    const float* w2 = kpath ? wk2 : wq2;

    // ---- fills (all row-major, conflict-free) ----
    const float* xblk = x + (size_t)(sb * 128) * D_ + h * DH_;
    for (int i = tid; i < 128 * 32; i += 256) {
        int r = i >> 5, c = (i & 31) << 2;
        float4 a = *(const float4*)(xblk + (size_t)r * D_ + c);
        *(unsigned*)&Xh[r * XH_LD + c]     = h2u(a.x, a.y);
        *(unsigned*)&Xh[r * XH_LD + c + 2] = h2u(a.z, a.w);
    }
    const float* w1b = w1 + (size_t)h * DH_ * DH_;
    for (int i = tid; i < 128 * 32; i += 256) {
        int d = i >> 5, e = (i & 31) << 2;
        float4 a = *(const float4*)(w1b + d * DH_ + e);
        *(unsigned*)&W1h[d * W1_LD + e]     = h2u(a.x, a.y);
        *(unsigned*)&W1h[d * W1_LD + e + 2] = h2u(a.z, a.w);
    }
    const float* w2b = w2 + (size_t)h * DH_ * DK_;
    for (int i = tid; i < 128 * 16; i += 256) {
        int d = i >> 4, e = (i & 15) << 2;
        float4 a = *(const float4*)(w2b + d * DK_ + e);
        *(unsigned*)&W2h[d * W2_LD + e]     = h2u(a.x, a.y);
        *(unsigned*)&W2h[d * W2_LD + e + 2] = h2u(a.z, a.w);
    }
    if (kpath) {
        const float* ikb = ik + (size_t)h * DK_ * DK_;
        for (int i = tid; i < 64 * 16; i += 256) {
            int e = i >> 4, f = (i & 15) << 2;
            float4 a = *(const float4*)(ikb + e * DK_ + f);
            *(unsigned*)&ikh[e * IK_LD + f]     = h2u(a.x, a.y);
            *(unsigned*)&ikh[e * IK_LD + f + 2] = h2u(a.z, a.w);
        }
    }
    __syncthreads();

    // ldmatrix base addresses
    const unsigned xa = (unsigned)__cvta_generic_to_shared(
        &Xh[(warp * 16 + (g & 1) * 8 + ri) * XH_LD + (g >> 1) * 8]);
    const unsigned w1a = (unsigned)__cvta_generic_to_shared(
        &W1h[((g & 1) * 8 + ri) * W1_LD + (g >> 1) * 8]);
    const unsigned w2a = (unsigned)__cvta_generic_to_shared(
        &W2h[((g & 1) * 8 + ri) * W2_LD + (g >> 1) * 8]);
    const unsigned ika = (unsigned)__cvta_generic_to_shared(
        &ikh[((g & 1) * 8 + ri) * IK_LD + (g >> 1) * 8]);
    const unsigned k2a = (unsigned)__cvta_generic_to_shared(
        &k2s[(warp * 16 + (g & 1) * 8 + ri) * K2_LD + (g >> 1) * 8]);

    // ---- stage 1: Y = gelu(X @ W1), [16 x 128] per warp ----
    float acc1[16][4];
#pragma unroll
    for (int n = 0; n < 16; n++)
#pragma unroll
        for (int j = 0; j < 4; j++) acc1[n][j] = 0.f;
#pragma unroll
    for (int kc = 0; kc < 8; kc++) {
        unsigned A[4];
        ldsm4(A[0], A[1], A[2], A[3], xa + kc * 32);
#pragma unroll
        for (int nb = 0; nb < 8; nb++) {
            unsigned B[4];
            ldsm4t(B[0], B[1], B[2], B[3], w1a + kc * 16 * (W1_LD * 2) + nb * 32);
            mma16816(acc1[2 * nb],     A, B + 0);
            mma16816(acc1[2 * nb + 1], A, B + 2);
        }
    }
    // gelu + Y writeback (warp-local rows; 4tq+tc banks -> conflict-free)
#pragma unroll
    for (int n = 0; n < 16; n++) {
        int col = n * 8 + tc * 2;
        *(unsigned*)&Xh[r0l * XH_LD + col] =
            h2u(gelu_f(acc1[n][0]), gelu_f(acc1[n][1]));
        *(unsigned*)&Xh[(r0l + 8) * XH_LD + col] =
            h2u(gelu_f(acc1[n][2]), gelu_f(acc1[n][3]));
    }
    __syncwarp();

    // ---- stage 2: G = Y @ W2, [16 x 64] per warp ----
    float acc2[8][4];
#pragma unroll
    for (int n = 0; n < 8; n++)
#pragma unroll
        for (int j = 0; j < 4; j++) acc2[n][j] = 0.f;
#pragma unroll
    for (int kc = 0; kc < 8; kc++) {
        unsigned A[4];
        ldsm4(A[0], A[1], A[2], A[3], xa + kc * 32);
#pragma unroll
        for (int nb = 0; nb < 4; nb++) {
            unsigned B[4];
            ldsm4t(B[0], B[1], B[2], B[3], w2a + kc * 16 * (W2_LD * 2) + nb * 32);
            mma16816(acc2[2 * nb],     A, B + 0);
            mma16816(acc2[2 * nb + 1], A, B + 2);
        }
    }

    if (!kpath) {
        __half* outp = g_Qf + ((size_t)h * S_ + gr0) * DK_;
#pragma unroll
        for (int n = 0; n < 8; n++) {
            int col = n * 8 + tc * 2;
            *(unsigned*)(outp + col) =
                h2u(fabsf(gelu_f(acc2[n][0])), fabsf(gelu_f(acc2[n][1])));
            *(unsigned*)(outp + 8 * DK_ + col) =
                h2u(fabsf(gelu_f(acc2[n][2])), fabsf(gelu_f(acc2[n][3])));
        }
        return;
    }

    // ---- K path: k2 = |sD|*gelu(G)*4096 ; k3 = k2 + (k2@ik)*sD2 ; |k3| ----
    float k2r[8][4];
#pragma unroll
    for (int n = 0; n < 8; n++) {
        int col = n * 8 + tc * 2;
        float2 sd = *(const float2*)(sD + h * DK_ + col);
        float s0 = fabsf(sd.x) * 4096.f, s1 = fabsf(sd.y) * 4096.f;
        k2r[n][0] = s0 * gelu_f(acc2[n][0]);
        k2r[n][1] = s1 * gelu_f(acc2[n][1]);
        k2r[n][2] = s0 * gelu_f(acc2[n][2]);
        k2r[n][3] = s1 * gelu_f(acc2[n][3]);
    }
    __syncthreads();   // all warps done with W1h before overwrite as k2s
#pragma unroll
    for (int n = 0; n < 8; n++) {
        int col = n * 8 + tc * 2;
        *(unsigned*)&k2s[r0l * K2_LD + col]       = h2u(k2r[n][0], k2r[n][1]);
        *(unsigned*)&k2s[(r0l + 8) * K2_LD + col] = h2u(k2r[n][2], k2r[n][3]);
    }
    __syncwarp();

    float acc3[8][4];
#pragma unroll
    for (int n = 0; n < 8; n++)
#pragma unroll
        for (int j = 0; j < 4; j++) acc3[n][j] = 0.f;
#pragma unroll
    for (int kc = 0; kc < 4; kc++) {
        unsigned A[4];
        ldsm4(A[0], A[1], A[2], A[3], k2a + kc * 32);
#pragma unroll
        for (int nb = 0; nb < 4; nb++) {
            unsigned B[4];
            ldsm4t(B[0], B[1], B[2], B[3], ika + kc * 16 * (IK_LD * 2) + nb * 32);
            mma16816(acc3[2 * nb],     A, B + 0);
            mma16816(acc3[2 * nb + 1], A, B + 2);
        }
    }
    __half* outp = g_Kf + ((size_t)h * S_ + gr0) * DK_;
#pragma unroll
    for (int n = 0; n < 8; n++) {
        int col = n * 8 + tc * 2;
        float2 s2 = *(const float2*)(sD2 + h * DK_ + col);
        float o0 = fabsf(fmaf(acc3[n][0], s2.x, k2r[n][0]));
        float o1 = fabsf(fmaf(acc3[n][1], s2.y, k2r[n][1]));
        float o2 = fabsf(fmaf(acc3[n][2], s2.x, k2r[n][2]));
        float o3 = fabsf(fmaf(acc3[n][3], s2.y, k2r[n][3]));
        *(unsigned*)(outp + col)           = h2u(o0, o1);
        *(unsigned*)(outp + 8 * DK_ + col) = h2u(o2, o3);
    }
}

// ---------------------------------------------------------------------------
// V transpose per head: g_VT[h][d][t] = (half) v[t][h*128+d]
// ---------------------------------------------------------------------------
__global__ void __launch_bounds__(256, 1)
vtrans_kernel(const float* __restrict__ v)
{
    __shared__ __half Vsm[128][136];
    const int h = blockIdx.y, tb = blockIdx.x, tid = threadIdx.x;
    for (int i = tid; i < 128 * 32; i += 256) {
        int t = i >> 5, ds = (i & 31) << 2;
        float4 f = *(const float4*)(v + (size_t)(tb * 128 + t) * D_ + h * DH_ + ds);
        Vsm[ds + 0][t] = __float2half(f.x);
        Vsm[ds + 1][t] = __float2half(f.y);
        Vsm[ds + 2][t] = __float2half(f.z);
        Vsm[ds + 3][t] = __float2half(f.w);
    }
    __syncthreads();
    for (int i = tid; i < 128 * 16; i += 256) {
        int d = i >> 4, seg = (i & 15) << 3;
        *(uint4*)(g_VT + ((size_t)h * DH_ + d) * S_ + tb * 128 + seg) =
            *(const uint4*)&Vsm[d][seg];
    }
}

// ---------------------------------------------------------------------------
// Stage 3: fp16 mma, ldmatrix, mask-bits, 3-stage cp.async
// ---------------------------------------------------------------------------
#define ATTN_SMEM_BYTES ((128*72 + 3*32*72 + 3*128*40) * 2 + 128 * 4)

__global__ void __launch_bounds__(256, 2)
attn2_kernel(const float* __restrict__ sp_lse, const float* __restrict__ spw,
             float* __restrict__ out)
{
    extern __shared__ __half sma[];
    __half* Qs = sma;                       // [128][72]
    __half* Ks = Qs + 128 * 72;             // [3][32][72]
    __half* Vs = Ks + 3 * 32 * 72;          // [3][128][40]
    float*  rs = (float*)(Vs + 3 * 128 * 40);

    const int h = blockIdx.y, sb = blockIdx.x, tid = threadIdx.x;
    const int warp = tid >> 5, lane = tid & 31;
    const int tq = lane >> 2, tc = lane & 3;
    const int r0l = warp * 16 + tq;
    const int gr0 = sb * 128 + r0l;

    const __half* kbase = g_Kf + (size_t)h * S_ * DK_;
    const __half* vbase = g_VT + (size_t)h * DH_ * S_;
    const __half* qsrc  = g_Qf + ((size_t)h * S_ + sb * 128) * DK_;

    const int krow = tid >> 3, kseg = (tid & 7) << 3;
    const int vrowA = tid >> 2, vsegA = (tid & 3) << 3;
    const unsigned qs_sm = (unsigned)__cvta_generic_to_shared(Qs);
    const unsigned ks_sm = (unsigned)__cvta_generic_to_shared(Ks);
    const unsigned vs_sm = (unsigned)__cvta_generic_to_shared(Vs);

    const int g = lane >> 3, ri = lane & 7;
    const unsigned qa = (unsigned)__cvta_generic_to_shared(
        &Qs[(warp * 16 + (g & 1) * 8 + ri) * 72 + (g >> 1) * 8]);
    const unsigned ka = (unsigned)__cvta_generic_to_shared(
        &Ks[((g >> 1) * 8 + ri) * 72 + (g & 1) * 8]);
    const unsigned va = (unsigned)__cvta_generic_to_shared(
        &Vs[((g >> 1) * 8 + ri) * 40 + (g & 1) * 8]);

    float O[16][4];
#pragma unroll
    for (int n = 0; n < 16; n++)
#pragma unroll
        for (int j = 0; j < 4; j++) O[n][j] = 0.f;
    float rl0 = 0.f, rl1 = 0.f;

    // prologue: Q tile + tile 0 (group 0), tile 1 (group 1)
#pragma unroll
    for (int j = 0; j < 4; j++) {
        int i = tid + j * 256;
        int r = i >> 3, cs = (i & 7) << 3;
        cpa16(qs_sm + (r * 72 + cs) * 2, qsrc + r * 64 + cs);
    }
    cpa16(ks_sm + (krow * 72 + kseg) * 2, kbase + (size_t)krow * DK_ + kseg);
    cpa16(vs_sm + (vrowA * 40 + vsegA) * 2, vbase + (size_t)vrowA * S_ + vsegA);
    cpa16(vs_sm + ((vrowA + 64) * 40 + vsegA) * 2, vbase + (size_t)(vrowA + 64) * S_ + vsegA);
    CP_COMMIT();
    cpa16(ks_sm + (32 * 72 + krow * 72 + kseg) * 2, kbase + (size_t)(32 + krow) * DK_ + kseg);
    cpa16(vs_sm + (128 * 40 + vrowA * 40 + vsegA) * 2, vbase + (size_t)vrowA * S_ + 32 + vsegA);
    cpa16(vs_sm + (128 * 40 + (vrowA + 64) * 40 + vsegA) * 2, vbase + (size_t)(vrowA + 64) * S_ + 32 + vsegA);
    CP_COMMIT();

    const unsigned* mb0p = g_MB + (size_t)gr0 * (S_ / 32);
    const unsigned* mb1p = mb0p + 8 * (S_ / 32);
    const size_t wrow0 = ((size_t)h * S_ + gr0) * S_;
    const size_t wrow1 = wrow0 + 8 * S_;

    int buf = 0, bufn = 2;
    for (int tb = 0; tb < 64; tb++) {
        CP_WAIT1();
        __syncthreads();

        // spw + mask-bit prefetch for this tile
        const int cbase = tb * 32 + tc * 2;
        float2 w0r[4], w1r[4];
#pragma unroll
        for (int j = 0; j < 4; j++) {
            w0r[j] = *(const float2*)(spw + wrow0 + cbase + 8 * j);
            w1r[j] = *(const float2*)(spw + wrow1 + cbase + 8 * j);
        }
        const unsigned mb0 = mb0p[tb];
        const unsigned mb1 = mb1p[tb];

        // prefetch tile tb+2 into bufn
        if (tb + 2 < 64) {
            cpa16(ks_sm + (bufn * 32 * 72 + krow * 72 + kseg) * 2,
                  kbase + (size_t)((tb + 2) * 32 + krow) * DK_ + kseg);
            cpa16(vs_sm + (bufn * 128 * 40 + vrowA * 40 + vsegA) * 2,
                  vbase + (size_t)vrowA * S_ + (tb + 2) * 32 + vsegA);
            cpa16(vs_sm + (bufn * 128 * 40 + (vrowA + 64) * 40 + vsegA) * 2,
                  vbase + (size_t)(vrowA + 64) * S_ + (tb + 2) * 32 + vsegA);
        }
        CP_COMMIT();

        // --- scores via ldmatrix: S[4 n-tiles][4], K=64 ---
        const unsigned kb = ka + buf * (32 * 72 * 2);
        float S[4][4];
#pragma unroll
        for (int j = 0; j < 4; j++)
#pragma unroll
            for (int e = 0; e < 4; e++) S[j][e] = 0.f;
#pragma unroll
        for (int kc = 0; kc < 4; kc++) {
            unsigned A[4], B[4], C[4];
            ldsm4(A[0], A[1], A[2], A[3], qa + kc * 32);
            ldsm4(B[0], B[1], B[2], B[3], kb + kc * 32);
            mma16816(S[0], A, B + 0);
            mma16816(S[1], A, B + 2);
            ldsm4(C[0], C[1], C[2], C[3], kb + kc * 32 + 16 * 72 * 2);
            mma16816(S[2], A, C + 0);
            mma16816(S[3], A, C + 2);
        }

        // --- merge: bits from g_MB, spw staged (lr_true = S/4096; P x1024) ---
#pragma unroll
        for (int j = 0; j < 4; j++) {
            const int idx = tc * 2 + 8 * j;
            const bool m0x = (mb0 >> idx) & 1, m0y = (mb0 >> idx) & 2;
            const bool m1x = (mb1 >> idx) & 1, m1y = (mb1 >> idx) & 2;
            float s0 = S[j][0], s1 = S[j][1], s2 = S[j][2], s3 = S[j][3];
            rl0 += (m0x ? s0 : 0.f) + (m0y ? s1 : 0.f);
            rl1 += (m1x ? s2 : 0.f) + (m1y ? s3 : 0.f);
            S[j][0] = m0x ? fmaf(s0, 0.25f, 1.024e-3f)
                          : ex2f(fmaf(w0r[j].x, 1.4426950408889634f, 10.f));
            S[j][1] = m0y ? fmaf(s1, 0.25f, 1.024e-3f)
                          : ex2f(fmaf(w0r[j].y, 1.4426950408889634f, 10.f));
            S[j][2] = m1x ? fmaf(s2, 0.25f, 1.024e-3f)
                          : ex2f(fmaf(w1r[j].x, 1.4426950408889634f, 10.f));
            S[j][3] = m1y ? fmaf(s3, 0.25f, 1.024e-3f)
                          : ex2f(fmaf(w1r[j].y, 1.4426950408889634f, 10.f));
        }

        // --- AV via ldmatrix: O += P[16x32] @ V[32x128] ---
        const unsigned vb = va + buf * (128 * 40 * 2);
#pragma unroll
        for (int kc = 0; kc < 2; kc++) {
            unsigned a[4];
            a[0] = h2u(S[2 * kc][0],     S[2 * kc][1]);
            a[1] = h2u(S[2 * kc][2],     S[2 * kc][3]);
            a[2] = h2u(S[2 * kc + 1][0], S[2 * kc + 1][1]);
            a[3] = h2u(S[2 * kc + 1][2], S[2 * kc + 1][3]);
#pragma unroll
            for (int v = 0; v < 8; v++) {
                unsigned B[4];
                ldsm4(B[0], B[1], B[2], B[3], vb + kc * 32 + v * (16 * 40 * 2));
                mma16816(O[2 * v],     a, B + 0);
                mma16816(O[2 * v + 1], a, B + 2);
            }
        }

        buf = (buf == 2) ? 0 : buf + 1;
        bufn = (bufn == 2) ? 0 : bufn + 1;
    }

    rl0 += __shfl_xor_sync(0xFFFFFFFFu, rl0, 1);
    rl0 += __shfl_xor_sync(0xFFFFFFFFu, rl0, 2);
    rl1 += __shfl_xor_sync(0xFFFFFFFFu, rl1, 1);
    rl1 += __shfl_xor_sync(0xFFFFFFFFu, rl1, 2);
    if (tc == 0) { rs[r0l] = rl0; rs[r0l + 8] = rl1; }
    __syncthreads();

    const float den0 = rs[r0l]     * (1.f / 4096.f) + EPS_ + __expf(sp_lse[h * S_ + gr0]);
    const float den1 = rs[r0l + 8] * (1.f / 4096.f) + EPS_ + __expf(sp_lse[h * S_ + gr0 + 8]);
    const float inv0 = 1.f / (1024.f * den0);
    const float inv1 = 1.f / (1024.f * den1);
    float* op0 = out + (size_t)gr0 * D_ + h * DH_;
    float* op1 = op0 + 8 * D_;
#pragma unroll
    for (int n = 0; n < 16; n++) {
        float2 t0 = make_float2(O[n][0] * inv0, O[n][1] * inv0);
        float2 t1 = make_float2(O[n][2] * inv1, O[n][3] * inv1);
        *(float2*)(op0 + 8 * n + tc * 2) = t0;
        *(float2*)(op1 + 8 * n + tc * 2) = t1;
    }
}

// ---------------------------------------------------------------------------
extern "C" void kernel_launch(void* const* d_in, const int* in_sizes, int n_in,
                              void* d_out, int out_size)
{
    (void)in_sizes; (void)n_in; (void)out_size;
    const float* q      = (const float*)d_in[0];
    const float* k      = (const float*)d_in[1];
    const float* v      = (const float*)d_in[2];
    const int*   mask   = (const int*)d_in[3];
    const float* sp_lse = (const float*)d_in[4];
    const float* spw    = (const float*)d_in[5];
    const float* kq1    = (const float*)d_in[6];
    const float* kk1    = (const float*)d_in[7];
    const float* kq2    = (const float*)d_in[8];
    const float* kk2    = (const float*)d_in[9];
    const float* ik     = (const float*)d_in[10];
    const float* sD     = (const float*)d_in[11];
    const float* sD2    = (const float*)d_in[12];
    float* out = (float*)d_out;

    const int smemF = SMEM_FEAT_HALVES * 2;   // 97280 B
    const int smemA = ATTN_SMEM_BYTES;        // 63488 B
    cudaFuncSetAttribute(featfused_kernel, cudaFuncAttributeMaxDynamicSharedMemorySize, smemF);
    cudaFuncSetAttribute(attn2_kernel,     cudaFuncAttributeMaxDynamicSharedMemorySize, smemA);

    dim3 grid(S_ / 128, H_), blk(256);
    dim3 gridF(S_ / 128, H_, 2);
    maskpack_kernel<<<(S_ * (S_ / 32)) / 256, blk>>>(mask);
    featfused_kernel<<<gridF, blk, smemF>>>(q, k, kq1, kk1, kq2, kk2, ik, sD, sD2);
    vtrans_kernel<<<grid, blk>>>(v);
    attn2_kernel<<<grid, blk, smemA>>>(sp_lse, spw, out);
}

// round 15
// speedup vs baseline: 5.2519x; 1.1247x over previous
#include <cuda_runtime.h>
#include <cuda_fp16.h>
#include <cstdint>
#include <math.h>

#define S_   2048
#define H_   16
#define D_   2048
#define DH_  128
#define DK_  64
#define EPS_ 1e-6f

// K features pre-scaled by 4096; merged P scaled by 1024; folded into epilogue.

static __device__ __half g_Qf[(size_t)H_ * S_ * DK_];   // [h][s][64]
static __device__ __half g_Kf[(size_t)H_ * S_ * DK_];   // [h][t][64], x4096
static __device__ __half g_VT[(size_t)H_ * DH_ * S_];   // [h][d][t]
static __device__ unsigned g_MB[(size_t)S_ * (S_ / 32)]; // mask bits [s][t/32]

__device__ __forceinline__ float gelu_f(float x) {
    return 0.5f * x * (1.0f + erff(x * 0.70710678118654752440f));
}

__device__ __forceinline__ void mma16816(float* c, const unsigned* a, const unsigned* b) {
    asm volatile(
        "mma.sync.aligned.m16n8k16.row.col.f32.f16.f16.f32 "
        "{%0,%1,%2,%3}, {%4,%5,%6,%7}, {%8,%9}, {%0,%1,%2,%3};\n"
        : "+f"(c[0]), "+f"(c[1]), "+f"(c[2]), "+f"(c[3])
        : "r"(a[0]), "r"(a[1]), "r"(a[2]), "r"(a[3]), "r"(b[0]), "r"(b[1]));
}

__device__ __forceinline__ void ldsm4(unsigned& r0, unsigned& r1, unsigned& r2,
                                      unsigned& r3, unsigned addr) {
    asm volatile("ldmatrix.sync.aligned.m8n8.x4.shared.b16 {%0,%1,%2,%3}, [%4];"
        : "=r"(r0), "=r"(r1), "=r"(r2), "=r"(r3) : "r"(addr));
}

__device__ __forceinline__ void ldsm4t(unsigned& r0, unsigned& r1, unsigned& r2,
                                       unsigned& r3, unsigned addr) {
    asm volatile("ldmatrix.sync.aligned.m8n8.x4.trans.shared.b16 {%0,%1,%2,%3}, [%4];"
        : "=r"(r0), "=r"(r1), "=r"(r2), "=r"(r3) : "r"(addr));
}

__device__ __forceinline__ unsigned h2u(float lo, float hi) {
    __half2 h = __floats2half2_rn(lo, hi);
    return *(unsigned*)&h;
}

__device__ __forceinline__ float ex2f(float x) {
    float r; asm("ex2.approx.f32 %0, %1;" : "=f"(r) : "f"(x)); return r;
}

__device__ __forceinline__ void cpa16(unsigned dst, const void* src) {
    asm volatile("cp.async.cg.shared.global [%0], [%1], 16;" :: "r"(dst), "l"(src));
}
#define CP_COMMIT()  asm volatile("cp.async.commit_group;")
#define CP_WAIT1()   asm volatile("cp.async.wait_group 1;")

__device__ __forceinline__ uint32_t smem_u32(const void* p) {
    uint32_t a;
    asm("{ .reg .u64 t; cvta.to.shared.u64 t, %1; cvt.u32.u64 %0, t; }" : "=r"(a) : "l"(p));
    return a;
}

// ---------------------------------------------------------------------------
// Mask bit-pack: g_MB[s][t/32] bit c = mask[s][32*(t/32)+c]
// ---------------------------------------------------------------------------
__global__ void __launch_bounds__(256, 4)
maskpack_kernel(const int* __restrict__ mask)
{
    int u = blockIdx.x * 256 + threadIdx.x;           // 0..131071
    const int* p = mask + (size_t)(u >> 6) * S_ + ((u & 63) << 5);
    unsigned bits = 0;
#pragma unroll
    for (int j = 0; j < 8; j++) {
        int4 m = *(const int4*)(p + 4 * j);
        bits |= (m.x ? 1u : 0u) << (4 * j)
              | (m.y ? 1u : 0u) << (4 * j + 1)
              | (m.z ? 1u : 0u) << (4 * j + 2)
              | (m.w ? 1u : 0u) << (4 * j + 3);
    }
    g_MB[u] = bits;
}

// ---------------------------------------------------------------------------
// Fused feature kernel (fp16 MMA + ldmatrix): z=0 Q path, z=1 K path
// ---------------------------------------------------------------------------
#define XH_LD   136
#define W1_LD   136
#define W2_LD   72
#define IK_LD   72
#define K2_LD   72
#define SMEM_XH   0
#define SMEM_W1H  (128 * XH_LD)
#define SMEM_W2H  (SMEM_W1H + 128 * W1_LD)
#define SMEM_IKH  (SMEM_W2H + 128 * W2_LD)
#define SMEM_FEAT_HALVES (SMEM_IKH + 64 * IK_LD)

__global__ void __launch_bounds__(256, 2)
featfused_kernel(const float* __restrict__ q, const float* __restrict__ k,
                 const float* __restrict__ wq1, const float* __restrict__ wk1,
                 const float* __restrict__ wq2, const float* __restrict__ wk2,
                 const float* __restrict__ ik, const float* __restrict__ sD,
                 const float* __restrict__ sD2)
{
    extern __shared__ __half smh[];
    __half* Xh  = smh + SMEM_XH;    // [128][136] X rows, later Y rows
    __half* W1h = smh + SMEM_W1H;   // [128][136] W1 rows [d][e]
    __half* W2h = smh + SMEM_W2H;   // [128][72]  W2 rows [d][e2]
    __half* ikh = smh + SMEM_IKH;   // [64][72]   ik rows [e][f]
    __half* k2s = W1h;              // [128][72]  (K path reuse)

    const int h = blockIdx.y, sb = blockIdx.x, tid = threadIdx.x;
    const int warp = tid >> 5, lane = tid & 31;
    const int tq = lane >> 2, tc = lane & 3;
    const int g = lane >> 3, ri = lane & 7;
    const int r0l = warp * 16 + tq;
    const int gr0 = sb * 128 + r0l;
    const int kpath = blockIdx.z;
    const float* x  = kpath ? k : q;
    const float* w1 = kpath ? wk1 : wq1;
    const float* w2 = kpath ? wk2 : wq2;

    const float* xblk = x + (size_t)(sb * 128) * D_ + h * DH_;
    for (int i = tid; i < 128 * 32; i += 256) {
        int r = i >> 5, c = (i & 31) << 2;
        float4 a = *(const float4*)(xblk + (size_t)r * D_ + c);
        *(unsigned*)&Xh[r * XH_LD + c]     = h2u(a.x, a.y);
        *(unsigned*)&Xh[r * XH_LD + c + 2] = h2u(a.z, a.w);
    }
    const float* w1b = w1 + (size_t)h * DH_ * DH_;
    for (int i = tid; i < 128 * 32; i += 256) {
        int d = i >> 5, e = (i & 31) << 2;
        float4 a = *(const float4*)(w1b + d * DH_ + e);
        *(unsigned*)&W1h[d * W1_LD + e]     = h2u(a.x, a.y);
        *(unsigned*)&W1h[d * W1_LD + e + 2] = h2u(a.z, a.w);
    }
    const float* w2b = w2 + (size_t)h * DH_ * DK_;
    for (int i = tid; i < 128 * 16; i += 256) {
        int d = i >> 4, e = (i & 15) << 2;
        float4 a = *(const float4*)(w2b + d * DK_ + e);
        *(unsigned*)&W2h[d * W2_LD + e]     = h2u(a.x, a.y);
        *(unsigned*)&W2h[d * W2_LD + e + 2] = h2u(a.z, a.w);
    }
    if (kpath) {
        const float* ikb = ik + (size_t)h * DK_ * DK_;
        for (int i = tid; i < 64 * 16; i += 256) {
            int e = i >> 4, f = (i & 15) << 2;
            float4 a = *(const float4*)(ikb + e * DK_ + f);
            *(unsigned*)&ikh[e * IK_LD + f]     = h2u(a.x, a.y);
            *(unsigned*)&ikh[e * IK_LD + f + 2] = h2u(a.z, a.w);
        }
    }
    __syncthreads();

    const unsigned xa = smem_u32(&Xh[(warp * 16 + (g & 1) * 8 + ri) * XH_LD + (g >> 1) * 8]);
    const unsigned w1a = smem_u32(&W1h[((g & 1) * 8 + ri) * W1_LD + (g >> 1) * 8]);
    const unsigned w2a = smem_u32(&W2h[((g & 1) * 8 + ri) * W2_LD + (g >> 1) * 8]);
    const unsigned ika = smem_u32(&ikh[((g & 1) * 8 + ri) * IK_LD + (g >> 1) * 8]);
    const unsigned k2a = smem_u32(&k2s[(warp * 16 + (g & 1) * 8 + ri) * K2_LD + (g >> 1) * 8]);

    float acc1[16][4];
#pragma unroll
    for (int n = 0; n < 16; n++)
#pragma unroll
        for (int j = 0; j < 4; j++) acc1[n][j] = 0.f;
#pragma unroll
    for (int kc = 0; kc < 8; kc++) {
        unsigned A[4];
        ldsm4(A[0], A[1], A[2], A[3], xa + kc * 32);
#pragma unroll
        for (int nb = 0; nb < 8; nb++) {
            unsigned B[4];
            ldsm4t(B[0], B[1], B[2], B[3], w1a + kc * 16 * (W1_LD * 2) + nb * 32);
            mma16816(acc1[2 * nb],     A, B + 0);
            mma16816(acc1[2 * nb + 1], A, B + 2);
        }
    }
#pragma unroll
    for (int n = 0; n < 16; n++) {
        int col = n * 8 + tc * 2;
        *(unsigned*)&Xh[r0l * XH_LD + col] =
            h2u(gelu_f(acc1[n][0]), gelu_f(acc1[n][1]));
        *(unsigned*)&Xh[(r0l + 8) * XH_LD + col] =
            h2u(gelu_f(acc1[n][2]), gelu_f(acc1[n][3]));
    }
    __syncwarp();

    float acc2[8][4];
#pragma unroll
    for (int n = 0; n < 8; n++)
#pragma unroll
        for (int j = 0; j < 4; j++) acc2[n][j] = 0.f;
#pragma unroll
    for (int kc = 0; kc < 8; kc++) {
        unsigned A[4];
        ldsm4(A[0], A[1], A[2], A[3], xa + kc * 32);
#pragma unroll
        for (int nb = 0; nb < 4; nb++) {
            unsigned B[4];
            ldsm4t(B[0], B[1], B[2], B[3], w2a + kc * 16 * (W2_LD * 2) + nb * 32);
            mma16816(acc2[2 * nb],     A, B + 0);
            mma16816(acc2[2 * nb + 1], A, B + 2);
        }
    }

    if (!kpath) {
        __half* outp = g_Qf + ((size_t)h * S_ + gr0) * DK_;
#pragma unroll
        for (int n = 0; n < 8; n++) {
            int col = n * 8 + tc * 2;
            *(unsigned*)(outp + col) =
                h2u(fabsf(gelu_f(acc2[n][0])), fabsf(gelu_f(acc2[n][1])));
            *(unsigned*)(outp + 8 * DK_ + col) =
                h2u(fabsf(gelu_f(acc2[n][2])), fabsf(gelu_f(acc2[n][3])));
        }
        return;
    }

    float k2r[8][4];
#pragma unroll
    for (int n = 0; n < 8; n++) {
        int col = n * 8 + tc * 2;
        float2 sd = *(const float2*)(sD + h * DK_ + col);
        float s0 = fabsf(sd.x) * 4096.f, s1 = fabsf(sd.y) * 4096.f;
        k2r[n][0] = s0 * gelu_f(acc2[n][0]);
        k2r[n][1] = s1 * gelu_f(acc2[n][1]);
        k2r[n][2] = s0 * gelu_f(acc2[n][2]);
        k2r[n][3] = s1 * gelu_f(acc2[n][3]);
    }
    __syncthreads();
#pragma unroll
    for (int n = 0; n < 8; n++) {
        int col = n * 8 + tc * 2;
        *(unsigned*)&k2s[r0l * K2_LD + col]       = h2u(k2r[n][0], k2r[n][1]);
        *(unsigned*)&k2s[(r0l + 8) * K2_LD + col] = h2u(k2r[n][2], k2r[n][3]);
    }
    __syncwarp();

    float acc3[8][4];
#pragma unroll
    for (int n = 0; n < 8; n++)
#pragma unroll
        for (int j = 0; j < 4; j++) acc3[n][j] = 0.f;
#pragma unroll
    for (int kc = 0; kc < 4; kc++) {
        unsigned A[4];
        ldsm4(A[0], A[1], A[2], A[3], k2a + kc * 32);
#pragma unroll
        for (int nb = 0; nb < 4; nb++) {
            unsigned B[4];
            ldsm4t(B[0], B[1], B[2], B[3], ika + kc * 16 * (IK_LD * 2) + nb * 32);
            mma16816(acc3[2 * nb],     A, B + 0);
            mma16816(acc3[2 * nb + 1], A, B + 2);
        }
    }
    __half* outp = g_Kf + ((size_t)h * S_ + gr0) * DK_;
#pragma unroll
    for (int n = 0; n < 8; n++) {
        int col = n * 8 + tc * 2;
        float2 s2 = *(const float2*)(sD2 + h * DK_ + col);
        float o0 = fabsf(fmaf(acc3[n][0], s2.x, k2r[n][0]));
        float o1 = fabsf(fmaf(acc3[n][1], s2.y, k2r[n][1]));
        float o2 = fabsf(fmaf(acc3[n][2], s2.x, k2r[n][2]));
        float o3 = fabsf(fmaf(acc3[n][3], s2.y, k2r[n][3]));
        *(unsigned*)(outp + col)           = h2u(o0, o1);
        *(unsigned*)(outp + 8 * DK_ + col) = h2u(o2, o3);
    }
}

// ---------------------------------------------------------------------------
// V transpose per head: g_VT[h][d][t] = (half) v[t][h*128+d]
// ---------------------------------------------------------------------------
__global__ void __launch_bounds__(256, 1)
vtrans_kernel(const float* __restrict__ v)
{
    __shared__ __half Vsm[128][136];
    const int h = blockIdx.y, tb = blockIdx.x, tid = threadIdx.x;
    for (int i = tid; i < 128 * 32; i += 256) {
        int t = i >> 5, ds = (i & 31) << 2;
        float4 f = *(const float4*)(v + (size_t)(tb * 128 + t) * D_ + h * DH_ + ds);
        Vsm[ds + 0][t] = __float2half(f.x);
        Vsm[ds + 1][t] = __float2half(f.y);
        Vsm[ds + 2][t] = __float2half(f.z);
        Vsm[ds + 3][t] = __float2half(f.w);
    }
    __syncthreads();
    for (int i = tid; i < 128 * 16; i += 256) {
        int d = i >> 4, seg = (i & 15) << 3;
        *(uint4*)(g_VT + ((size_t)h * DH_ + d) * S_ + tb * 128 + seg) =
            *(const uint4*)&Vsm[d][seg];
    }
}

// ---------------------------------------------------------------------------
// Stage 3: fp16 mma, ldmatrix, mask-bits, 3-stage cp.async
// Q fragments hoisted into registers (loop-invariant)
// ---------------------------------------------------------------------------
#define ATTN_SMEM_BYTES ((128*72 + 3*32*72 + 3*128*40) * 2 + 128 * 4)

__global__ void __launch_bounds__(256, 2)
attn2_kernel(const float* __restrict__ sp_lse, const float* __restrict__ spw,
             float* __restrict__ out)
{
    extern __shared__ __half sma[];
    __half* Qs = sma;                       // [128][72]
    __half* Ks = Qs + 128 * 72;             // [3][32][72]
    __half* Vs = Ks + 3 * 32 * 72;          // [3][128][40]
    float*  rs = (float*)(Vs + 3 * 128 * 40);

    const int h = blockIdx.y, sb = blockIdx.x, tid = threadIdx.x;
    const int warp = tid >> 5, lane = tid & 31;
    const int tq = lane >> 2, tc = lane & 3;
    const int r0l = warp * 16 + tq;
    const int gr0 = sb * 128 + r0l;

    const __half* kbase = g_Kf + (size_t)h * S_ * DK_;
    const __half* vbase = g_VT + (size_t)h * DH_ * S_;
    const __half* qsrc  = g_Qf + ((size_t)h * S_ + sb * 128) * DK_;

    const int krow = tid >> 3, kseg = (tid & 7) << 3;
    const int vrowA = tid >> 2, vsegA = (tid & 3) << 3;
    const unsigned qs_sm = (unsigned)__cvta_generic_to_shared(Qs);
    const unsigned ks_sm = (unsigned)__cvta_generic_to_shared(Ks);
    const unsigned vs_sm = (unsigned)__cvta_generic_to_shared(Vs);

    const int g = lane >> 3, ri = lane & 7;
    const unsigned qa = (unsigned)__cvta_generic_to_shared(
        &Qs[(warp * 16 + (g & 1) * 8 + ri) * 72 + (g >> 1) * 8]);
    const unsigned ka = (unsigned)__cvta_generic_to_shared(
        &Ks[((g >> 1) * 8 + ri) * 72 + (g & 1) * 8]);
    const unsigned va = (unsigned)__cvta_generic_to_shared(
        &Vs[((g >> 1) * 8 + ri) * 40 + (g & 1) * 8]);

    float O[16][4];
#pragma unroll
    for (int n = 0; n < 16; n++)
#pragma unroll
        for (int j = 0; j < 4; j++) O[n][j] = 0.f;
    float rl0 = 0.f, rl1 = 0.f;

    // prologue: group0 = Q tile + tile 0; group1 = tile 1
#pragma unroll
    for (int j = 0; j < 4; j++) {
        int i = tid + j * 256;
        int r = i >> 3, cs = (i & 7) << 3;
        cpa16(qs_sm + (r * 72 + cs) * 2, qsrc + r * 64 + cs);
    }
    cpa16(ks_sm + (krow * 72 + kseg) * 2, kbase + (size_t)krow * DK_ + kseg);
    cpa16(vs_sm + (vrowA * 40 + vsegA) * 2, vbase + (size_t)vrowA * S_ + vsegA);
    cpa16(vs_sm + ((vrowA + 64) * 40 + vsegA) * 2, vbase + (size_t)(vrowA + 64) * S_ + vsegA);
    CP_COMMIT();
    cpa16(ks_sm + (32 * 72 + krow * 72 + kseg) * 2, kbase + (size_t)(32 + krow) * DK_ + kseg);
    cpa16(vs_sm + (128 * 40 + vrowA * 40 + vsegA) * 2, vbase + (size_t)vrowA * S_ + 32 + vsegA);
    cpa16(vs_sm + (128 * 40 + (vrowA + 64) * 40 + vsegA) * 2, vbase + (size_t)(vrowA + 64) * S_ + 32 + vsegA);
    CP_COMMIT();

    // hoist loop-invariant Q fragments into registers
    unsigned qf[4][4];
    CP_WAIT1();            // group0 (Q + tile0) complete
    __syncthreads();
#pragma unroll
    for (int kc = 0; kc < 4; kc++)
        ldsm4(qf[kc][0], qf[kc][1], qf[kc][2], qf[kc][3], qa + kc * 32);

    const unsigned* mb0p = g_MB + (size_t)gr0 * (S_ / 32);
    const unsigned* mb1p = mb0p + 8 * (S_ / 32);
    const size_t wrow0 = ((size_t)h * S_ + gr0) * S_;
    const size_t wrow1 = wrow0 + 8 * S_;

    int buf = 0, bufn = 2;
    for (int tb = 0; tb < 64; tb++) {
        CP_WAIT1();
        __syncthreads();

        // spw + mask-bit prefetch for this tile
        const int cbase = tb * 32 + tc * 2;
        float2 w0r[4], w1r[4];
#pragma unroll
        for (int j = 0; j < 4; j++) {
            w0r[j] = *(const float2*)(spw + wrow0 + cbase + 8 * j);
            w1r[j] = *(const float2*)(spw + wrow1 + cbase + 8 * j);
        }
        const unsigned mb0 = mb0p[tb];
        const unsigned mb1 = mb1p[tb];

        // prefetch tile tb+2 into bufn
        if (tb + 2 < 64) {
            cpa16(ks_sm + (bufn * 32 * 72 + krow * 72 + kseg) * 2,
                  kbase + (size_t)((tb + 2) * 32 + krow) * DK_ + kseg);
            cpa16(vs_sm + (bufn * 128 * 40 + vrowA * 40 + vsegA) * 2,
                  vbase + (size_t)vrowA * S_ + (tb + 2) * 32 + vsegA);
            cpa16(vs_sm + (bufn * 128 * 40 + (vrowA + 64) * 40 + vsegA) * 2,
                  vbase + (size_t)(vrowA + 64) * S_ + (tb + 2) * 32 + vsegA);
        }
        CP_COMMIT();

        // --- scores: S[4 n-tiles][4], K=64, Q from registers ---
        const unsigned kb = ka + buf * (32 * 72 * 2);
        float S[4][4];
#pragma unroll
        for (int j = 0; j < 4; j++)
#pragma unroll
            for (int e = 0; e < 4; e++) S[j][e] = 0.f;
#pragma unroll
        for (int kc = 0; kc < 4; kc++) {
            unsigned B[4], C[4];
            ldsm4(B[0], B[1], B[2], B[3], kb + kc * 32);
            mma16816(S[0], qf[kc], B + 0);
            mma16816(S[1], qf[kc], B + 2);
            ldsm4(C[0], C[1], C[2], C[3], kb + kc * 32 + 16 * 72 * 2);
            mma16816(S[2], qf[kc], C + 0);
            mma16816(S[3], qf[kc], C + 2);
        }

        // --- merge: bits from g_MB, spw staged (lr_true = S/4096; P x1024) ---
#pragma unroll
        for (int j = 0; j < 4; j++) {
            const int idx = tc * 2 + 8 * j;
            const bool m0x = (mb0 >> idx) & 1, m0y = (mb0 >> idx) & 2;
            const bool m1x = (mb1 >> idx) & 1, m1y = (mb1 >> idx) & 2;
            float s0 = S[j][0], s1 = S[j][1], s2 = S[j][2], s3 = S[j][3];
            rl0 += (m0x ? s0 : 0.f) + (m0y ? s1 : 0.f);
            rl1 += (m1x ? s2 : 0.f) + (m1y ? s3 : 0.f);
            S[j][0] = m0x ? fmaf(s0, 0.25f, 1.024e-3f)
                          : ex2f(fmaf(w0r[j].x, 1.4426950408889634f, 10.f));
            S[j][1] = m0y ? fmaf(s1, 0.25f, 1.024e-3f)
                          : ex2f(fmaf(w0r[j].y, 1.4426950408889634f, 10.f));
            S[j][2] = m1x ? fmaf(s2, 0.25f, 1.024e-3f)
                          : ex2f(fmaf(w1r[j].x, 1.4426950408889634f, 10.f));
            S[j][3] = m1y ? fmaf(s3, 0.25f, 1.024e-3f)
                          : ex2f(fmaf(w1r[j].y, 1.4426950408889634f, 10.f));
        }

        // --- AV via ldmatrix: O += P[16x32] @ V[32x128] ---
        const unsigned vb = va + buf * (128 * 40 * 2);
#pragma unroll
        for (int kc = 0; kc < 2; kc++) {
            unsigned a[4];
            a[0] = h2u(S[2 * kc][0],     S[2 * kc][1]);
            a[1] = h2u(S[2 * kc][2],     S[2 * kc][3]);
            a[2] = h2u(S[2 * kc + 1][0], S[2 * kc + 1][1]);
            a[3] = h2u(S[2 * kc + 1][2], S[2 * kc + 1][3]);
#pragma unroll
            for (int v = 0; v < 8; v++) {
                unsigned B[4];
                ldsm4(B[0], B[1], B[2], B[3], vb + kc * 32 + v * (16 * 40 * 2));
                mma16816(O[2 * v],     a, B + 0);
                mma16816(O[2 * v + 1], a, B + 2);
            }
        }

        buf = (buf == 2) ? 0 : buf + 1;
        bufn = (bufn == 2) ? 0 : bufn + 1;
    }

    rl0 += __shfl_xor_sync(0xFFFFFFFFu, rl0, 1);
    rl0 += __shfl_xor_sync(0xFFFFFFFFu, rl0, 2);
    rl1 += __shfl_xor_sync(0xFFFFFFFFu, rl1, 1);
    rl1 += __shfl_xor_sync(0xFFFFFFFFu, rl1, 2);
    if (tc == 0) { rs[r0l] = rl0; rs[r0l + 8] = rl1; }
    __syncthreads();

    const float den0 = rs[r0l]     * (1.f / 4096.f) + EPS_ + __expf(sp_lse[h * S_ + gr0]);
    const float den1 = rs[r0l + 8] * (1.f / 4096.f) + EPS_ + __expf(sp_lse[h * S_ + gr0 + 8]);
    const float inv0 = 1.f / (1024.f * den0);
    const float inv1 = 1.f / (1024.f * den1);
    float* op0 = out + (size_t)gr0 * D_ + h * DH_;
    float* op1 = op0 + 8 * D_;
#pragma unroll
    for (int n = 0; n < 16; n++) {
        float2 t0 = make_float2(O[n][0] * inv0, O[n][1] * inv0);
        float2 t1 = make_float2(O[n][2] * inv1, O[n][3] * inv1);
        *(float2*)(op0 + 8 * n + tc * 2) = t0;
        *(float2*)(op1 + 8 * n + tc * 2) = t1;
    }
}

// ---------------------------------------------------------------------------
extern "C" void kernel_launch(void* const* d_in, const int* in_sizes, int n_in,
                              void* d_out, int out_size)
{
    (void)in_sizes; (void)n_in; (void)out_size;
    const float* q      = (const float*)d_in[0];
    const float* k      = (const float*)d_in[1];
    const float* v      = (const float*)d_in[2];
    const int*   mask   = (const int*)d_in[3];
    const float* sp_lse = (const float*)d_in[4];
    const float* spw    = (const float*)d_in[5];
    const float* kq1    = (const float*)d_in[6];
    const float* kk1    = (const float*)d_in[7];
    const float* kq2    = (const float*)d_in[8];
    const float* kk2    = (const float*)d_in[9];
    const float* ik     = (const float*)d_in[10];
    const float* sD     = (const float*)d_in[11];
    const float* sD2    = (const float*)d_in[12];
    float* out = (float*)d_out;

    const int smemF = SMEM_FEAT_HALVES * 2;   // 97280 B
    const int smemA = ATTN_SMEM_BYTES;        // 63488 B
    cudaFuncSetAttribute(featfused_kernel, cudaFuncAttributeMaxDynamicSharedMemorySize, smemF);
    cudaFuncSetAttribute(attn2_kernel,     cudaFuncAttributeMaxDynamicSharedMemorySize, smemA);

    dim3 grid(S_ / 128, H_), blk(256);
    dim3 gridF(S_ / 128, H_, 2);
    maskpack_kernel<<<(S_ * (S_ / 32)) / 256, blk>>>(mask);
    featfused_kernel<<<gridF, blk, smemF>>>(q, k, kq1, kk1, kq2, kk2, ik, sD, sD2);
    vtrans_kernel<<<grid, blk>>>(v);
    attn2_kernel<<<grid, blk, smemA>>>(sp_lse, spw, out);
}